// round 8
// baseline (speedup 1.0000x reference)
#include <cuda_runtime.h>
#include <cuda_bf16.h>
#include <cstddef>
#include <cstdint>
#include <math.h>

// ---------------- problem constants ----------------
#define Lc   4
#define Hc   2048
#define NHc  16
#define NKVc 4
#define DHc  128
#define Fc   5632
#define Rc   16
#define Bc   4
#define Sc   512
#define NCc  2
#define MTc  (Bc * Sc)          // 2048 tokens
#define QNc  (NHc * DHc)        // 2048
#define KNc  (NKVc * DHc)       // 512
#define LORA_SCALE 2.0f
#define INV_SQRT_DH 0.08838834764831845f

// per-layer transposed weight buffer offsets (elements)
#define WOFF_Q 0
#define WOFF_K (WOFF_Q + Hc * QNc)
#define WOFF_V (WOFF_K + Hc * KNc)
#define WOFF_O (WOFF_V + Hc * KNc)
#define WOFF_G (WOFF_O + QNc * Hc)
#define WOFF_U (WOFF_G + Hc * Fc)
#define WOFF_D (WOFF_U + Hc * Fc)
#define LAYER_W (WOFF_D + Fc * Hc)   // 45,088,768

// ---------------- scratch (static device memory; allocation-free) ----------------
__device__ float          d_h[MTc * Hc];
__device__ float          d_x[MTc * Hc];
__device__ __nv_bfloat16  d_xh[MTc * Hc];
__device__ __nv_bfloat16  d_xl[MTc * Hc];
__device__ float          d_q[MTc * QNc];
__device__ float          d_k[MTc * KNc];
__device__ float          d_v[MTc * KNc];
__device__ float          d_t1[MTc * Rc];
__device__ float          d_t2[MTc * Rc];
__device__ float          d_t3[MTc * Rc];
__device__ float          d_sc[Bc * NHc * Sc * Sc];
__device__ float          d_ctx[MTc * QNc];
__device__ __nv_bfloat16  d_ch[MTc * QNc];
__device__ __nv_bfloat16  d_cl[MTc * QNc];
__device__ float          d_g[MTc * Fc];
__device__ float          d_u[MTc * Fc];
__device__ __nv_bfloat16  d_gh[MTc * Fc];
__device__ __nv_bfloat16  d_gl[MTc * Fc];
__device__ float          d_pooled[Bc * Hc];
__device__ float          d_cls[Bc * Hc];
__device__ __nv_bfloat16  d_whT[(size_t)Lc * LAYER_W];  // hi weights, [N,K]
__device__ __nv_bfloat16  d_wlT[(size_t)Lc * LAYER_W];  // lo weights, [N,K]

// ---------------- PTX helpers ----------------
__device__ __forceinline__ uint32_t sptr(const void* p) {
    return (uint32_t)__cvta_generic_to_shared(p);
}
#define CP_ASYNC16(dst, src) asm volatile("cp.async.cg.shared.global [%0], [%1], 16;\n" :: "r"(dst), "l"(src))
#define CP_COMMIT()          asm volatile("cp.async.commit_group;\n" ::: "memory")
#define CP_WAIT(n)           asm volatile("cp.async.wait_group %0;\n" :: "n"(n) : "memory")

__device__ __forceinline__ void mma_bf16(float* c, const uint32_t* a, const uint32_t* b) {
    asm volatile(
        "mma.sync.aligned.m16n8k16.row.col.f32.bf16.bf16.f32 "
        "{%0,%1,%2,%3}, {%4,%5,%6,%7}, {%8,%9}, {%0,%1,%2,%3};\n"
        : "+f"(c[0]), "+f"(c[1]), "+f"(c[2]), "+f"(c[3])
        : "r"(a[0]), "r"(a[1]), "r"(a[2]), "r"(a[3]), "r"(b[0]), "r"(b[1]));
}

__device__ __forceinline__ void ldsm4(uint32_t* r, uint32_t addr) {
    asm volatile("ldmatrix.sync.aligned.m8n8.x4.shared.b16 {%0,%1,%2,%3}, [%4];"
        : "=r"(r[0]), "=r"(r[1]), "=r"(r[2]), "=r"(r[3]) : "r"(addr));
}

// ---------------- ALL weights transpose + bf16 split in ONE launch ----------------
// W[K,N] fp32 -> hiT/loT [N,K] bf16. Flat tile dispatch over 4 layers x 7 matrices.
// tiles per type: Q 4096, K 1024, V 1024, O 4096, G 11264, U 11264, D 11264 -> 44032/layer
#define TILES_PER_LAYER 44032
__global__ void wsplit_all_kernel(const float* __restrict__ wq, const float* __restrict__ wk,
                                  const float* __restrict__ wv, const float* __restrict__ wo,
                                  const float* __restrict__ wg, const float* __restrict__ wu,
                                  const float* __restrict__ wd,
                                  __nv_bfloat16* __restrict__ hiT,
                                  __nv_bfloat16* __restrict__ loT) {
    int l = blockIdx.x / TILES_PER_LAYER;
    int r = blockIdx.x % TILES_PER_LAYER;
    const float* src; size_t woff; int K, N, tidx;
    if (r < 4096)       { src = wq + (size_t)l * Hc * QNc; woff = WOFF_Q; K = Hc;  N = QNc; tidx = r; }
    else if (r < 5120)  { src = wk + (size_t)l * Hc * KNc; woff = WOFF_K; K = Hc;  N = KNc; tidx = r - 4096; }
    else if (r < 6144)  { src = wv + (size_t)l * Hc * KNc; woff = WOFF_V; K = Hc;  N = KNc; tidx = r - 5120; }
    else if (r < 10240) { src = wo + (size_t)l * QNc * Hc; woff = WOFF_O; K = QNc; N = Hc;  tidx = r - 6144; }
    else if (r < 21504) { src = wg + (size_t)l * Hc * Fc;  woff = WOFF_G; K = Hc;  N = Fc;  tidx = r - 10240; }
    else if (r < 32768) { src = wu + (size_t)l * Hc * Fc;  woff = WOFF_U; K = Hc;  N = Fc;  tidx = r - 21504; }
    else                { src = wd + (size_t)l * Fc * Hc;  woff = WOFF_D; K = Fc;  N = Hc;  tidx = r - 32768; }
    woff += (size_t)l * LAYER_W;
    int nt = N / 32;
    int k0 = (tidx / nt) * 32, n0 = (tidx % nt) * 32;

    __shared__ float tile[32][33];
    int tx = threadIdx.x, ty = threadIdx.y;
    for (int i = ty; i < 32; i += 8)
        tile[i][tx] = src[(size_t)(k0 + i) * N + n0 + tx];
    __syncthreads();
    for (int i = ty; i < 32; i += 8) {
        float v = tile[tx][i];
        __nv_bfloat16 hb = __float2bfloat16(v);
        float lo = v - __bfloat162float(hb);
        size_t idx = woff + (size_t)(n0 + i) * K + k0 + tx;
        hiT[idx] = hb;
        loT[idx] = __float2bfloat16(lo);
    }
}

// ---------------- embedding gather ----------------
__global__ void embed_kernel(const int* __restrict__ ids,
                             const float* __restrict__ emb,
                             float* __restrict__ h) {
    int row = blockIdx.x;
    const float* src = emb + (size_t)ids[row] * Hc;
    float* dst = h + (size_t)row * Hc;
    for (int i = threadIdx.x; i < Hc; i += 256) dst[i] = src[i];
}

// ---------------- rmsnorm: fp32 out + bf16 hi/lo split ----------------
__global__ void rmsnorm_kernel(const float* __restrict__ in,
                               const float* __restrict__ w,
                               float* __restrict__ out,
                               __nv_bfloat16* __restrict__ oh,
                               __nv_bfloat16* __restrict__ ol) {
    int row = blockIdx.x;
    const float* x = in + (size_t)row * Hc;
    float ss = 0.f;
    for (int i = threadIdx.x; i < Hc; i += 256) { float v = x[i]; ss += v * v; }
    __shared__ float sh[256];
    sh[threadIdx.x] = ss; __syncthreads();
    for (int o = 128; o; o >>= 1) { if (threadIdx.x < o) sh[threadIdx.x] += sh[threadIdx.x + o]; __syncthreads(); }
    float sc = rsqrtf(sh[0] / (float)Hc + 1e-6f);
    for (int i = threadIdx.x; i < Hc; i += 256) {
        float v = x[i] * sc * w[i];
        out[(size_t)row * Hc + i] = v;
        __nv_bfloat16 hb = __float2bfloat16(v);
        oh[(size_t)row * Hc + i] = hb;
        ol[(size_t)row * Hc + i] = __float2bfloat16(v - __bfloat162float(hb));
    }
}

// ---------------- bf16x3 mma.sync GEMM, ldmatrix + 3-stage cp.async, de-spilled ----------------
// C[M,N] = (Ahi+Alo)[M,K] * (Bhi+Blo)^T  (B stored [N,K] row-major).
// Optional fused: +bias, +resid, +LORA_SCALE*(loraT @ loraB^T). gridDim.z selects target 2.
// CTA 128x128, k-tile 32, 8 warps (4M x 2N), warp tile 32x64 (2x8 m16n8k16).
// Mainloop register staging keeps peak live frags at afH(8)+afL(8)+bf(16): fits 128 regs @ 2 CTAs/SM.
#define TILE_B 8192                  // 128 * 64B
#define STAGE_B (4 * TILE_B)         // Ah, Al, Bh, Bl = 32KB
#define NSTAGE 3
#define GEMM_SMEM (NSTAGE * STAGE_B) // 96KB

__global__ __launch_bounds__(256, 2) void gemm_bf16x3(
    const __nv_bfloat16* __restrict__ Ahi, const __nv_bfloat16* __restrict__ Alo,
    const __nv_bfloat16* __restrict__ Bhi1, const __nv_bfloat16* __restrict__ Blo1,
    const float* __restrict__ bias1, const float* __restrict__ resid1,
    const float* __restrict__ loraT1, const float* __restrict__ loraB1,
    float* __restrict__ C1,
    const __nv_bfloat16* __restrict__ Bhi2, const __nv_bfloat16* __restrict__ Blo2,
    const float* __restrict__ bias2, const float* __restrict__ resid2,
    const float* __restrict__ loraT2, const float* __restrict__ loraB2,
    float* __restrict__ C2,
    int M, int N, int K) {
    extern __shared__ uint8_t smraw[];
    const int tid = threadIdx.x;
    const int bm = blockIdx.y * 128, bn = blockIdx.x * 128;

    const __nv_bfloat16* Bhi = Bhi1; const __nv_bfloat16* Blo = Blo1;
    const float* bias = bias1; const float* resid = resid1;
    const float* loraT = loraT1; const float* loraB = loraB1;
    float* C = C1;
    if (blockIdx.z == 1) {
        Bhi = Bhi2; Blo = Blo2; bias = bias2; resid = resid2;
        loraT = loraT2; loraB = loraB2; C = C2;
    }

    const int warpId = tid >> 5, lane = tid & 31;
    const int warpM = warpId & 3, warpN = warpId >> 2;
    const int m0 = warpM * 32, n0 = warpN * 64;
    const int grp = lane >> 2, qd = lane & 3;

    // ldmatrix addressing
    const int lrow16 = lane & 15;
    const int lch    = lane >> 4;
    const int lsw    = (lrow16 >> 1) & 3;
    const uint32_t sb = sptr(smraw);

    // loader: thread -> row (0..127), 2 granules of 16B
    const int lrow = tid >> 1, lg0 = (tid & 1) * 2;
    const int lswz = (lrow >> 1) & 3;
    const __nv_bfloat16* pAh = Ahi + (size_t)(bm + lrow) * K;
    const __nv_bfloat16* pAl = Alo + (size_t)(bm + lrow) * K;
    const __nv_bfloat16* pBh = Bhi + (size_t)(bn + lrow) * K;
    const __nv_bfloat16* pBl = Blo + (size_t)(bn + lrow) * K;
    const uint32_t srow = sb + lrow * 64;

    float acc[2][8][4];
    #pragma unroll
    for (int mt = 0; mt < 2; mt++)
        #pragma unroll
        for (int nt = 0; nt < 8; nt++)
            #pragma unroll
            for (int r = 0; r < 4; r++) acc[mt][nt][r] = 0.f;

    auto loadStage = [&](int st, int k0) {
        uint32_t d = srow + st * STAGE_B;
        #pragma unroll
        for (int i = 0; i < 2; i++) {
            int g = lg0 + i;
            uint32_t off = (uint32_t)(g ^ lswz) << 4;
            CP_ASYNC16(d + 0 * TILE_B + off, pAh + k0 + g * 8);
            CP_ASYNC16(d + 1 * TILE_B + off, pAl + k0 + g * 8);
            CP_ASYNC16(d + 2 * TILE_B + off, pBh + k0 + g * 8);
            CP_ASYNC16(d + 3 * TILE_B + off, pBl + k0 + g * 8);
        }
        CP_COMMIT();
    };

    const int KT = K >> 5;
    loadStage(0, 0);
    if (KT > 1) loadStage(1, 32);

    for (int kt = 0; kt < KT; kt++) {
        const int st = kt % NSTAGE;
        if (kt + 1 < KT) { CP_WAIT(1); } else { CP_WAIT(0); }
        __syncthreads();
        if (kt + 2 < KT) loadStage((kt + 2) % NSTAGE, (kt + 2) << 5);

        const uint32_t tAh = sb + st * STAGE_B;
        const uint32_t tAl = tAh + TILE_B;
        const uint32_t tBh = tAh + 2 * TILE_B;
        const uint32_t tBl = tAh + 3 * TILE_B;

        #pragma unroll
        for (int ks = 0; ks < 2; ks++) {
            const uint32_t choff = (uint32_t)(((ks * 2 + lch) ^ lsw)) << 4;
            uint32_t ra0 = (uint32_t)(m0 + lrow16) * 64 + choff;
            uint32_t ra1 = (uint32_t)(m0 + 16 + lrow16) * 64 + choff;
            uint32_t rb0 = (uint32_t)(n0 + lrow16) * 64 + choff;

            uint32_t afH[2][4], afL[2][4], bf[8][2];

            // --- B hi fragments ---
            #pragma unroll
            for (int np = 0; np < 4; np++) {
                uint32_t q[4];
                ldsm4(q, tBh + rb0 + (uint32_t)(np * 16 * 64));
                bf[2 * np][0] = q[0]; bf[2 * np + 1][0] = q[1];
                bf[2 * np][1] = q[2]; bf[2 * np + 1][1] = q[3];
            }
            // --- A hi, product HH ---
            ldsm4(afH[0], tAh + ra0);
            ldsm4(afH[1], tAh + ra1);
            #pragma unroll
            for (int mt = 0; mt < 2; mt++)
                #pragma unroll
                for (int nt = 0; nt < 8; nt++)
                    mma_bf16(acc[mt][nt], afH[mt], bf[nt]);
            // --- A lo, product LH ---
            ldsm4(afL[0], tAl + ra0);
            ldsm4(afL[1], tAl + ra1);
            #pragma unroll
            for (int mt = 0; mt < 2; mt++)
                #pragma unroll
                for (int nt = 0; nt < 8; nt++)
                    mma_bf16(acc[mt][nt], afL[mt], bf[nt]);
            // --- B lo overwrites bf, product HL ---
            #pragma unroll
            for (int np = 0; np < 4; np++) {
                uint32_t q[4];
                ldsm4(q, tBl + rb0 + (uint32_t)(np * 16 * 64));
                bf[2 * np][0] = q[0]; bf[2 * np + 1][0] = q[1];
                bf[2 * np][1] = q[2]; bf[2 * np + 1][1] = q[3];
            }
            #pragma unroll
            for (int mt = 0; mt < 2; mt++)
                #pragma unroll
                for (int nt = 0; nt < 8; nt++)
                    mma_bf16(acc[mt][nt], afH[mt], bf[nt]);
        }
    }
    __syncthreads();

    // stage LoRA factors in smem (tiles no longer needed)
    float* sT = (float*)smraw;                 // 128 x 16 fp32
    float* sB = (float*)(smraw + 8192);        // 128 x 16 fp32
    if (loraT) {
        const float4* gT = (const float4*)(loraT + (size_t)bm * Rc);
        const float4* gB = (const float4*)(loraB + (size_t)bn * Rc);
        for (int i = tid; i < 512; i += 256) {
            ((float4*)sT)[i] = gT[i];
            ((float4*)sB)[i] = gB[i];
        }
        __syncthreads();
    }

    // epilogue
    #pragma unroll
    for (int mt = 0; mt < 2; mt++) {
        int lr0 = m0 + mt * 16 + grp;
        int lr1 = lr0 + 8;
        int row0 = bm + lr0, row1 = bm + lr1;
        #pragma unroll
        for (int nt = 0; nt < 8; nt++) {
            int lc0 = n0 + nt * 8 + 2 * qd;
            int lc1 = lc0 + 1;
            int col0 = bn + lc0, col1 = bn + lc1;
            float o00 = acc[mt][nt][0], o01 = acc[mt][nt][1];
            float o10 = acc[mt][nt][2], o11 = acc[mt][nt][3];
            if (loraT) {
                const float* t0 = sT + lr0 * Rc;
                const float* t1 = sT + lr1 * Rc;
                const float* c0 = sB + lc0 * Rc;
                const float* c1 = sB + lc1 * Rc;
                float l00 = 0.f, l01 = 0.f, l10 = 0.f, l11 = 0.f;
                #pragma unroll
                for (int r = 0; r < Rc; r++) {
                    float a0 = t0[r], a1 = t1[r], b0 = c0[r], b1 = c1[r];
                    l00 += a0 * b0; l01 += a0 * b1; l10 += a1 * b0; l11 += a1 * b1;
                }
                o00 += LORA_SCALE * l00; o01 += LORA_SCALE * l01;
                o10 += LORA_SCALE * l10; o11 += LORA_SCALE * l11;
            }
            if (bias) {
                float b0 = bias[col0], b1 = bias[col1];
                o00 += b0; o01 += b1; o10 += b0; o11 += b1;
            }
            if (resid) {
                o00 += resid[(size_t)row0 * N + col0];
                o01 += resid[(size_t)row0 * N + col1];
                o10 += resid[(size_t)row1 * N + col0];
                o11 += resid[(size_t)row1 * N + col1];
            }
            *(float2*)(C + (size_t)row0 * N + col0) = make_float2(o00, o01);
            *(float2*)(C + (size_t)row1 * N + col0) = make_float2(o10, o11);
        }
    }
}

// ---------------- LoRA down (3 targets in one launch): t[m,r] = sum_k x[m,k]*A[r,k] ----------------
__global__ void lora_down3_kernel(const float* __restrict__ x,
                                  const float* __restrict__ A1, float* __restrict__ t1,
                                  const float* __restrict__ A2, float* __restrict__ t2,
                                  const float* __restrict__ A3, float* __restrict__ t3,
                                  int K) {
    int m = blockIdx.x;
    const float* A = A1; float* t = t1;
    if (blockIdx.y == 1) { A = A2; t = t2; }
    else if (blockIdx.y == 2) { A = A3; t = t3; }
    if (A == nullptr) return;
    int r = threadIdx.y;
    int lane = threadIdx.x;
    const float* xr = x + (size_t)m * K;
    const float* Ar = A + (size_t)r * K;
    float acc = 0.f;
    for (int k = lane; k < K; k += 32) acc += xr[k] * Ar[k];
    #pragma unroll
    for (int o = 16; o; o >>= 1) acc += __shfl_xor_sync(0xFFFFFFFFu, acc, o);
    if (lane == 0) t[m * Rc + r] = acc;
}

// ---------------- RoPE (rotate_half), in place ----------------
__global__ void rope_kernel(float* __restrict__ buf, int nheads) {
    int token = blockIdx.x;
    int head  = blockIdx.y;
    int d = threadIdx.x;
    int s = token % Sc;
    float* p = buf + ((size_t)token * nheads + head) * DHc;
    float freq = powf(1000000.0f, -(float)d / 64.0f);
    float ang = (float)s * freq;
    float sn, cs;
    sincosf(ang, &sn, &cs);
    float x1 = p[d], x2 = p[d + 64];
    p[d]      = x1 * cs - x2 * sn;
    p[d + 64] = x2 * cs + x1 * sn;
}

// ---------------- attention scores: per (b,h): S = Q K^T / sqrt(DH) ----------------
__global__ __launch_bounds__(256) void attn_scores_kernel(const float* __restrict__ qb,
                                                          const float* __restrict__ kb,
                                                          float* __restrict__ scores) {
    int bh = blockIdx.z;
    int b = bh / NHc, hd = bh % NHc;
    const float* A  = qb + ((size_t)b * Sc * NHc + hd) * DHc;
    const float* Bm = kb + ((size_t)b * Sc * NKVc + hd / (NHc / NKVc)) * DHc;
    float* C = scores + (size_t)bh * Sc * Sc;
    const int lda = NHc * DHc, ldb = NKVc * DHc;
    int bm = blockIdx.y * 64, bn = blockIdx.x * 64;
    __shared__ float As[16][64];
    __shared__ float Bs[16][64];
    int tid = threadIdx.x;
    int lr = tid >> 2, lc = (tid & 3) * 4;
    int tx = tid & 15, ty = tid >> 4;
    float acc[4][4];
    #pragma unroll
    for (int i = 0; i < 4; i++)
        #pragma unroll
        for (int j = 0; j < 4; j++) acc[i][j] = 0.f;

    for (int k0 = 0; k0 < DHc; k0 += 16) {
        float4 av = *(const float4*)(A + (size_t)(bm + lr) * lda + k0 + lc);
        As[lc + 0][lr] = av.x; As[lc + 1][lr] = av.y; As[lc + 2][lr] = av.z; As[lc + 3][lr] = av.w;
        float4 bv = *(const float4*)(Bm + (size_t)(bn + lr) * ldb + k0 + lc);
        Bs[lc + 0][lr] = bv.x; Bs[lc + 1][lr] = bv.y; Bs[lc + 2][lr] = bv.z; Bs[lc + 3][lr] = bv.w;
        __syncthreads();
        #pragma unroll
        for (int kk = 0; kk < 16; kk++) {
            float ar[4], br[4];
            #pragma unroll
            for (int i = 0; i < 4; i++) ar[i] = As[kk][ty * 4 + i];
            #pragma unroll
            for (int j = 0; j < 4; j++) br[j] = Bs[kk][tx * 4 + j];
            #pragma unroll
            for (int i = 0; i < 4; i++)
                #pragma unroll
                for (int j = 0; j < 4; j++) acc[i][j] += ar[i] * br[j];
        }
        __syncthreads();
    }
    #pragma unroll
    for (int i = 0; i < 4; i++)
        #pragma unroll
        for (int j = 0; j < 4; j++)
            C[(size_t)(bm + ty * 4 + i) * Sc + bn + tx * 4 + j] = acc[i][j] * INV_SQRT_DH;
}

// ---------------- masked softmax ----------------
__global__ void softmax_kernel(float* __restrict__ scores, const int* __restrict__ mask) {
    int row = blockIdx.x;
    int qpos = row % Sc;
    int b = row / (NHc * Sc);
    float* r = scores + (size_t)row * Sc;
    int t = threadIdx.x;
    float v[4];
    float mx = -3.0e38f;
    #pragma unroll
    for (int i = 0; i < 4; i++) {
        int k = t + 128 * i;
        bool ok = (k <= qpos) && (mask[b * Sc + k] > 0);
        v[i] = ok ? r[k] : -1e30f;
        mx = fmaxf(mx, v[i]);
    }
    __shared__ float sh[128];
    sh[t] = mx; __syncthreads();
    for (int o = 64; o; o >>= 1) { if (t < o) sh[t] = fmaxf(sh[t], sh[t + o]); __syncthreads(); }
    mx = sh[0]; __syncthreads();
    float sm = 0.f;
    #pragma unroll
    for (int i = 0; i < 4; i++) { v[i] = expf(v[i] - mx); sm += v[i]; }
    sh[t] = sm; __syncthreads();
    for (int o = 64; o; o >>= 1) { if (t < o) sh[t] += sh[t + o]; __syncthreads(); }
    float inv = 1.0f / sh[0];
    #pragma unroll
    for (int i = 0; i < 4; i++) r[t + 128 * i] = v[i] * inv;
}

// ---------------- attention context: ctx = P V  (fp32 + bf16 split out) ----------------
__global__ __launch_bounds__(256) void attn_ctx_kernel(const float* __restrict__ scores,
                                                       const float* __restrict__ vb,
                                                       float* __restrict__ ctx,
                                                       __nv_bfloat16* __restrict__ ch,
                                                       __nv_bfloat16* __restrict__ cl) {
    int bh = blockIdx.z;
    int b = bh / NHc, hd = bh % NHc;
    const float* A  = scores + (size_t)bh * Sc * Sc;
    const float* Bm = vb + ((size_t)b * Sc * NKVc + hd / (NHc / NKVc)) * DHc;
    size_t cbase = ((size_t)b * Sc * NHc + hd) * DHc;
    const int ldb = NKVc * DHc, ldc = NHc * DHc;
    int bm = blockIdx.y * 64, bn = blockIdx.x * 64;
    __shared__ float As[16][64];
    __shared__ float Bs[16][64];
    int tid = threadIdx.x;
    int tx = tid & 15, ty = tid >> 4;
    float acc[4][4];
    #pragma unroll
    for (int i = 0; i < 4; i++)
        #pragma unroll
        for (int j = 0; j < 4; j++) acc[i][j] = 0.f;

    for (int k0 = 0; k0 < Sc; k0 += 16) {
        int lr = tid >> 2, lc = (tid & 3) * 4;
        float4 av = *(const float4*)(A + (size_t)(bm + lr) * Sc + k0 + lc);
        As[lc + 0][lr] = av.x; As[lc + 1][lr] = av.y; As[lc + 2][lr] = av.z; As[lc + 3][lr] = av.w;
        int kr = tid >> 4, nc = (tid & 15) * 4;
        float4 bv = *(const float4*)(Bm + (size_t)(k0 + kr) * ldb + bn + nc);
        *(float4*)(&Bs[kr][nc]) = bv;
        __syncthreads();
        #pragma unroll
        for (int kk = 0; kk < 16; kk++) {
            float ar[4], br[4];
            #pragma unroll
            for (int i = 0; i < 4; i++) ar[i] = As[kk][ty * 4 + i];
            #pragma unroll
            for (int j = 0; j < 4; j++) br[j] = Bs[kk][tx * 4 + j];
            #pragma unroll
            for (int i = 0; i < 4; i++)
                #pragma unroll
                for (int j = 0; j < 4; j++) acc[i][j] += ar[i] * br[j];
        }
        __syncthreads();
    }
    #pragma unroll
    for (int i = 0; i < 4; i++)
        #pragma unroll
        for (int j = 0; j < 4; j++) {
            size_t idx = cbase + (size_t)(bm + ty * 4 + i) * ldc + bn + tx * 4 + j;
            float v = acc[i][j];
            ctx[idx] = v;
            __nv_bfloat16 hb = __float2bfloat16(v);
            ch[idx] = hb;
            cl[idx] = __float2bfloat16(v - __bfloat162float(hb));
        }
}

// ---------------- silu(g)*u -> bf16 hi/lo ----------------
__global__ void silu_mul_kernel(const float* __restrict__ g, const float* __restrict__ u,
                                __nv_bfloat16* __restrict__ gh, __nv_bfloat16* __restrict__ gl, int n) {
    int i = blockIdx.x * 256 + threadIdx.x;
    if (i < n) {
        float x = g[i];
        float v = (x / (1.0f + expf(-x))) * u[i];
        __nv_bfloat16 hb = __float2bfloat16(v);
        gh[i] = hb;
        gl[i] = __float2bfloat16(v - __bfloat162float(hb));
    }
}

// ---------------- final pooling + rmsnorm(lnf) ----------------
__global__ void pool_kernel(const float* __restrict__ h, const int* __restrict__ mask,
                            const float* __restrict__ lnf, float* __restrict__ pooled) {
    int b = blockIdx.x;
    int t = threadIdx.x;
    __shared__ float sh[256];
    int cnt = 0;
    for (int i = t; i < Sc; i += 256) cnt += mask[b * Sc + i];
    sh[t] = (float)cnt; __syncthreads();
    for (int o = 128; o; o >>= 1) { if (t < o) sh[t] += sh[t + o]; __syncthreads(); }
    int last = (int)sh[0] - 1;
    __syncthreads();
    const float* row = h + ((size_t)b * Sc + last) * Hc;
    float ss = 0.f;
    for (int i = t; i < Hc; i += 256) { float x = row[i]; ss += x * x; }
    sh[t] = ss; __syncthreads();
    for (int o = 128; o; o >>= 1) { if (t < o) sh[t] += sh[t + o]; __syncthreads(); }
    float sc = rsqrtf(sh[0] / (float)Hc + 1e-6f);
    for (int i = t; i < Hc; i += 256) pooled[b * Hc + i] = row[i] * sc * lnf[i];
}

// ---------------- classifier ----------------
__global__ void cls1_kernel(const float* __restrict__ pooled, const float* __restrict__ cw1,
                            const float* __restrict__ cb1, float* __restrict__ hid) {
    int n = blockIdx.x * 128 + threadIdx.x;
    int b = blockIdx.y;
    float acc = cb1[n];
    const float* p = pooled + (size_t)b * Hc;
    for (int k = 0; k < Hc; k++) acc += p[k] * cw1[(size_t)k * Hc + n];
    hid[(size_t)b * Hc + n] = fmaxf(acc, 0.f);
}

__global__ void cls2_kernel(const float* __restrict__ hid, const float* __restrict__ cw2,
                            const float* __restrict__ cb2, float* __restrict__ out) {
    int b = blockIdx.x >> 1, c = blockIdx.x & 1;
    float acc = 0.f;
    for (int k = threadIdx.x; k < Hc; k += 128) acc += hid[(size_t)b * Hc + k] * cw2[k * NCc + c];
    __shared__ float sh[128];
    sh[threadIdx.x] = acc; __syncthreads();
    for (int o = 64; o; o >>= 1) { if (threadIdx.x < o) sh[threadIdx.x] += sh[threadIdx.x + o]; __syncthreads(); }
    if (threadIdx.x == 0) out[b * NCc + c] = sh[0] + cb2[c];
}

// ---------------- host orchestration ----------------
extern "C" void kernel_launch(void* const* d_in, const int* in_sizes, int n_in,
                              void* d_out, int out_size) {
    (void)in_sizes; (void)n_in; (void)out_size;
    const int*   ids   = (const int*)d_in[0];
    const int*   mask  = (const int*)d_in[1];
    const float* embed = (const float*)d_in[2];
    const float* ln1   = (const float*)d_in[3];
    const float* wq    = (const float*)d_in[4];
    const float* bq    = (const float*)d_in[5];
    const float* wk    = (const float*)d_in[6];
    const float* bk    = (const float*)d_in[7];
    const float* wv    = (const float*)d_in[8];
    const float* bv    = (const float*)d_in[9];
    const float* wo    = (const float*)d_in[10];
    const float* laq   = (const float*)d_in[11];
    const float* lbq   = (const float*)d_in[12];
    const float* lak   = (const float*)d_in[13];
    const float* lbk   = (const float*)d_in[14];
    const float* lav   = (const float*)d_in[15];
    const float* lbv   = (const float*)d_in[16];
    const float* lao   = (const float*)d_in[17];
    const float* lbo   = (const float*)d_in[18];
    const float* ln2   = (const float*)d_in[19];
    const float* wg    = (const float*)d_in[20];
    const float* wu    = (const float*)d_in[21];
    const float* wd    = (const float*)d_in[22];
    const float* lnf   = (const float*)d_in[23];
    const float* cw1   = (const float*)d_in[24];
    const float* cb1   = (const float*)d_in[25];
    const float* cw2   = (const float*)d_in[26];
    const float* cb2   = (const float*)d_in[27];
    float* out = (float*)d_out;

    cudaFuncSetAttribute(gemm_bf16x3, cudaFuncAttributeMaxDynamicSharedMemorySize, GEMM_SMEM);

    float *h, *x, *q, *k, *v, *t1, *t2, *t3, *sc, *ctx, *g, *u, *pooled, *cls;
    __nv_bfloat16 *xh, *xl, *ch, *cl, *gh, *gl, *whT, *wlT;
    cudaGetSymbolAddress((void**)&h,   d_h);
    cudaGetSymbolAddress((void**)&x,   d_x);
    cudaGetSymbolAddress((void**)&xh,  d_xh);
    cudaGetSymbolAddress((void**)&xl,  d_xl);
    cudaGetSymbolAddress((void**)&q,   d_q);
    cudaGetSymbolAddress((void**)&k,   d_k);
    cudaGetSymbolAddress((void**)&v,   d_v);
    cudaGetSymbolAddress((void**)&t1,  d_t1);
    cudaGetSymbolAddress((void**)&t2,  d_t2);
    cudaGetSymbolAddress((void**)&t3,  d_t3);
    cudaGetSymbolAddress((void**)&sc,  d_sc);
    cudaGetSymbolAddress((void**)&ctx, d_ctx);
    cudaGetSymbolAddress((void**)&ch,  d_ch);
    cudaGetSymbolAddress((void**)&cl,  d_cl);
    cudaGetSymbolAddress((void**)&g,   d_g);
    cudaGetSymbolAddress((void**)&u,   d_u);
    cudaGetSymbolAddress((void**)&gh,  d_gh);
    cudaGetSymbolAddress((void**)&gl,  d_gl);
    cudaGetSymbolAddress((void**)&pooled, d_pooled);
    cudaGetSymbolAddress((void**)&cls,    d_cls);
    cudaGetSymbolAddress((void**)&whT,    d_whT);
    cudaGetSymbolAddress((void**)&wlT,    d_wlT);

    // ---- split + transpose ALL weights in ONE launch ----
    wsplit_all_kernel<<<Lc * TILES_PER_LAYER, dim3(32, 8)>>>(wq, wk, wv, wo, wg, wu, wd, whT, wlT);

    embed_kernel<<<MTc, 256>>>(ids, embed, h);

    for (int l = 0; l < Lc; l++) {
        size_t lw = (size_t)l * LAYER_W;
        const float* LN1 = ln1 + (size_t)l * Hc;
        const float* BQ = bq + (size_t)l * QNc;
        const float* BK = bk + (size_t)l * KNc;
        const float* BV = bv + (size_t)l * KNc;
        const float* LAQ = laq + (size_t)l * Rc * Hc;  const float* LBQ = lbq + (size_t)l * QNc * Rc;
        const float* LAK = lak + (size_t)l * Rc * Hc;  const float* LBK = lbk + (size_t)l * KNc * Rc;
        const float* LAV = lav + (size_t)l * Rc * Hc;  const float* LBV = lbv + (size_t)l * KNc * Rc;
        const float* LAO = lao + (size_t)l * Rc * QNc; const float* LBO = lbo + (size_t)l * Hc * Rc;
        const float* LN2 = ln2 + (size_t)l * Hc;

        rmsnorm_kernel<<<MTc, 256>>>(h, LN1, x, xh, xl);

        lora_down3_kernel<<<dim3(MTc, 3), dim3(32, 16)>>>(x, LAQ, t1, LAK, t2, LAV, t3, Hc);

        // Q projection
        gemm_bf16x3<<<dim3(QNc / 128, MTc / 128, 1), 256, GEMM_SMEM>>>(
            xh, xl,
            whT + lw + WOFF_Q, wlT + lw + WOFF_Q, BQ, nullptr, t1, LBQ, q,
            nullptr, nullptr, nullptr, nullptr, nullptr, nullptr, nullptr,
            MTc, QNc, Hc);
        // K + V fused (z dim)
        gemm_bf16x3<<<dim3(KNc / 128, MTc / 128, 2), 256, GEMM_SMEM>>>(
            xh, xl,
            whT + lw + WOFF_K, wlT + lw + WOFF_K, BK, nullptr, t2, LBK, k,
            whT + lw + WOFF_V, wlT + lw + WOFF_V, BV, nullptr, t3, LBV, v,
            MTc, KNc, Hc);

        // RoPE
        rope_kernel<<<dim3(MTc, NHc), 64>>>(q, NHc);
        rope_kernel<<<dim3(MTc, NKVc), 64>>>(k, NKVc);

        // attention
        attn_scores_kernel<<<dim3(Sc / 64, Sc / 64, Bc * NHc), 256>>>(q, k, sc);
        softmax_kernel<<<Bc * NHc * Sc, 128>>>(sc, mask);
        attn_ctx_kernel<<<dim3(DHc / 64, Sc / 64, Bc * NHc), 256>>>(sc, v, ctx, ch, cl);

        // O projection: h = h + ctx@WO + lora
        lora_down3_kernel<<<dim3(MTc, 1), dim3(32, 16)>>>(ctx, LAO, t1,
                                                          nullptr, nullptr, nullptr, nullptr, QNc);
        gemm_bf16x3<<<dim3(Hc / 128, MTc / 128, 1), 256, GEMM_SMEM>>>(
            ch, cl,
            whT + lw + WOFF_O, wlT + lw + WOFF_O, nullptr, h, t1, LBO, h,
            nullptr, nullptr, nullptr, nullptr, nullptr, nullptr, nullptr,
            MTc, Hc, QNc);

        // MLP
        rmsnorm_kernel<<<MTc, 256>>>(h, LN2, x, xh, xl);
        gemm_bf16x3<<<dim3(Fc / 128, MTc / 128, 2), 256, GEMM_SMEM>>>(
            xh, xl,
            whT + lw + WOFF_G, wlT + lw + WOFF_G, nullptr, nullptr, nullptr, nullptr, g,
            whT + lw + WOFF_U, wlT + lw + WOFF_U, nullptr, nullptr, nullptr, nullptr, u,
            MTc, Fc, Hc);
        silu_mul_kernel<<<(MTc * Fc) / 256, 256>>>(g, u, gh, gl, MTc * Fc);
        gemm_bf16x3<<<dim3(Hc / 128, MTc / 128, 1), 256, GEMM_SMEM>>>(
            gh, gl,
            whT + lw + WOFF_D, wlT + lw + WOFF_D, nullptr, h, nullptr, nullptr, h,
            nullptr, nullptr, nullptr, nullptr, nullptr, nullptr, nullptr,
            MTc, Hc, Fc);
    }

    pool_kernel<<<Bc, 256>>>(h, mask, lnf, pooled);
    cls1_kernel<<<dim3(Hc / 128, Bc), 128>>>(pooled, cw1, cb1, cls);
    cls2_kernel<<<Bc * NCc, 128>>>(cls, cw2, cb2, out);
}

// round 9
// speedup vs baseline: 1.0689x; 1.0689x over previous
#include <cuda_runtime.h>
#include <cuda_bf16.h>
#include <cstddef>
#include <cstdint>
#include <math.h>

// ---------------- problem constants ----------------
#define Lc   4
#define Hc   2048
#define NHc  16
#define NKVc 4
#define DHc  128
#define Fc   5632
#define Rc   16
#define Bc   4
#define Sc   512
#define NCc  2
#define MTc  (Bc * Sc)          // 2048 tokens
#define QNc  (NHc * DHc)        // 2048
#define KNc  (NKVc * DHc)       // 512
#define LORA_SCALE 2.0f
#define INV_SQRT_DH 0.08838834764831845f

// per-layer transposed weight buffer offsets (elements)
#define WOFF_Q 0
#define WOFF_K (WOFF_Q + Hc * QNc)
#define WOFF_V (WOFF_K + Hc * KNc)
#define WOFF_O (WOFF_V + Hc * KNc)
#define WOFF_G (WOFF_O + QNc * Hc)
#define WOFF_U (WOFF_G + Hc * Fc)
#define WOFF_D (WOFF_U + Hc * Fc)
#define LAYER_W (WOFF_D + Fc * Hc)   // 45,088,768

// ---------------- scratch (static device memory; allocation-free) ----------------
__device__ float          d_h[MTc * Hc];
__device__ float          d_x[MTc * Hc];
__device__ __nv_bfloat16  d_xh[MTc * Hc];
__device__ __nv_bfloat16  d_xl[MTc * Hc];
__device__ float          d_q[MTc * QNc];
__device__ float          d_k[MTc * KNc];
__device__ float          d_v[MTc * KNc];
__device__ __nv_bfloat16  d_qh[MTc * QNc];
__device__ __nv_bfloat16  d_ql[MTc * QNc];
__device__ __nv_bfloat16  d_kh[MTc * KNc];
__device__ __nv_bfloat16  d_kl[MTc * KNc];
__device__ __nv_bfloat16  d_vTh[Bc * KNc * Sc];
__device__ __nv_bfloat16  d_vTl[Bc * KNc * Sc];
__device__ float          d_t1[MTc * Rc];
__device__ float          d_t2[MTc * Rc];
__device__ float          d_t3[MTc * Rc];
__device__ float          d_sc[Bc * NHc * Sc * Sc];
__device__ __nv_bfloat16  d_ph[Bc * NHc * Sc * Sc];
__device__ __nv_bfloat16  d_pl[Bc * NHc * Sc * Sc];
__device__ float          d_ctx[MTc * QNc];
__device__ __nv_bfloat16  d_ch[MTc * QNc];
__device__ __nv_bfloat16  d_cl[MTc * QNc];
__device__ float          d_g[MTc * Fc];
__device__ float          d_u[MTc * Fc];
__device__ __nv_bfloat16  d_gh[MTc * Fc];
__device__ __nv_bfloat16  d_gl[MTc * Fc];
__device__ float          d_pooled[Bc * Hc];
__device__ float          d_cls[Bc * Hc];
__device__ __nv_bfloat16  d_whT[(size_t)Lc * LAYER_W];  // hi weights, [N,K]
__device__ __nv_bfloat16  d_wlT[(size_t)Lc * LAYER_W];  // lo weights, [N,K]

// ---------------- PTX helpers ----------------
__device__ __forceinline__ uint32_t sptr(const void* p) {
    return (uint32_t)__cvta_generic_to_shared(p);
}
#define CP_ASYNC16(dst, src) asm volatile("cp.async.cg.shared.global [%0], [%1], 16;\n" :: "r"(dst), "l"(src))
#define CP_COMMIT()          asm volatile("cp.async.commit_group;\n" ::: "memory")
#define CP_WAIT(n)           asm volatile("cp.async.wait_group %0;\n" :: "n"(n) : "memory")

__device__ __forceinline__ void mma_bf16(float* c, const uint32_t* a, const uint32_t* b) {
    asm volatile(
        "mma.sync.aligned.m16n8k16.row.col.f32.bf16.bf16.f32 "
        "{%0,%1,%2,%3}, {%4,%5,%6,%7}, {%8,%9}, {%0,%1,%2,%3};\n"
        : "+f"(c[0]), "+f"(c[1]), "+f"(c[2]), "+f"(c[3])
        : "r"(a[0]), "r"(a[1]), "r"(a[2]), "r"(a[3]), "r"(b[0]), "r"(b[1]));
}

__device__ __forceinline__ void ldsm4(uint32_t* r, uint32_t addr) {
    asm volatile("ldmatrix.sync.aligned.m8n8.x4.shared.b16 {%0,%1,%2,%3}, [%4];"
        : "=r"(r[0]), "=r"(r[1]), "=r"(r[2]), "=r"(r[3]) : "r"(addr));
}

// ---------------- ALL weights transpose + bf16 split in ONE launch ----------------
#define TILES_PER_LAYER 44032
__global__ void wsplit_all_kernel(const float* __restrict__ wq, const float* __restrict__ wk,
                                  const float* __restrict__ wv, const float* __restrict__ wo,
                                  const float* __restrict__ wg, const float* __restrict__ wu,
                                  const float* __restrict__ wd,
                                  __nv_bfloat16* __restrict__ hiT,
                                  __nv_bfloat16* __restrict__ loT) {
    int l = blockIdx.x / TILES_PER_LAYER;
    int r = blockIdx.x % TILES_PER_LAYER;
    const float* src; size_t woff; int K, N, tidx;
    if (r < 4096)       { src = wq + (size_t)l * Hc * QNc; woff = WOFF_Q; K = Hc;  N = QNc; tidx = r; }
    else if (r < 5120)  { src = wk + (size_t)l * Hc * KNc; woff = WOFF_K; K = Hc;  N = KNc; tidx = r - 4096; }
    else if (r < 6144)  { src = wv + (size_t)l * Hc * KNc; woff = WOFF_V; K = Hc;  N = KNc; tidx = r - 5120; }
    else if (r < 10240) { src = wo + (size_t)l * QNc * Hc; woff = WOFF_O; K = QNc; N = Hc;  tidx = r - 6144; }
    else if (r < 21504) { src = wg + (size_t)l * Hc * Fc;  woff = WOFF_G; K = Hc;  N = Fc;  tidx = r - 10240; }
    else if (r < 32768) { src = wu + (size_t)l * Hc * Fc;  woff = WOFF_U; K = Hc;  N = Fc;  tidx = r - 21504; }
    else                { src = wd + (size_t)l * Fc * Hc;  woff = WOFF_D; K = Fc;  N = Hc;  tidx = r - 32768; }
    woff += (size_t)l * LAYER_W;
    int nt = N / 32;
    int k0 = (tidx / nt) * 32, n0 = (tidx % nt) * 32;

    __shared__ float tile[32][33];
    int tx = threadIdx.x, ty = threadIdx.y;
    for (int i = ty; i < 32; i += 8)
        tile[i][tx] = src[(size_t)(k0 + i) * N + n0 + tx];
    __syncthreads();
    for (int i = ty; i < 32; i += 8) {
        float v = tile[tx][i];
        __nv_bfloat16 hb = __float2bfloat16(v);
        float lo = v - __bfloat162float(hb);
        size_t idx = woff + (size_t)(n0 + i) * K + k0 + tx;
        hiT[idx] = hb;
        loT[idx] = __float2bfloat16(lo);
    }
}

// ---------------- embedding gather ----------------
__global__ void embed_kernel(const int* __restrict__ ids,
                             const float* __restrict__ emb,
                             float* __restrict__ h) {
    int row = blockIdx.x;
    const float* src = emb + (size_t)ids[row] * Hc;
    float* dst = h + (size_t)row * Hc;
    for (int i = threadIdx.x; i < Hc; i += 256) dst[i] = src[i];
}

// ---------------- rmsnorm: fp32 out + bf16 hi/lo split ----------------
__global__ void rmsnorm_kernel(const float* __restrict__ in,
                               const float* __restrict__ w,
                               float* __restrict__ out,
                               __nv_bfloat16* __restrict__ oh,
                               __nv_bfloat16* __restrict__ ol) {
    int row = blockIdx.x;
    const float* x = in + (size_t)row * Hc;
    float ss = 0.f;
    for (int i = threadIdx.x; i < Hc; i += 256) { float v = x[i]; ss += v * v; }
    __shared__ float sh[256];
    sh[threadIdx.x] = ss; __syncthreads();
    for (int o = 128; o; o >>= 1) { if (threadIdx.x < o) sh[threadIdx.x] += sh[threadIdx.x + o]; __syncthreads(); }
    float sc = rsqrtf(sh[0] / (float)Hc + 1e-6f);
    for (int i = threadIdx.x; i < Hc; i += 256) {
        float v = x[i] * sc * w[i];
        out[(size_t)row * Hc + i] = v;
        __nv_bfloat16 hb = __float2bfloat16(v);
        oh[(size_t)row * Hc + i] = hb;
        ol[(size_t)row * Hc + i] = __float2bfloat16(v - __bfloat162float(hb));
    }
}

// ---------------- bf16x3 mma.sync GEMM (projections), same as R8 ----------------
#define TILE_B 8192                  // 128 * 64B
#define STAGE_B (4 * TILE_B)         // Ah, Al, Bh, Bl = 32KB
#define NSTAGE 3
#define GEMM_SMEM (NSTAGE * STAGE_B) // 96KB

__global__ __launch_bounds__(256, 2) void gemm_bf16x3(
    const __nv_bfloat16* __restrict__ Ahi, const __nv_bfloat16* __restrict__ Alo,
    const __nv_bfloat16* __restrict__ Bhi1, const __nv_bfloat16* __restrict__ Blo1,
    const float* __restrict__ bias1, const float* __restrict__ resid1,
    const float* __restrict__ loraT1, const float* __restrict__ loraB1,
    float* __restrict__ C1,
    const __nv_bfloat16* __restrict__ Bhi2, const __nv_bfloat16* __restrict__ Blo2,
    const float* __restrict__ bias2, const float* __restrict__ resid2,
    const float* __restrict__ loraT2, const float* __restrict__ loraB2,
    float* __restrict__ C2,
    int M, int N, int K) {
    extern __shared__ uint8_t smraw[];
    const int tid = threadIdx.x;
    const int bm = blockIdx.y * 128, bn = blockIdx.x * 128;

    const __nv_bfloat16* Bhi = Bhi1; const __nv_bfloat16* Blo = Blo1;
    const float* bias = bias1; const float* resid = resid1;
    const float* loraT = loraT1; const float* loraB = loraB1;
    float* C = C1;
    if (blockIdx.z == 1) {
        Bhi = Bhi2; Blo = Blo2; bias = bias2; resid = resid2;
        loraT = loraT2; loraB = loraB2; C = C2;
    }

    const int warpId = tid >> 5, lane = tid & 31;
    const int warpM = warpId & 3, warpN = warpId >> 2;
    const int m0 = warpM * 32, n0 = warpN * 64;
    const int grp = lane >> 2, qd = lane & 3;

    const int lrow16 = lane & 15;
    const int lch    = lane >> 4;
    const int lsw    = (lrow16 >> 1) & 3;
    const uint32_t sb = sptr(smraw);

    const int lrow = tid >> 1, lg0 = (tid & 1) * 2;
    const int lswz = (lrow >> 1) & 3;
    const __nv_bfloat16* pAh = Ahi + (size_t)(bm + lrow) * K;
    const __nv_bfloat16* pAl = Alo + (size_t)(bm + lrow) * K;
    const __nv_bfloat16* pBh = Bhi + (size_t)(bn + lrow) * K;
    const __nv_bfloat16* pBl = Blo + (size_t)(bn + lrow) * K;
    const uint32_t srow = sb + lrow * 64;

    float acc[2][8][4];
    #pragma unroll
    for (int mt = 0; mt < 2; mt++)
        #pragma unroll
        for (int nt = 0; nt < 8; nt++)
            #pragma unroll
            for (int r = 0; r < 4; r++) acc[mt][nt][r] = 0.f;

    auto loadStage = [&](int st, int k0) {
        uint32_t d = srow + st * STAGE_B;
        #pragma unroll
        for (int i = 0; i < 2; i++) {
            int g = lg0 + i;
            uint32_t off = (uint32_t)(g ^ lswz) << 4;
            CP_ASYNC16(d + 0 * TILE_B + off, pAh + k0 + g * 8);
            CP_ASYNC16(d + 1 * TILE_B + off, pAl + k0 + g * 8);
            CP_ASYNC16(d + 2 * TILE_B + off, pBh + k0 + g * 8);
            CP_ASYNC16(d + 3 * TILE_B + off, pBl + k0 + g * 8);
        }
        CP_COMMIT();
    };

    const int KT = K >> 5;
    loadStage(0, 0);
    if (KT > 1) loadStage(1, 32);

    for (int kt = 0; kt < KT; kt++) {
        const int st = kt % NSTAGE;
        if (kt + 1 < KT) { CP_WAIT(1); } else { CP_WAIT(0); }
        __syncthreads();
        if (kt + 2 < KT) loadStage((kt + 2) % NSTAGE, (kt + 2) << 5);

        const uint32_t tAh = sb + st * STAGE_B;
        const uint32_t tAl = tAh + TILE_B;
        const uint32_t tBh = tAh + 2 * TILE_B;
        const uint32_t tBl = tAh + 3 * TILE_B;

        #pragma unroll
        for (int ks = 0; ks < 2; ks++) {
            const uint32_t choff = (uint32_t)(((ks * 2 + lch) ^ lsw)) << 4;
            uint32_t ra0 = (uint32_t)(m0 + lrow16) * 64 + choff;
            uint32_t ra1 = (uint32_t)(m0 + 16 + lrow16) * 64 + choff;
            uint32_t rb0 = (uint32_t)(n0 + lrow16) * 64 + choff;

            uint32_t afH[2][4], afL[2][4], bf[8][2];

            #pragma unroll
            for (int np = 0; np < 4; np++) {
                uint32_t q[4];
                ldsm4(q, tBh + rb0 + (uint32_t)(np * 16 * 64));
                bf[2 * np][0] = q[0]; bf[2 * np + 1][0] = q[1];
                bf[2 * np][1] = q[2]; bf[2 * np + 1][1] = q[3];
            }
            ldsm4(afH[0], tAh + ra0);
            ldsm4(afH[1], tAh + ra1);
            #pragma unroll
            for (int mt = 0; mt < 2; mt++)
                #pragma unroll
                for (int nt = 0; nt < 8; nt++)
                    mma_bf16(acc[mt][nt], afH[mt], bf[nt]);
            ldsm4(afL[0], tAl + ra0);
            ldsm4(afL[1], tAl + ra1);
            #pragma unroll
            for (int mt = 0; mt < 2; mt++)
                #pragma unroll
                for (int nt = 0; nt < 8; nt++)
                    mma_bf16(acc[mt][nt], afL[mt], bf[nt]);
            #pragma unroll
            for (int np = 0; np < 4; np++) {
                uint32_t q[4];
                ldsm4(q, tBl + rb0 + (uint32_t)(np * 16 * 64));
                bf[2 * np][0] = q[0]; bf[2 * np + 1][0] = q[1];
                bf[2 * np][1] = q[2]; bf[2 * np + 1][1] = q[3];
            }
            #pragma unroll
            for (int mt = 0; mt < 2; mt++)
                #pragma unroll
                for (int nt = 0; nt < 8; nt++)
                    mma_bf16(acc[mt][nt], afH[mt], bf[nt]);
        }
    }
    __syncthreads();

    float* sT = (float*)smraw;                 // 128 x 16 fp32
    float* sB = (float*)(smraw + 8192);        // 128 x 16 fp32
    if (loraT) {
        const float4* gT = (const float4*)(loraT + (size_t)bm * Rc);
        const float4* gB = (const float4*)(loraB + (size_t)bn * Rc);
        for (int i = tid; i < 512; i += 256) {
            ((float4*)sT)[i] = gT[i];
            ((float4*)sB)[i] = gB[i];
        }
        __syncthreads();
    }

    #pragma unroll
    for (int mt = 0; mt < 2; mt++) {
        int lr0 = m0 + mt * 16 + grp;
        int lr1 = lr0 + 8;
        int row0 = bm + lr0, row1 = bm + lr1;
        #pragma unroll
        for (int nt = 0; nt < 8; nt++) {
            int lc0 = n0 + nt * 8 + 2 * qd;
            int lc1 = lc0 + 1;
            int col0 = bn + lc0, col1 = bn + lc1;
            float o00 = acc[mt][nt][0], o01 = acc[mt][nt][1];
            float o10 = acc[mt][nt][2], o11 = acc[mt][nt][3];
            if (loraT) {
                const float* t0 = sT + lr0 * Rc;
                const float* t1 = sT + lr1 * Rc;
                const float* c0 = sB + lc0 * Rc;
                const float* c1 = sB + lc1 * Rc;
                float l00 = 0.f, l01 = 0.f, l10 = 0.f, l11 = 0.f;
                #pragma unroll
                for (int r = 0; r < Rc; r++) {
                    float a0 = t0[r], a1 = t1[r], b0 = c0[r], b1 = c1[r];
                    l00 += a0 * b0; l01 += a0 * b1; l10 += a1 * b0; l11 += a1 * b1;
                }
                o00 += LORA_SCALE * l00; o01 += LORA_SCALE * l01;
                o10 += LORA_SCALE * l10; o11 += LORA_SCALE * l11;
            }
            if (bias) {
                float b0 = bias[col0], b1 = bias[col1];
                o00 += b0; o01 += b1; o10 += b0; o11 += b1;
            }
            if (resid) {
                o00 += resid[(size_t)row0 * N + col0];
                o01 += resid[(size_t)row0 * N + col1];
                o10 += resid[(size_t)row1 * N + col0];
                o11 += resid[(size_t)row1 * N + col1];
            }
            *(float2*)(C + (size_t)row0 * N + col0) = make_float2(o00, o01);
            *(float2*)(C + (size_t)row1 * N + col0) = make_float2(o10, o11);
        }
    }
}

// ---------------- attention scores on tensor cores: S = Qs * K^T (bf16x3) ----------------
// grid (4, 4, B*NH); CTA tile 128x128; K-dim = DHc = 128 (KT=4). Skips fully-masked tiles.
__global__ __launch_bounds__(256, 2) void attn_scores_mma(
    const __nv_bfloat16* __restrict__ qh, const __nv_bfloat16* __restrict__ ql,
    const __nv_bfloat16* __restrict__ kh, const __nv_bfloat16* __restrict__ kl,
    float* __restrict__ scores) {
    if (blockIdx.x > blockIdx.y) return;   // fully causal-masked tile
    extern __shared__ uint8_t smraw[];
    const int tid = threadIdx.x;
    const int bh = blockIdx.z;
    const int b = bh >> 4, hd = bh & 15, kvh = hd >> 2;
    const int bm = blockIdx.y * 128, bn = blockIdx.x * 128;
    const __nv_bfloat16* Ah = qh + (size_t)b * Sc * QNc + (size_t)hd * DHc;
    const __nv_bfloat16* Al = ql + (size_t)b * Sc * QNc + (size_t)hd * DHc;
    const __nv_bfloat16* Bh = kh + (size_t)b * Sc * KNc + (size_t)kvh * DHc;
    const __nv_bfloat16* Bl = kl + (size_t)b * Sc * KNc + (size_t)kvh * DHc;
    float* C = scores + (size_t)bh * Sc * Sc;

    const int warpId = tid >> 5, lane = tid & 31;
    const int warpM = warpId & 3, warpN = warpId >> 2;
    const int m0 = warpM * 32, n0 = warpN * 64;
    const int grp = lane >> 2, qd = lane & 3;
    const int lrow16 = lane & 15, lch = lane >> 4, lsw = (lrow16 >> 1) & 3;
    const uint32_t sb = sptr(smraw);

    const int lrow = tid >> 1, lg0 = (tid & 1) * 2;
    const int lswz = (lrow >> 1) & 3;
    const __nv_bfloat16* pAh = Ah + (size_t)(bm + lrow) * QNc;
    const __nv_bfloat16* pAl = Al + (size_t)(bm + lrow) * QNc;
    const __nv_bfloat16* pBh = Bh + (size_t)(bn + lrow) * KNc;
    const __nv_bfloat16* pBl = Bl + (size_t)(bn + lrow) * KNc;
    const uint32_t srow = sb + lrow * 64;

    float acc[2][8][4];
    #pragma unroll
    for (int mt = 0; mt < 2; mt++)
        #pragma unroll
        for (int nt = 0; nt < 8; nt++)
            #pragma unroll
            for (int r = 0; r < 4; r++) acc[mt][nt][r] = 0.f;

    auto loadStage = [&](int st, int k0) {
        uint32_t d = srow + st * STAGE_B;
        #pragma unroll
        for (int i = 0; i < 2; i++) {
            int g = lg0 + i;
            uint32_t off = (uint32_t)(g ^ lswz) << 4;
            CP_ASYNC16(d + 0 * TILE_B + off, pAh + k0 + g * 8);
            CP_ASYNC16(d + 1 * TILE_B + off, pAl + k0 + g * 8);
            CP_ASYNC16(d + 2 * TILE_B + off, pBh + k0 + g * 8);
            CP_ASYNC16(d + 3 * TILE_B + off, pBl + k0 + g * 8);
        }
        CP_COMMIT();
    };

    const int KT = DHc >> 5;   // 4
    loadStage(0, 0);
    loadStage(1, 32);

    for (int kt = 0; kt < KT; kt++) {
        const int st = kt % NSTAGE;
        if (kt + 1 < KT) { CP_WAIT(1); } else { CP_WAIT(0); }
        __syncthreads();
        if (kt + 2 < KT) loadStage((kt + 2) % NSTAGE, (kt + 2) << 5);

        const uint32_t tAh = sb + st * STAGE_B;
        const uint32_t tAl = tAh + TILE_B;
        const uint32_t tBh = tAh + 2 * TILE_B;
        const uint32_t tBl = tAh + 3 * TILE_B;

        #pragma unroll
        for (int ks = 0; ks < 2; ks++) {
            const uint32_t choff = (uint32_t)(((ks * 2 + lch) ^ lsw)) << 4;
            uint32_t ra0 = (uint32_t)(m0 + lrow16) * 64 + choff;
            uint32_t ra1 = (uint32_t)(m0 + 16 + lrow16) * 64 + choff;
            uint32_t rb0 = (uint32_t)(n0 + lrow16) * 64 + choff;
            uint32_t afH[2][4], afL[2][4], bf[8][2];
            #pragma unroll
            for (int np = 0; np < 4; np++) {
                uint32_t q[4];
                ldsm4(q, tBh + rb0 + (uint32_t)(np * 16 * 64));
                bf[2 * np][0] = q[0]; bf[2 * np + 1][0] = q[1];
                bf[2 * np][1] = q[2]; bf[2 * np + 1][1] = q[3];
            }
            ldsm4(afH[0], tAh + ra0);
            ldsm4(afH[1], tAh + ra1);
            #pragma unroll
            for (int mt = 0; mt < 2; mt++)
                #pragma unroll
                for (int nt = 0; nt < 8; nt++)
                    mma_bf16(acc[mt][nt], afH[mt], bf[nt]);
            ldsm4(afL[0], tAl + ra0);
            ldsm4(afL[1], tAl + ra1);
            #pragma unroll
            for (int mt = 0; mt < 2; mt++)
                #pragma unroll
                for (int nt = 0; nt < 8; nt++)
                    mma_bf16(acc[mt][nt], afL[mt], bf[nt]);
            #pragma unroll
            for (int np = 0; np < 4; np++) {
                uint32_t q[4];
                ldsm4(q, tBl + rb0 + (uint32_t)(np * 16 * 64));
                bf[2 * np][0] = q[0]; bf[2 * np + 1][0] = q[1];
                bf[2 * np][1] = q[2]; bf[2 * np + 1][1] = q[3];
            }
            #pragma unroll
            for (int mt = 0; mt < 2; mt++)
                #pragma unroll
                for (int nt = 0; nt < 8; nt++)
                    mma_bf16(acc[mt][nt], afH[mt], bf[nt]);
        }
    }

    #pragma unroll
    for (int mt = 0; mt < 2; mt++) {
        int row0 = bm + m0 + mt * 16 + grp;
        int row1 = row0 + 8;
        #pragma unroll
        for (int nt = 0; nt < 8; nt++) {
            int col = bn + n0 + nt * 8 + 2 * qd;
            *(float2*)(C + (size_t)row0 * Sc + col) = make_float2(acc[mt][nt][0], acc[mt][nt][1]);
            *(float2*)(C + (size_t)row1 * Sc + col) = make_float2(acc[mt][nt][2], acc[mt][nt][3]);
        }
    }
}

// ---------------- attention context on tensor cores: ctx = P * V (bf16x3) ----------------
// grid (1, 4, B*NH); CTA 128x128 (N=DHc=128); K-loop truncated at causal boundary (exact).
__global__ __launch_bounds__(256, 2) void attn_ctx_mma(
    const __nv_bfloat16* __restrict__ ph, const __nv_bfloat16* __restrict__ pl,
    const __nv_bfloat16* __restrict__ vTh, const __nv_bfloat16* __restrict__ vTl,
    float* __restrict__ ctx,
    __nv_bfloat16* __restrict__ ch, __nv_bfloat16* __restrict__ cl) {
    extern __shared__ uint8_t smraw[];
    const int tid = threadIdx.x;
    const int bh = blockIdx.z;
    const int b = bh >> 4, hd = bh & 15, kvh = hd >> 2;
    const int bm = blockIdx.y * 128;
    const __nv_bfloat16* Ah = ph + (size_t)bh * Sc * Sc;
    const __nv_bfloat16* Al = pl + (size_t)bh * Sc * Sc;
    const __nv_bfloat16* Bh = vTh + ((size_t)b * KNc + (size_t)kvh * DHc) * Sc;
    const __nv_bfloat16* Bl = vTl + ((size_t)b * KNc + (size_t)kvh * DHc) * Sc;

    const int warpId = tid >> 5, lane = tid & 31;
    const int warpM = warpId & 3, warpN = warpId >> 2;
    const int m0 = warpM * 32, n0 = warpN * 64;
    const int grp = lane >> 2, qd = lane & 3;
    const int lrow16 = lane & 15, lch = lane >> 4, lsw = (lrow16 >> 1) & 3;
    const uint32_t sb = sptr(smraw);

    const int lrow = tid >> 1, lg0 = (tid & 1) * 2;
    const int lswz = (lrow >> 1) & 3;
    const __nv_bfloat16* pAh = Ah + (size_t)(bm + lrow) * Sc;
    const __nv_bfloat16* pAl = Al + (size_t)(bm + lrow) * Sc;
    const __nv_bfloat16* pBh = Bh + (size_t)lrow * Sc;
    const __nv_bfloat16* pBl = Bl + (size_t)lrow * Sc;
    const uint32_t srow = sb + lrow * 64;

    float acc[2][8][4];
    #pragma unroll
    for (int mt = 0; mt < 2; mt++)
        #pragma unroll
        for (int nt = 0; nt < 8; nt++)
            #pragma unroll
            for (int r = 0; r < 4; r++) acc[mt][nt][r] = 0.f;

    auto loadStage = [&](int st, int k0) {
        uint32_t d = srow + st * STAGE_B;
        #pragma unroll
        for (int i = 0; i < 2; i++) {
            int g = lg0 + i;
            uint32_t off = (uint32_t)(g ^ lswz) << 4;
            CP_ASYNC16(d + 0 * TILE_B + off, pAh + k0 + g * 8);
            CP_ASYNC16(d + 1 * TILE_B + off, pAl + k0 + g * 8);
            CP_ASYNC16(d + 2 * TILE_B + off, pBh + k0 + g * 8);
            CP_ASYNC16(d + 3 * TILE_B + off, pBl + k0 + g * 8);
        }
        CP_COMMIT();
    };

    const int KT = (bm >> 5) + 4;   // causal: keys <= bm+127 only (P beyond is exactly 0)
    loadStage(0, 0);
    loadStage(1, 32);

    for (int kt = 0; kt < KT; kt++) {
        const int st = kt % NSTAGE;
        if (kt + 1 < KT) { CP_WAIT(1); } else { CP_WAIT(0); }
        __syncthreads();
        if (kt + 2 < KT) loadStage((kt + 2) % NSTAGE, (kt + 2) << 5);

        const uint32_t tAh = sb + st * STAGE_B;
        const uint32_t tAl = tAh + TILE_B;
        const uint32_t tBh = tAh + 2 * TILE_B;
        const uint32_t tBl = tAh + 3 * TILE_B;

        #pragma unroll
        for (int ks = 0; ks < 2; ks++) {
            const uint32_t choff = (uint32_t)(((ks * 2 + lch) ^ lsw)) << 4;
            uint32_t ra0 = (uint32_t)(m0 + lrow16) * 64 + choff;
            uint32_t ra1 = (uint32_t)(m0 + 16 + lrow16) * 64 + choff;
            uint32_t rb0 = (uint32_t)(n0 + lrow16) * 64 + choff;
            uint32_t afH[2][4], afL[2][4], bf[8][2];
            #pragma unroll
            for (int np = 0; np < 4; np++) {
                uint32_t q[4];
                ldsm4(q, tBh + rb0 + (uint32_t)(np * 16 * 64));
                bf[2 * np][0] = q[0]; bf[2 * np + 1][0] = q[1];
                bf[2 * np][1] = q[2]; bf[2 * np + 1][1] = q[3];
            }
            ldsm4(afH[0], tAh + ra0);
            ldsm4(afH[1], tAh + ra1);
            #pragma unroll
            for (int mt = 0; mt < 2; mt++)
                #pragma unroll
                for (int nt = 0; nt < 8; nt++)
                    mma_bf16(acc[mt][nt], afH[mt], bf[nt]);
            ldsm4(afL[0], tAl + ra0);
            ldsm4(afL[1], tAl + ra1);
            #pragma unroll
            for (int mt = 0; mt < 2; mt++)
                #pragma unroll
                for (int nt = 0; nt < 8; nt++)
                    mma_bf16(acc[mt][nt], afL[mt], bf[nt]);
            #pragma unroll
            for (int np = 0; np < 4; np++) {
                uint32_t q[4];
                ldsm4(q, tBl + rb0 + (uint32_t)(np * 16 * 64));
                bf[2 * np][0] = q[0]; bf[2 * np + 1][0] = q[1];
                bf[2 * np][1] = q[2]; bf[2 * np + 1][1] = q[3];
            }
            #pragma unroll
            for (int mt = 0; mt < 2; mt++)
                #pragma unroll
                for (int nt = 0; nt < 8; nt++)
                    mma_bf16(acc[mt][nt], afH[mt], bf[nt]);
        }
    }

    // epilogue: ctx fp32 + bf16 hi/lo split, layout [token, hd*128+dim]
    #pragma unroll
    for (int mt = 0; mt < 2; mt++) {
        int lr0 = m0 + mt * 16 + grp;
        #pragma unroll
        for (int half = 0; half < 2; half++) {
            int row = bm + lr0 + half * 8;
            size_t base = ((size_t)(b * Sc + row)) * QNc + (size_t)hd * DHc;
            #pragma unroll
            for (int nt = 0; nt < 8; nt++) {
                int col = n0 + nt * 8 + 2 * qd;
                float v0 = acc[mt][nt][half * 2 + 0];
                float v1 = acc[mt][nt][half * 2 + 1];
                *(float2*)(ctx + base + col) = make_float2(v0, v1);
                __nv_bfloat16 h0 = __float2bfloat16(v0);
                __nv_bfloat16 h1 = __float2bfloat16(v1);
                __nv_bfloat162 hv; hv.x = h0; hv.y = h1;
                __nv_bfloat162 lv;
                lv.x = __float2bfloat16(v0 - __bfloat162float(h0));
                lv.y = __float2bfloat16(v1 - __bfloat162float(h1));
                *(__nv_bfloat162*)(ch + base + col) = hv;
                *(__nv_bfloat162*)(cl + base + col) = lv;
            }
        }
    }
}

// ---------------- LoRA down, tiled: t[m,r] = sum_k x[m,k]*A[r,k], K=2048 ----------------
// grid (MTc/64, nTargets), 256 threads. Reads x once per block via smem tiles.
__global__ __launch_bounds__(256) void lora_down_tiled(
    const float* __restrict__ x,
    const float* __restrict__ A1, float* __restrict__ t1,
    const float* __restrict__ A2, float* __restrict__ t2,
    const float* __restrict__ A3, float* __restrict__ t3,
    int K) {
    const float* A = A1; float* t = t1;
    if (blockIdx.y == 1) { A = A2; t = t2; }
    else if (blockIdx.y == 2) { A = A3; t = t3; }
    __shared__ float sx[64][33];
    __shared__ float sAT[32][16];
    const int tid = threadIdx.x;
    const int m0 = blockIdx.x * 64;
    const int m = tid & 63, rg = tid >> 6;          // 4 r per thread
    float acc[4] = {0.f, 0.f, 0.f, 0.f};

    for (int k0 = 0; k0 < K; k0 += 32) {
        // load x tile 64x32
        {
            int lm = tid >> 3, lk = (tid & 7) * 4;
            #pragma unroll
            for (int p = 0; p < 2; p++) {
                float4 v = *(const float4*)(x + (size_t)(m0 + lm + p * 32) * K + k0 + lk);
                sx[lm + p * 32][lk + 0] = v.x; sx[lm + p * 32][lk + 1] = v.y;
                sx[lm + p * 32][lk + 2] = v.z; sx[lm + p * 32][lk + 3] = v.w;
            }
        }
        // load A tile transposed: sAT[kk][r]
        {
            int e = tid;
            if (e < 512) {
                int r = e & 15, kk = e >> 4;
                sAT[kk][r] = A[(size_t)r * K + k0 + kk];
            }
            e = tid + 256;
            if (e < 512) {
                int r = e & 15, kk = e >> 4;
                sAT[kk][r] = A[(size_t)r * K + k0 + kk];
            }
        }
        __syncthreads();
        #pragma unroll
        for (int kk = 0; kk < 32; kk++) {
            float xv = sx[m][kk];
            float4 av = *(const float4*)(&sAT[kk][rg * 4]);
            acc[0] += xv * av.x; acc[1] += xv * av.y;
            acc[2] += xv * av.z; acc[3] += xv * av.w;
        }
        __syncthreads();
    }
    float4 o = make_float4(acc[0], acc[1], acc[2], acc[3]);
    *(float4*)(t + (size_t)(m0 + m) * Rc + rg * 4) = o;
}

// ---------------- RoPE + scale + bf16 hi/lo split ----------------
__global__ void rope_split_kernel(const float* __restrict__ buf, int nheads, float scale,
                                  __nv_bfloat16* __restrict__ oh, __nv_bfloat16* __restrict__ ol) {
    int token = blockIdx.x;
    int head  = blockIdx.y;
    int d = threadIdx.x;
    int s = token % Sc;
    const float* p = buf + ((size_t)token * nheads + head) * DHc;
    float freq = powf(1000000.0f, -(float)d / 64.0f);
    float ang = (float)s * freq;
    float sn, cs;
    sincosf(ang, &sn, &cs);
    float x1 = p[d], x2 = p[d + 64];
    float v0 = (x1 * cs - x2 * sn) * scale;
    float v1 = (x2 * cs + x1 * sn) * scale;
    size_t idx = ((size_t)token * nheads + head) * DHc;
    __nv_bfloat16 h0 = __float2bfloat16(v0);
    __nv_bfloat16 h1 = __float2bfloat16(v1);
    oh[idx + d]      = h0;
    ol[idx + d]      = __float2bfloat16(v0 - __bfloat162float(h0));
    oh[idx + d + 64] = h1;
    ol[idx + d + 64] = __float2bfloat16(v1 - __bfloat162float(h1));
}

// ---------------- V transpose + split: v[M,512] -> vT[b][dim512][token512] hi/lo ----------------
__global__ void vsplitT_kernel(const float* __restrict__ v,
                               __nv_bfloat16* __restrict__ vTh,
                               __nv_bfloat16* __restrict__ vTl) {
    __shared__ float tile[32][33];
    int b = blockIdx.z;
    int t0 = blockIdx.x * 32, d0 = blockIdx.y * 32;
    int tx = threadIdx.x, ty = threadIdx.y;
    for (int i = ty; i < 32; i += 8)
        tile[i][tx] = v[(size_t)(b * Sc + t0 + i) * KNc + d0 + tx];
    __syncthreads();
    for (int i = ty; i < 32; i += 8) {
        float val = tile[tx][i];
        size_t idx = ((size_t)b * KNc + d0 + i) * Sc + t0 + tx;
        __nv_bfloat16 hb = __float2bfloat16(val);
        vTh[idx] = hb;
        vTl[idx] = __float2bfloat16(val - __bfloat162float(hb));
    }
}

// ---------------- masked softmax -> bf16 hi/lo P ----------------
__global__ void softmax_kernel(const float* __restrict__ scores, const int* __restrict__ mask,
                               __nv_bfloat16* __restrict__ ph, __nv_bfloat16* __restrict__ pl) {
    int row = blockIdx.x;
    int qpos = row % Sc;
    int b = row / (NHc * Sc);
    const float* r = scores + (size_t)row * Sc;
    int t = threadIdx.x;
    float v[4];
    float mx = -3.0e38f;
    #pragma unroll
    for (int i = 0; i < 4; i++) {
        int k = t + 128 * i;
        bool ok = (k <= qpos) && (mask[b * Sc + k] > 0);
        v[i] = ok ? r[k] : -1e30f;
        mx = fmaxf(mx, v[i]);
    }
    __shared__ float sh[128];
    sh[t] = mx; __syncthreads();
    for (int o = 64; o; o >>= 1) { if (t < o) sh[t] = fmaxf(sh[t], sh[t + o]); __syncthreads(); }
    mx = sh[0]; __syncthreads();
    float sm = 0.f;
    #pragma unroll
    for (int i = 0; i < 4; i++) { v[i] = expf(v[i] - mx); sm += v[i]; }
    sh[t] = sm; __syncthreads();
    for (int o = 64; o; o >>= 1) { if (t < o) sh[t] += sh[t + o]; __syncthreads(); }
    float inv = 1.0f / sh[0];
    #pragma unroll
    for (int i = 0; i < 4; i++) {
        float p = v[i] * inv;
        __nv_bfloat16 hb = __float2bfloat16(p);
        ph[(size_t)row * Sc + t + 128 * i] = hb;
        pl[(size_t)row * Sc + t + 128 * i] = __float2bfloat16(p - __bfloat162float(hb));
    }
}

// ---------------- silu(g)*u -> bf16 hi/lo ----------------
__global__ void silu_mul_kernel(const float* __restrict__ g, const float* __restrict__ u,
                                __nv_bfloat16* __restrict__ gh, __nv_bfloat16* __restrict__ gl, int n) {
    int i = blockIdx.x * 256 + threadIdx.x;
    if (i < n) {
        float x = g[i];
        float v = (x / (1.0f + expf(-x))) * u[i];
        __nv_bfloat16 hb = __float2bfloat16(v);
        gh[i] = hb;
        gl[i] = __float2bfloat16(v - __bfloat162float(hb));
    }
}

// ---------------- final pooling + rmsnorm(lnf) ----------------
__global__ void pool_kernel(const float* __restrict__ h, const int* __restrict__ mask,
                            const float* __restrict__ lnf, float* __restrict__ pooled) {
    int b = blockIdx.x;
    int t = threadIdx.x;
    __shared__ float sh[256];
    int cnt = 0;
    for (int i = t; i < Sc; i += 256) cnt += mask[b * Sc + i];
    sh[t] = (float)cnt; __syncthreads();
    for (int o = 128; o; o >>= 1) { if (t < o) sh[t] += sh[t + o]; __syncthreads(); }
    int last = (int)sh[0] - 1;
    __syncthreads();
    const float* row = h + ((size_t)b * Sc + last) * Hc;
    float ss = 0.f;
    for (int i = t; i < Hc; i += 256) { float x = row[i]; ss += x * x; }
    sh[t] = ss; __syncthreads();
    for (int o = 128; o; o >>= 1) { if (t < o) sh[t] += sh[t + o]; __syncthreads(); }
    float sc = rsqrtf(sh[0] / (float)Hc + 1e-6f);
    for (int i = t; i < Hc; i += 256) pooled[b * Hc + i] = row[i] * sc * lnf[i];
}

// ---------------- classifier ----------------
__global__ void cls1_kernel(const float* __restrict__ pooled, const float* __restrict__ cw1,
                            const float* __restrict__ cb1, float* __restrict__ hid) {
    int n = blockIdx.x * 128 + threadIdx.x;
    int b = blockIdx.y;
    float acc = cb1[n];
    const float* p = pooled + (size_t)b * Hc;
    for (int k = 0; k < Hc; k++) acc += p[k] * cw1[(size_t)k * Hc + n];
    hid[(size_t)b * Hc + n] = fmaxf(acc, 0.f);
}

__global__ void cls2_kernel(const float* __restrict__ hid, const float* __restrict__ cw2,
                            const float* __restrict__ cb2, float* __restrict__ out) {
    int b = blockIdx.x >> 1, c = blockIdx.x & 1;
    float acc = 0.f;
    for (int k = threadIdx.x; k < Hc; k += 128) acc += hid[(size_t)b * Hc + k] * cw2[k * NCc + c];
    __shared__ float sh[128];
    sh[threadIdx.x] = acc; __syncthreads();
    for (int o = 64; o; o >>= 1) { if (threadIdx.x < o) sh[threadIdx.x] += sh[threadIdx.x + o]; __syncthreads(); }
    if (threadIdx.x == 0) out[b * NCc + c] = sh[0] + cb2[c];
}

// ---------------- host orchestration ----------------
extern "C" void kernel_launch(void* const* d_in, const int* in_sizes, int n_in,
                              void* d_out, int out_size) {
    (void)in_sizes; (void)n_in; (void)out_size;
    const int*   ids   = (const int*)d_in[0];
    const int*   mask  = (const int*)d_in[1];
    const float* embed = (const float*)d_in[2];
    const float* ln1   = (const float*)d_in[3];
    const float* wq    = (const float*)d_in[4];
    const float* bq    = (const float*)d_in[5];
    const float* wk    = (const float*)d_in[6];
    const float* bk    = (const float*)d_in[7];
    const float* wv    = (const float*)d_in[8];
    const float* bv    = (const float*)d_in[9];
    const float* wo    = (const float*)d_in[10];
    const float* laq   = (const float*)d_in[11];
    const float* lbq   = (const float*)d_in[12];
    const float* lak   = (const float*)d_in[13];
    const float* lbk   = (const float*)d_in[14];
    const float* lav   = (const float*)d_in[15];
    const float* lbv   = (const float*)d_in[16];
    const float* lao   = (const float*)d_in[17];
    const float* lbo   = (const float*)d_in[18];
    const float* ln2   = (const float*)d_in[19];
    const float* wg    = (const float*)d_in[20];
    const float* wu    = (const float*)d_in[21];
    const float* wd    = (const float*)d_in[22];
    const float* lnf   = (const float*)d_in[23];
    const float* cw1   = (const float*)d_in[24];
    const float* cb1   = (const float*)d_in[25];
    const float* cw2   = (const float*)d_in[26];
    const float* cb2   = (const float*)d_in[27];
    float* out = (float*)d_out;

    cudaFuncSetAttribute(gemm_bf16x3, cudaFuncAttributeMaxDynamicSharedMemorySize, GEMM_SMEM);
    cudaFuncSetAttribute(attn_scores_mma, cudaFuncAttributeMaxDynamicSharedMemorySize, GEMM_SMEM);
    cudaFuncSetAttribute(attn_ctx_mma, cudaFuncAttributeMaxDynamicSharedMemorySize, GEMM_SMEM);

    float *h, *x, *q, *k, *v, *t1, *t2, *t3, *sc, *ctx, *g, *u, *pooled, *cls;
    __nv_bfloat16 *xh, *xl, *qh, *ql, *kh, *kl, *vTh, *vTl, *ph, *pl, *ch, *cl, *gh, *gl, *whT, *wlT;
    cudaGetSymbolAddress((void**)&h,   d_h);
    cudaGetSymbolAddress((void**)&x,   d_x);
    cudaGetSymbolAddress((void**)&xh,  d_xh);
    cudaGetSymbolAddress((void**)&xl,  d_xl);
    cudaGetSymbolAddress((void**)&q,   d_q);
    cudaGetSymbolAddress((void**)&k,   d_k);
    cudaGetSymbolAddress((void**)&v,   d_v);
    cudaGetSymbolAddress((void**)&qh,  d_qh);
    cudaGetSymbolAddress((void**)&ql,  d_ql);
    cudaGetSymbolAddress((void**)&kh,  d_kh);
    cudaGetSymbolAddress((void**)&kl,  d_kl);
    cudaGetSymbolAddress((void**)&vTh, d_vTh);
    cudaGetSymbolAddress((void**)&vTl, d_vTl);
    cudaGetSymbolAddress((void**)&t1,  d_t1);
    cudaGetSymbolAddress((void**)&t2,  d_t2);
    cudaGetSymbolAddress((void**)&t3,  d_t3);
    cudaGetSymbolAddress((void**)&sc,  d_sc);
    cudaGetSymbolAddress((void**)&ph,  d_ph);
    cudaGetSymbolAddress((void**)&pl,  d_pl);
    cudaGetSymbolAddress((void**)&ctx, d_ctx);
    cudaGetSymbolAddress((void**)&ch,  d_ch);
    cudaGetSymbolAddress((void**)&cl,  d_cl);
    cudaGetSymbolAddress((void**)&g,   d_g);
    cudaGetSymbolAddress((void**)&u,   d_u);
    cudaGetSymbolAddress((void**)&gh,  d_gh);
    cudaGetSymbolAddress((void**)&gl,  d_gl);
    cudaGetSymbolAddress((void**)&pooled, d_pooled);
    cudaGetSymbolAddress((void**)&cls,    d_cls);
    cudaGetSymbolAddress((void**)&whT,    d_whT);
    cudaGetSymbolAddress((void**)&wlT,    d_wlT);

    wsplit_all_kernel<<<Lc * TILES_PER_LAYER, dim3(32, 8)>>>(wq, wk, wv, wo, wg, wu, wd, whT, wlT);
    embed_kernel<<<MTc, 256>>>(ids, embed, h);

    for (int l = 0; l < Lc; l++) {
        size_t lw = (size_t)l * LAYER_W;
        const float* LN1 = ln1 + (size_t)l * Hc;
        const float* BQ = bq + (size_t)l * QNc;
        const float* BK = bk + (size_t)l * KNc;
        const float* BV = bv + (size_t)l * KNc;
        const float* LAQ = laq + (size_t)l * Rc * Hc;  const float* LBQ = lbq + (size_t)l * QNc * Rc;
        const float* LAK = lak + (size_t)l * Rc * Hc;  const float* LBK = lbk + (size_t)l * KNc * Rc;
        const float* LAV = lav + (size_t)l * Rc * Hc;  const float* LBV = lbv + (size_t)l * KNc * Rc;
        const float* LAO = lao + (size_t)l * Rc * QNc; const float* LBO = lbo + (size_t)l * Hc * Rc;
        const float* LN2 = ln2 + (size_t)l * Hc;

        rmsnorm_kernel<<<MTc, 256>>>(h, LN1, x, xh, xl);
        lora_down_tiled<<<dim3(MTc / 64, 3), 256>>>(x, LAQ, t1, LAK, t2, LAV, t3, Hc);

        gemm_bf16x3<<<dim3(QNc / 128, MTc / 128, 1), 256, GEMM_SMEM>>>(
            xh, xl,
            whT + lw + WOFF_Q, wlT + lw + WOFF_Q, BQ, nullptr, t1, LBQ, q,
            nullptr, nullptr, nullptr, nullptr, nullptr, nullptr, nullptr,
            MTc, QNc, Hc);
        gemm_bf16x3<<<dim3(KNc / 128, MTc / 128, 2), 256, GEMM_SMEM>>>(
            xh, xl,
            whT + lw + WOFF_K, wlT + lw + WOFF_K, BK, nullptr, t2, LBK, k,
            whT + lw + WOFF_V, wlT + lw + WOFF_V, BV, nullptr, t3, LBV, v,
            MTc, KNc, Hc);

        rope_split_kernel<<<dim3(MTc, NHc), 64>>>(q, NHc, INV_SQRT_DH, qh, ql);
        rope_split_kernel<<<dim3(MTc, NKVc), 64>>>(k, NKVc, 1.0f, kh, kl);
        vsplitT_kernel<<<dim3(16, 16, Bc), dim3(32, 8)>>>(v, vTh, vTl);

        attn_scores_mma<<<dim3(4, 4, Bc * NHc), 256, GEMM_SMEM>>>(qh, ql, kh, kl, sc);
        softmax_kernel<<<Bc * NHc * Sc, 128>>>(sc, mask, ph, pl);
        attn_ctx_mma<<<dim3(1, 4, Bc * NHc), 256, GEMM_SMEM>>>(ph, pl, vTh, vTl, ctx, ch, cl);

        lora_down_tiled<<<dim3(MTc / 64, 1), 256>>>(ctx, LAO, t1,
                                                    nullptr, nullptr, nullptr, nullptr, QNc);
        gemm_bf16x3<<<dim3(Hc / 128, MTc / 128, 1), 256, GEMM_SMEM>>>(
            ch, cl,
            whT + lw + WOFF_O, wlT + lw + WOFF_O, nullptr, h, t1, LBO, h,
            nullptr, nullptr, nullptr, nullptr, nullptr, nullptr, nullptr,
            MTc, Hc, QNc);

        rmsnorm_kernel<<<MTc, 256>>>(h, LN2, x, xh, xl);
        gemm_bf16x3<<<dim3(Fc / 128, MTc / 128, 2), 256, GEMM_SMEM>>>(
            xh, xl,
            whT + lw + WOFF_G, wlT + lw + WOFF_G, nullptr, nullptr, nullptr, nullptr, g,
            whT + lw + WOFF_U, wlT + lw + WOFF_U, nullptr, nullptr, nullptr, nullptr, u,
            MTc, Fc, Hc);
        silu_mul_kernel<<<(MTc * Fc) / 256, 256>>>(g, u, gh, gl, MTc * Fc);
        gemm_bf16x3<<<dim3(Hc / 128, MTc / 128, 1), 256, GEMM_SMEM>>>(
            gh, gl,
            whT + lw + WOFF_D, wlT + lw + WOFF_D, nullptr, h, nullptr, nullptr, h,
            nullptr, nullptr, nullptr, nullptr, nullptr, nullptr, nullptr,
            MTc, Hc, Fc);
    }

    pool_kernel<<<Bc, 256>>>(h, mask, lnf, pooled);
    cls1_kernel<<<dim3(Hc / 128, Bc), 128>>>(pooled, cw1, cb1, cls);
    cls2_kernel<<<Bc * NCc, 128>>>(cls, cw2, cb2, out);
}

// round 10
// speedup vs baseline: 1.1116x; 1.0400x over previous
#include <cuda_runtime.h>
#include <cuda_bf16.h>
#include <cstddef>
#include <cstdint>
#include <math.h>

// ---------------- problem constants ----------------
#define Lc   4
#define Hc   2048
#define NHc  16
#define NKVc 4
#define DHc  128
#define Fc   5632
#define Rc   16
#define Bc   4
#define Sc   512
#define NCc  2
#define MTc  (Bc * Sc)          // 2048 tokens
#define QNc  (NHc * DHc)        // 2048
#define KNc  (NKVc * DHc)       // 512
#define LORA_SCALE 2.0f
#define INV_SQRT_DH 0.08838834764831845f
#define LKS  4                  // lora k-split

// per-layer transposed weight buffer offsets (elements)
#define WOFF_Q 0
#define WOFF_K (WOFF_Q + Hc * QNc)
#define WOFF_V (WOFF_K + Hc * KNc)
#define WOFF_O (WOFF_V + Hc * KNc)
#define WOFF_G (WOFF_O + QNc * Hc)
#define WOFF_U (WOFF_G + Hc * Fc)
#define WOFF_D (WOFF_U + Hc * Fc)
#define LAYER_W (WOFF_D + Fc * Hc)   // 45,088,768

// ---------------- scratch (static device memory; allocation-free) ----------------
__device__ float          d_h[MTc * Hc];
__device__ float          d_x[MTc * Hc];
__device__ __nv_bfloat16  d_xh[MTc * Hc];
__device__ __nv_bfloat16  d_xl[MTc * Hc];
__device__ float          d_q[MTc * QNc];
__device__ float          d_k[MTc * KNc];
__device__ float          d_v[MTc * KNc];
__device__ __nv_bfloat16  d_qh[MTc * QNc];
__device__ __nv_bfloat16  d_ql[MTc * QNc];
__device__ __nv_bfloat16  d_kh[MTc * KNc];
__device__ __nv_bfloat16  d_kl[MTc * KNc];
__device__ __nv_bfloat16  d_vTh[Bc * KNc * Sc];
__device__ __nv_bfloat16  d_vTl[Bc * KNc * Sc];
__device__ float          d_t1[MTc * Rc];
__device__ float          d_t2[MTc * Rc];
__device__ float          d_t3[MTc * Rc];
__device__ float          d_tp[3 * LKS * MTc * Rc];
__device__ float          d_sc[Bc * NHc * Sc * Sc];
__device__ __nv_bfloat16  d_ph[Bc * NHc * Sc * Sc];
__device__ __nv_bfloat16  d_pl[Bc * NHc * Sc * Sc];
__device__ float          d_ctx[MTc * QNc];
__device__ __nv_bfloat16  d_ch[MTc * QNc];
__device__ __nv_bfloat16  d_cl[MTc * QNc];
__device__ float          d_g[MTc * Fc];
__device__ float          d_u[MTc * Fc];
__device__ __nv_bfloat16  d_gh[MTc * Fc];
__device__ __nv_bfloat16  d_gl[MTc * Fc];
__device__ float          d_pooled[Bc * Hc];
__device__ float          d_cls[Bc * Hc];
__device__ __nv_bfloat16  d_whT[(size_t)Lc * LAYER_W];  // hi weights, [N,K]
__device__ __nv_bfloat16  d_wlT[(size_t)Lc * LAYER_W];  // lo weights, [N,K]

// ---------------- PTX helpers ----------------
__device__ __forceinline__ uint32_t sptr(const void* p) {
    return (uint32_t)__cvta_generic_to_shared(p);
}
#define CP_ASYNC16(dst, src) asm volatile("cp.async.cg.shared.global [%0], [%1], 16;\n" :: "r"(dst), "l"(src))
#define CP_COMMIT()          asm volatile("cp.async.commit_group;\n" ::: "memory")
#define CP_WAIT(n)           asm volatile("cp.async.wait_group %0;\n" :: "n"(n) : "memory")

__device__ __forceinline__ void mma_bf16(float* c, const uint32_t* a, const uint32_t* b) {
    asm volatile(
        "mma.sync.aligned.m16n8k16.row.col.f32.bf16.bf16.f32 "
        "{%0,%1,%2,%3}, {%4,%5,%6,%7}, {%8,%9}, {%0,%1,%2,%3};\n"
        : "+f"(c[0]), "+f"(c[1]), "+f"(c[2]), "+f"(c[3])
        : "r"(a[0]), "r"(a[1]), "r"(a[2]), "r"(a[3]), "r"(b[0]), "r"(b[1]));
}

__device__ __forceinline__ void ldsm4(uint32_t* r, uint32_t addr) {
    asm volatile("ldmatrix.sync.aligned.m8n8.x4.shared.b16 {%0,%1,%2,%3}, [%4];"
        : "=r"(r[0]), "=r"(r[1]), "=r"(r[2]), "=r"(r[3]) : "r"(addr));
}

// ---------------- ALL weights transpose + bf16 split, full-line stores ----------------
// k-tile 64, n-tile 32. Tiles/layer: Q 2048, K 512, V 512, O 2048, G 5632, U 5632, D 5632.
#define TILES_PER_LAYER 22016
__global__ void wsplit_all_kernel(const float* __restrict__ wq, const float* __restrict__ wk,
                                  const float* __restrict__ wv, const float* __restrict__ wo,
                                  const float* __restrict__ wg, const float* __restrict__ wu,
                                  const float* __restrict__ wd,
                                  __nv_bfloat16* __restrict__ hiT,
                                  __nv_bfloat16* __restrict__ loT) {
    int l = blockIdx.x / TILES_PER_LAYER;
    int r = blockIdx.x % TILES_PER_LAYER;
    const float* src; size_t woff; int K, N, tidx;
    if (r < 2048)       { src = wq + (size_t)l * Hc * QNc; woff = WOFF_Q; K = Hc;  N = QNc; tidx = r; }
    else if (r < 2560)  { src = wk + (size_t)l * Hc * KNc; woff = WOFF_K; K = Hc;  N = KNc; tidx = r - 2048; }
    else if (r < 3072)  { src = wv + (size_t)l * Hc * KNc; woff = WOFF_V; K = Hc;  N = KNc; tidx = r - 2560; }
    else if (r < 5120)  { src = wo + (size_t)l * QNc * Hc; woff = WOFF_O; K = QNc; N = Hc;  tidx = r - 3072; }
    else if (r < 10752) { src = wg + (size_t)l * Hc * Fc;  woff = WOFF_G; K = Hc;  N = Fc;  tidx = r - 5120; }
    else if (r < 16384) { src = wu + (size_t)l * Hc * Fc;  woff = WOFF_U; K = Hc;  N = Fc;  tidx = r - 10752; }
    else                { src = wd + (size_t)l * Fc * Hc;  woff = WOFF_D; K = Fc;  N = Hc;  tidx = r - 16384; }
    woff += (size_t)l * LAYER_W;
    int nt = N / 32;
    int k0 = (tidx / nt) * 64, n0 = (tidx % nt) * 32;

    __shared__ float tile[64][33];   // [k][n]
    int tx = threadIdx.x, ty = threadIdx.y;   // (32, 8)
    for (int i = ty; i < 64; i += 8)
        tile[i][tx] = src[(size_t)(k0 + i) * N + n0 + tx];
    __syncthreads();
    for (int i = ty; i < 32; i += 8) {
        float v0 = tile[2 * tx][i], v1 = tile[2 * tx + 1][i];
        __nv_bfloat16 h0 = __float2bfloat16(v0), h1 = __float2bfloat16(v1);
        __nv_bfloat162 hv; hv.x = h0; hv.y = h1;
        __nv_bfloat162 lv;
        lv.x = __float2bfloat16(v0 - __bfloat162float(h0));
        lv.y = __float2bfloat16(v1 - __bfloat162float(h1));
        size_t idx = woff + (size_t)(n0 + i) * K + k0 + 2 * tx;
        *(__nv_bfloat162*)(hiT + idx) = hv;
        *(__nv_bfloat162*)(loT + idx) = lv;
    }
}

// ---------------- embedding gather ----------------
__global__ void embed_kernel(const int* __restrict__ ids,
                             const float* __restrict__ emb,
                             float* __restrict__ h) {
    int row = blockIdx.x;
    const float* src = emb + (size_t)ids[row] * Hc;
    float* dst = h + (size_t)row * Hc;
    for (int i = threadIdx.x; i < Hc; i += 256) dst[i] = src[i];
}

// ---------------- rmsnorm: fp32 out + bf16 hi/lo split ----------------
__global__ void rmsnorm_kernel(const float* __restrict__ in,
                               const float* __restrict__ w,
                               float* __restrict__ out,
                               __nv_bfloat16* __restrict__ oh,
                               __nv_bfloat16* __restrict__ ol) {
    int row = blockIdx.x;
    const float* x = in + (size_t)row * Hc;
    float ss = 0.f;
    for (int i = threadIdx.x; i < Hc; i += 256) { float v = x[i]; ss += v * v; }
    __shared__ float sh[256];
    sh[threadIdx.x] = ss; __syncthreads();
    for (int o = 128; o; o >>= 1) { if (threadIdx.x < o) sh[threadIdx.x] += sh[threadIdx.x + o]; __syncthreads(); }
    float sc = rsqrtf(sh[0] / (float)Hc + 1e-6f);
    for (int i = threadIdx.x; i < Hc; i += 256) {
        float v = x[i] * sc * w[i];
        out[(size_t)row * Hc + i] = v;
        __nv_bfloat16 hb = __float2bfloat16(v);
        oh[(size_t)row * Hc + i] = hb;
        ol[(size_t)row * Hc + i] = __float2bfloat16(v - __bfloat162float(hb));
    }
}

// ---------------- bf16x3 mma.sync GEMM (projections) ----------------
#define TILE_B 8192                  // 128 * 64B
#define STAGE_B (4 * TILE_B)         // Ah, Al, Bh, Bl = 32KB
#define NSTAGE 3
#define GEMM_SMEM (NSTAGE * STAGE_B) // 96KB

__global__ __launch_bounds__(256, 2) void gemm_bf16x3(
    const __nv_bfloat16* __restrict__ Ahi, const __nv_bfloat16* __restrict__ Alo,
    const __nv_bfloat16* __restrict__ Bhi1, const __nv_bfloat16* __restrict__ Blo1,
    const float* __restrict__ bias1, const float* __restrict__ resid1,
    const float* __restrict__ loraT1, const float* __restrict__ loraB1,
    float* __restrict__ C1,
    const __nv_bfloat16* __restrict__ Bhi2, const __nv_bfloat16* __restrict__ Blo2,
    const float* __restrict__ bias2, const float* __restrict__ resid2,
    const float* __restrict__ loraT2, const float* __restrict__ loraB2,
    float* __restrict__ C2,
    int M, int N, int K) {
    extern __shared__ uint8_t smraw[];
    const int tid = threadIdx.x;
    const int bm = blockIdx.y * 128, bn = blockIdx.x * 128;

    const __nv_bfloat16* Bhi = Bhi1; const __nv_bfloat16* Blo = Blo1;
    const float* bias = bias1; const float* resid = resid1;
    const float* loraT = loraT1; const float* loraB = loraB1;
    float* C = C1;
    if (blockIdx.z == 1) {
        Bhi = Bhi2; Blo = Blo2; bias = bias2; resid = resid2;
        loraT = loraT2; loraB = loraB2; C = C2;
    }

    const int warpId = tid >> 5, lane = tid & 31;
    const int warpM = warpId & 3, warpN = warpId >> 2;
    const int m0 = warpM * 32, n0 = warpN * 64;
    const int grp = lane >> 2, qd = lane & 3;

    const int lrow16 = lane & 15;
    const int lch    = lane >> 4;
    const int lsw    = (lrow16 >> 1) & 3;
    const uint32_t sb = sptr(smraw);

    const int lrow = tid >> 1, lg0 = (tid & 1) * 2;
    const int lswz = (lrow >> 1) & 3;
    const __nv_bfloat16* pAh = Ahi + (size_t)(bm + lrow) * K;
    const __nv_bfloat16* pAl = Alo + (size_t)(bm + lrow) * K;
    const __nv_bfloat16* pBh = Bhi + (size_t)(bn + lrow) * K;
    const __nv_bfloat16* pBl = Blo + (size_t)(bn + lrow) * K;
    const uint32_t srow = sb + lrow * 64;

    float acc[2][8][4];
    #pragma unroll
    for (int mt = 0; mt < 2; mt++)
        #pragma unroll
        for (int nt = 0; nt < 8; nt++)
            #pragma unroll
            for (int r = 0; r < 4; r++) acc[mt][nt][r] = 0.f;

    auto loadStage = [&](int st, int k0) {
        uint32_t d = srow + st * STAGE_B;
        #pragma unroll
        for (int i = 0; i < 2; i++) {
            int g = lg0 + i;
            uint32_t off = (uint32_t)(g ^ lswz) << 4;
            CP_ASYNC16(d + 0 * TILE_B + off, pAh + k0 + g * 8);
            CP_ASYNC16(d + 1 * TILE_B + off, pAl + k0 + g * 8);
            CP_ASYNC16(d + 2 * TILE_B + off, pBh + k0 + g * 8);
            CP_ASYNC16(d + 3 * TILE_B + off, pBl + k0 + g * 8);
        }
        CP_COMMIT();
    };

    const int KT = K >> 5;
    loadStage(0, 0);
    if (KT > 1) loadStage(1, 32);

    for (int kt = 0; kt < KT; kt++) {
        const int st = kt % NSTAGE;
        if (kt + 1 < KT) { CP_WAIT(1); } else { CP_WAIT(0); }
        __syncthreads();
        if (kt + 2 < KT) loadStage((kt + 2) % NSTAGE, (kt + 2) << 5);

        const uint32_t tAh = sb + st * STAGE_B;
        const uint32_t tAl = tAh + TILE_B;
        const uint32_t tBh = tAh + 2 * TILE_B;
        const uint32_t tBl = tAh + 3 * TILE_B;

        #pragma unroll
        for (int ks = 0; ks < 2; ks++) {
            const uint32_t choff = (uint32_t)(((ks * 2 + lch) ^ lsw)) << 4;
            uint32_t ra0 = (uint32_t)(m0 + lrow16) * 64 + choff;
            uint32_t ra1 = (uint32_t)(m0 + 16 + lrow16) * 64 + choff;
            uint32_t rb0 = (uint32_t)(n0 + lrow16) * 64 + choff;

            uint32_t afH[2][4], afL[2][4], bf[8][2];

            #pragma unroll
            for (int np = 0; np < 4; np++) {
                uint32_t q[4];
                ldsm4(q, tBh + rb0 + (uint32_t)(np * 16 * 64));
                bf[2 * np][0] = q[0]; bf[2 * np + 1][0] = q[1];
                bf[2 * np][1] = q[2]; bf[2 * np + 1][1] = q[3];
            }
            ldsm4(afH[0], tAh + ra0);
            ldsm4(afH[1], tAh + ra1);
            #pragma unroll
            for (int mt = 0; mt < 2; mt++)
                #pragma unroll
                for (int nt = 0; nt < 8; nt++)
                    mma_bf16(acc[mt][nt], afH[mt], bf[nt]);
            ldsm4(afL[0], tAl + ra0);
            ldsm4(afL[1], tAl + ra1);
            #pragma unroll
            for (int mt = 0; mt < 2; mt++)
                #pragma unroll
                for (int nt = 0; nt < 8; nt++)
                    mma_bf16(acc[mt][nt], afL[mt], bf[nt]);
            #pragma unroll
            for (int np = 0; np < 4; np++) {
                uint32_t q[4];
                ldsm4(q, tBl + rb0 + (uint32_t)(np * 16 * 64));
                bf[2 * np][0] = q[0]; bf[2 * np + 1][0] = q[1];
                bf[2 * np][1] = q[2]; bf[2 * np + 1][1] = q[3];
            }
            #pragma unroll
            for (int mt = 0; mt < 2; mt++)
                #pragma unroll
                for (int nt = 0; nt < 8; nt++)
                    mma_bf16(acc[mt][nt], afH[mt], bf[nt]);
        }
    }
    __syncthreads();

    float* sT = (float*)smraw;                 // 128 x 16 fp32
    float* sB = (float*)(smraw + 8192);        // 128 x 16 fp32
    if (loraT) {
        const float4* gT = (const float4*)(loraT + (size_t)bm * Rc);
        const float4* gB = (const float4*)(loraB + (size_t)bn * Rc);
        for (int i = tid; i < 512; i += 256) {
            ((float4*)sT)[i] = gT[i];
            ((float4*)sB)[i] = gB[i];
        }
        __syncthreads();
    }

    #pragma unroll
    for (int mt = 0; mt < 2; mt++) {
        int lr0 = m0 + mt * 16 + grp;
        int lr1 = lr0 + 8;
        int row0 = bm + lr0, row1 = bm + lr1;
        #pragma unroll
        for (int nt = 0; nt < 8; nt++) {
            int lc0 = n0 + nt * 8 + 2 * qd;
            int lc1 = lc0 + 1;
            int col0 = bn + lc0, col1 = bn + lc1;
            float o00 = acc[mt][nt][0], o01 = acc[mt][nt][1];
            float o10 = acc[mt][nt][2], o11 = acc[mt][nt][3];
            if (loraT) {
                const float* t0 = sT + lr0 * Rc;
                const float* t1 = sT + lr1 * Rc;
                const float* c0 = sB + lc0 * Rc;
                const float* c1 = sB + lc1 * Rc;
                float l00 = 0.f, l01 = 0.f, l10 = 0.f, l11 = 0.f;
                #pragma unroll
                for (int r = 0; r < Rc; r++) {
                    float a0 = t0[r], a1 = t1[r], b0 = c0[r], b1 = c1[r];
                    l00 += a0 * b0; l01 += a0 * b1; l10 += a1 * b0; l11 += a1 * b1;
                }
                o00 += LORA_SCALE * l00; o01 += LORA_SCALE * l01;
                o10 += LORA_SCALE * l10; o11 += LORA_SCALE * l11;
            }
            if (bias) {
                float b0 = bias[col0], b1 = bias[col1];
                o00 += b0; o01 += b1; o10 += b0; o11 += b1;
            }
            if (resid) {
                o00 += resid[(size_t)row0 * N + col0];
                o01 += resid[(size_t)row0 * N + col1];
                o10 += resid[(size_t)row1 * N + col0];
                o11 += resid[(size_t)row1 * N + col1];
            }
            *(float2*)(C + (size_t)row0 * N + col0) = make_float2(o00, o01);
            *(float2*)(C + (size_t)row1 * N + col0) = make_float2(o10, o11);
        }
    }
}

// ---------------- attention scores on tensor cores: S = Qs * K^T (bf16x3) ----------------
__global__ __launch_bounds__(256, 2) void attn_scores_mma(
    const __nv_bfloat16* __restrict__ qh, const __nv_bfloat16* __restrict__ ql,
    const __nv_bfloat16* __restrict__ kh, const __nv_bfloat16* __restrict__ kl,
    float* __restrict__ scores) {
    if (blockIdx.x > blockIdx.y) return;
    extern __shared__ uint8_t smraw[];
    const int tid = threadIdx.x;
    const int bh = blockIdx.z;
    const int b = bh >> 4, hd = bh & 15, kvh = hd >> 2;
    const int bm = blockIdx.y * 128, bn = blockIdx.x * 128;
    const __nv_bfloat16* Ah = qh + (size_t)b * Sc * QNc + (size_t)hd * DHc;
    const __nv_bfloat16* Al = ql + (size_t)b * Sc * QNc + (size_t)hd * DHc;
    const __nv_bfloat16* Bh = kh + (size_t)b * Sc * KNc + (size_t)kvh * DHc;
    const __nv_bfloat16* Bl = kl + (size_t)b * Sc * KNc + (size_t)kvh * DHc;
    float* C = scores + (size_t)bh * Sc * Sc;

    const int warpId = tid >> 5, lane = tid & 31;
    const int warpM = warpId & 3, warpN = warpId >> 2;
    const int m0 = warpM * 32, n0 = warpN * 64;
    const int grp = lane >> 2, qd = lane & 3;
    const int lrow16 = lane & 15, lch = lane >> 4, lsw = (lrow16 >> 1) & 3;
    const uint32_t sb = sptr(smraw);

    const int lrow = tid >> 1, lg0 = (tid & 1) * 2;
    const int lswz = (lrow >> 1) & 3;
    const __nv_bfloat16* pAh = Ah + (size_t)(bm + lrow) * QNc;
    const __nv_bfloat16* pAl = Al + (size_t)(bm + lrow) * QNc;
    const __nv_bfloat16* pBh = Bh + (size_t)(bn + lrow) * KNc;
    const __nv_bfloat16* pBl = Bl + (size_t)(bn + lrow) * KNc;
    const uint32_t srow = sb + lrow * 64;

    float acc[2][8][4];
    #pragma unroll
    for (int mt = 0; mt < 2; mt++)
        #pragma unroll
        for (int nt = 0; nt < 8; nt++)
            #pragma unroll
            for (int r = 0; r < 4; r++) acc[mt][nt][r] = 0.f;

    auto loadStage = [&](int st, int k0) {
        uint32_t d = srow + st * STAGE_B;
        #pragma unroll
        for (int i = 0; i < 2; i++) {
            int g = lg0 + i;
            uint32_t off = (uint32_t)(g ^ lswz) << 4;
            CP_ASYNC16(d + 0 * TILE_B + off, pAh + k0 + g * 8);
            CP_ASYNC16(d + 1 * TILE_B + off, pAl + k0 + g * 8);
            CP_ASYNC16(d + 2 * TILE_B + off, pBh + k0 + g * 8);
            CP_ASYNC16(d + 3 * TILE_B + off, pBl + k0 + g * 8);
        }
        CP_COMMIT();
    };

    const int KT = DHc >> 5;
    loadStage(0, 0);
    loadStage(1, 32);

    for (int kt = 0; kt < KT; kt++) {
        const int st = kt % NSTAGE;
        if (kt + 1 < KT) { CP_WAIT(1); } else { CP_WAIT(0); }
        __syncthreads();
        if (kt + 2 < KT) loadStage((kt + 2) % NSTAGE, (kt + 2) << 5);

        const uint32_t tAh = sb + st * STAGE_B;
        const uint32_t tAl = tAh + TILE_B;
        const uint32_t tBh = tAh + 2 * TILE_B;
        const uint32_t tBl = tAh + 3 * TILE_B;

        #pragma unroll
        for (int ks = 0; ks < 2; ks++) {
            const uint32_t choff = (uint32_t)(((ks * 2 + lch) ^ lsw)) << 4;
            uint32_t ra0 = (uint32_t)(m0 + lrow16) * 64 + choff;
            uint32_t ra1 = (uint32_t)(m0 + 16 + lrow16) * 64 + choff;
            uint32_t rb0 = (uint32_t)(n0 + lrow16) * 64 + choff;
            uint32_t afH[2][4], afL[2][4], bf[8][2];
            #pragma unroll
            for (int np = 0; np < 4; np++) {
                uint32_t q[4];
                ldsm4(q, tBh + rb0 + (uint32_t)(np * 16 * 64));
                bf[2 * np][0] = q[0]; bf[2 * np + 1][0] = q[1];
                bf[2 * np][1] = q[2]; bf[2 * np + 1][1] = q[3];
            }
            ldsm4(afH[0], tAh + ra0);
            ldsm4(afH[1], tAh + ra1);
            #pragma unroll
            for (int mt = 0; mt < 2; mt++)
                #pragma unroll
                for (int nt = 0; nt < 8; nt++)
                    mma_bf16(acc[mt][nt], afH[mt], bf[nt]);
            ldsm4(afL[0], tAl + ra0);
            ldsm4(afL[1], tAl + ra1);
            #pragma unroll
            for (int mt = 0; mt < 2; mt++)
                #pragma unroll
                for (int nt = 0; nt < 8; nt++)
                    mma_bf16(acc[mt][nt], afL[mt], bf[nt]);
            #pragma unroll
            for (int np = 0; np < 4; np++) {
                uint32_t q[4];
                ldsm4(q, tBl + rb0 + (uint32_t)(np * 16 * 64));
                bf[2 * np][0] = q[0]; bf[2 * np + 1][0] = q[1];
                bf[2 * np][1] = q[2]; bf[2 * np + 1][1] = q[3];
            }
            #pragma unroll
            for (int mt = 0; mt < 2; mt++)
                #pragma unroll
                for (int nt = 0; nt < 8; nt++)
                    mma_bf16(acc[mt][nt], afH[mt], bf[nt]);
        }
    }

    #pragma unroll
    for (int mt = 0; mt < 2; mt++) {
        int row0 = bm + m0 + mt * 16 + grp;
        int row1 = row0 + 8;
        #pragma unroll
        for (int nt = 0; nt < 8; nt++) {
            int col = bn + n0 + nt * 8 + 2 * qd;
            *(float2*)(C + (size_t)row0 * Sc + col) = make_float2(acc[mt][nt][0], acc[mt][nt][1]);
            *(float2*)(C + (size_t)row1 * Sc + col) = make_float2(acc[mt][nt][2], acc[mt][nt][3]);
        }
    }
}

// ---------------- attention context on tensor cores: ctx = P * V (bf16x3) ----------------
__global__ __launch_bounds__(256, 2) void attn_ctx_mma(
    const __nv_bfloat16* __restrict__ ph, const __nv_bfloat16* __restrict__ pl,
    const __nv_bfloat16* __restrict__ vTh, const __nv_bfloat16* __restrict__ vTl,
    float* __restrict__ ctx,
    __nv_bfloat16* __restrict__ ch, __nv_bfloat16* __restrict__ cl) {
    extern __shared__ uint8_t smraw[];
    const int tid = threadIdx.x;
    const int bh = blockIdx.z;
    const int b = bh >> 4, hd = bh & 15, kvh = hd >> 2;
    const int bm = blockIdx.y * 128;
    const __nv_bfloat16* Ah = ph + (size_t)bh * Sc * Sc;
    const __nv_bfloat16* Al = pl + (size_t)bh * Sc * Sc;
    const __nv_bfloat16* Bh = vTh + ((size_t)b * KNc + (size_t)kvh * DHc) * Sc;
    const __nv_bfloat16* Bl = vTl + ((size_t)b * KNc + (size_t)kvh * DHc) * Sc;

    const int warpId = tid >> 5, lane = tid & 31;
    const int warpM = warpId & 3, warpN = warpId >> 2;
    const int m0 = warpM * 32, n0 = warpN * 64;
    const int grp = lane >> 2, qd = lane & 3;
    const int lrow16 = lane & 15, lch = lane >> 4, lsw = (lrow16 >> 1) & 3;
    const uint32_t sb = sptr(smraw);

    const int lrow = tid >> 1, lg0 = (tid & 1) * 2;
    const int lswz = (lrow >> 1) & 3;
    const __nv_bfloat16* pAh = Ah + (size_t)(bm + lrow) * Sc;
    const __nv_bfloat16* pAl = Al + (size_t)(bm + lrow) * Sc;
    const __nv_bfloat16* pBh = Bh + (size_t)lrow * Sc;
    const __nv_bfloat16* pBl = Bl + (size_t)lrow * Sc;
    const uint32_t srow = sb + lrow * 64;

    float acc[2][8][4];
    #pragma unroll
    for (int mt = 0; mt < 2; mt++)
        #pragma unroll
        for (int nt = 0; nt < 8; nt++)
            #pragma unroll
            for (int r = 0; r < 4; r++) acc[mt][nt][r] = 0.f;

    auto loadStage = [&](int st, int k0) {
        uint32_t d = srow + st * STAGE_B;
        #pragma unroll
        for (int i = 0; i < 2; i++) {
            int g = lg0 + i;
            uint32_t off = (uint32_t)(g ^ lswz) << 4;
            CP_ASYNC16(d + 0 * TILE_B + off, pAh + k0 + g * 8);
            CP_ASYNC16(d + 1 * TILE_B + off, pAl + k0 + g * 8);
            CP_ASYNC16(d + 2 * TILE_B + off, pBh + k0 + g * 8);
            CP_ASYNC16(d + 3 * TILE_B + off, pBl + k0 + g * 8);
        }
        CP_COMMIT();
    };

    const int KT = (bm >> 5) + 4;
    loadStage(0, 0);
    loadStage(1, 32);

    for (int kt = 0; kt < KT; kt++) {
        const int st = kt % NSTAGE;
        if (kt + 1 < KT) { CP_WAIT(1); } else { CP_WAIT(0); }
        __syncthreads();
        if (kt + 2 < KT) loadStage((kt + 2) % NSTAGE, (kt + 2) << 5);

        const uint32_t tAh = sb + st * STAGE_B;
        const uint32_t tAl = tAh + TILE_B;
        const uint32_t tBh = tAh + 2 * TILE_B;
        const uint32_t tBl = tAh + 3 * TILE_B;

        #pragma unroll
        for (int ks = 0; ks < 2; ks++) {
            const uint32_t choff = (uint32_t)(((ks * 2 + lch) ^ lsw)) << 4;
            uint32_t ra0 = (uint32_t)(m0 + lrow16) * 64 + choff;
            uint32_t ra1 = (uint32_t)(m0 + 16 + lrow16) * 64 + choff;
            uint32_t rb0 = (uint32_t)(n0 + lrow16) * 64 + choff;
            uint32_t afH[2][4], afL[2][4], bf[8][2];
            #pragma unroll
            for (int np = 0; np < 4; np++) {
                uint32_t q[4];
                ldsm4(q, tBh + rb0 + (uint32_t)(np * 16 * 64));
                bf[2 * np][0] = q[0]; bf[2 * np + 1][0] = q[1];
                bf[2 * np][1] = q[2]; bf[2 * np + 1][1] = q[3];
            }
            ldsm4(afH[0], tAh + ra0);
            ldsm4(afH[1], tAh + ra1);
            #pragma unroll
            for (int mt = 0; mt < 2; mt++)
                #pragma unroll
                for (int nt = 0; nt < 8; nt++)
                    mma_bf16(acc[mt][nt], afH[mt], bf[nt]);
            ldsm4(afL[0], tAl + ra0);
            ldsm4(afL[1], tAl + ra1);
            #pragma unroll
            for (int mt = 0; mt < 2; mt++)
                #pragma unroll
                for (int nt = 0; nt < 8; nt++)
                    mma_bf16(acc[mt][nt], afL[mt], bf[nt]);
            #pragma unroll
            for (int np = 0; np < 4; np++) {
                uint32_t q[4];
                ldsm4(q, tBl + rb0 + (uint32_t)(np * 16 * 64));
                bf[2 * np][0] = q[0]; bf[2 * np + 1][0] = q[1];
                bf[2 * np][1] = q[2]; bf[2 * np + 1][1] = q[3];
            }
            #pragma unroll
            for (int mt = 0; mt < 2; mt++)
                #pragma unroll
                for (int nt = 0; nt < 8; nt++)
                    mma_bf16(acc[mt][nt], afH[mt], bf[nt]);
        }
    }

    #pragma unroll
    for (int mt = 0; mt < 2; mt++) {
        int lr0 = m0 + mt * 16 + grp;
        #pragma unroll
        for (int half = 0; half < 2; half++) {
            int row = bm + lr0 + half * 8;
            size_t base = ((size_t)(b * Sc + row)) * QNc + (size_t)hd * DHc;
            #pragma unroll
            for (int nt = 0; nt < 8; nt++) {
                int col = n0 + nt * 8 + 2 * qd;
                float v0 = acc[mt][nt][half * 2 + 0];
                float v1 = acc[mt][nt][half * 2 + 1];
                *(float2*)(ctx + base + col) = make_float2(v0, v1);
                __nv_bfloat16 h0 = __float2bfloat16(v0);
                __nv_bfloat16 h1 = __float2bfloat16(v1);
                __nv_bfloat162 hv; hv.x = h0; hv.y = h1;
                __nv_bfloat162 lv;
                lv.x = __float2bfloat16(v0 - __bfloat162float(h0));
                lv.y = __float2bfloat16(v1 - __bfloat162float(h1));
                *(__nv_bfloat162*)(ch + base + col) = hv;
                *(__nv_bfloat162*)(cl + base + col) = lv;
            }
        }
    }
}

// ---------------- LoRA down, k-split partials (deterministic 2-phase) ----------------
// grid (MTc/64, nTargets, LKS); partial[target][ks][m][r] += x[m, kchunk] * A[r, kchunk]
__global__ __launch_bounds__(256) void lora_down_part(
    const float* __restrict__ x,
    const float* __restrict__ A1, const float* __restrict__ A2, const float* __restrict__ A3,
    float* __restrict__ tp, int K) {
    const float* A = A1;
    if (blockIdx.y == 1) A = A2;
    else if (blockIdx.y == 2) A = A3;
    const int ks = blockIdx.z;
    const int kbeg = ks * (K / LKS), kend = kbeg + K / LKS;
    __shared__ float sx[64][33];
    __shared__ float sAT[32][16];
    const int tid = threadIdx.x;
    const int m0 = blockIdx.x * 64;
    const int m = tid & 63, rg = tid >> 6;
    float acc[4] = {0.f, 0.f, 0.f, 0.f};

    for (int k0 = kbeg; k0 < kend; k0 += 32) {
        {
            int lm = tid >> 3, lk = (tid & 7) * 4;
            #pragma unroll
            for (int p = 0; p < 2; p++) {
                float4 v = *(const float4*)(x + (size_t)(m0 + lm + p * 32) * K + k0 + lk);
                sx[lm + p * 32][lk + 0] = v.x; sx[lm + p * 32][lk + 1] = v.y;
                sx[lm + p * 32][lk + 2] = v.z; sx[lm + p * 32][lk + 3] = v.w;
            }
        }
        {
            int e = tid;
            if (e < 512) { int r = e & 15, kk = e >> 4; sAT[kk][r] = A[(size_t)r * K + k0 + kk]; }
            e = tid + 256;
            if (e < 512) { int r = e & 15, kk = e >> 4; sAT[kk][r] = A[(size_t)r * K + k0 + kk]; }
        }
        __syncthreads();
        #pragma unroll
        for (int kk = 0; kk < 32; kk++) {
            float xv = sx[m][kk];
            float4 av = *(const float4*)(&sAT[kk][rg * 4]);
            acc[0] += xv * av.x; acc[1] += xv * av.y;
            acc[2] += xv * av.z; acc[3] += xv * av.w;
        }
        __syncthreads();
    }
    float* out = tp + ((size_t)blockIdx.y * LKS + ks) * (MTc * Rc);
    *(float4*)(out + (size_t)(m0 + m) * Rc + rg * 4) = make_float4(acc[0], acc[1], acc[2], acc[3]);
}

__global__ void lora_reduce(const float* __restrict__ tp,
                            float* __restrict__ t1, float* __restrict__ t2, float* __restrict__ t3) {
    int i = blockIdx.x * 256 + threadIdx.x;
    int target = blockIdx.y;
    const float* p = tp + (size_t)target * LKS * (MTc * Rc);
    float s = p[i];
    #pragma unroll
    for (int ks = 1; ks < LKS; ks++) s += p[(size_t)ks * (MTc * Rc) + i];
    float* t = t1;
    if (target == 1) t = t2;
    else if (target == 2) t = t3;
    t[i] = s;
}

// ---------------- RoPE (q+k fused) + scale + bf16 hi/lo split ----------------
__global__ void rope_split2_kernel(const float* __restrict__ qb, const float* __restrict__ kb,
                                   __nv_bfloat16* __restrict__ qh, __nv_bfloat16* __restrict__ ql,
                                   __nv_bfloat16* __restrict__ kh, __nv_bfloat16* __restrict__ kl) {
    int token = blockIdx.x;
    int head  = blockIdx.y;       // 0..19: 0-15 = q, 16-19 = k
    int d = threadIdx.x;
    int s = token % Sc;
    const float* p;
    __nv_bfloat16 *oh, *ol;
    size_t idx;
    float scale;
    if (head < NHc) {
        p = qb + ((size_t)token * NHc + head) * DHc;
        idx = ((size_t)token * NHc + head) * DHc;
        oh = qh; ol = ql; scale = INV_SQRT_DH;
    } else {
        int h2 = head - NHc;
        p = kb + ((size_t)token * NKVc + h2) * DHc;
        idx = ((size_t)token * NKVc + h2) * DHc;
        oh = kh; ol = kl; scale = 1.0f;
    }
    float freq = powf(1000000.0f, -(float)d / 64.0f);
    float ang = (float)s * freq;
    float sn, cs;
    sincosf(ang, &sn, &cs);
    float x1 = p[d], x2 = p[d + 64];
    float v0 = (x1 * cs - x2 * sn) * scale;
    float v1 = (x2 * cs + x1 * sn) * scale;
    __nv_bfloat16 h0 = __float2bfloat16(v0);
    __nv_bfloat16 h1 = __float2bfloat16(v1);
    oh[idx + d]      = h0;
    ol[idx + d]      = __float2bfloat16(v0 - __bfloat162float(h0));
    oh[idx + d + 64] = h1;
    ol[idx + d + 64] = __float2bfloat16(v1 - __bfloat162float(h1));
}

// ---------------- V transpose + split ----------------
__global__ void vsplitT_kernel(const float* __restrict__ v,
                               __nv_bfloat16* __restrict__ vTh,
                               __nv_bfloat16* __restrict__ vTl) {
    __shared__ float tile[32][33];
    int b = blockIdx.z;
    int t0 = blockIdx.x * 32, d0 = blockIdx.y * 32;
    int tx = threadIdx.x, ty = threadIdx.y;
    for (int i = ty; i < 32; i += 8)
        tile[i][tx] = v[(size_t)(b * Sc + t0 + i) * KNc + d0 + tx];
    __syncthreads();
    for (int i = ty; i < 32; i += 8) {
        float val = tile[tx][i];
        size_t idx = ((size_t)b * KNc + d0 + i) * Sc + t0 + tx;
        __nv_bfloat16 hb = __float2bfloat16(val);
        vTh[idx] = hb;
        vTl[idx] = __float2bfloat16(val - __bfloat162float(hb));
    }
}

// ---------------- masked softmax -> bf16 hi/lo P ----------------
__global__ void softmax_kernel(const float* __restrict__ scores, const int* __restrict__ mask,
                               __nv_bfloat16* __restrict__ ph, __nv_bfloat16* __restrict__ pl) {
    int row = blockIdx.x;
    int qpos = row % Sc;
    int b = row / (NHc * Sc);
    const float* r = scores + (size_t)row * Sc;
    int t = threadIdx.x;
    float v[4];
    float mx = -3.0e38f;
    #pragma unroll
    for (int i = 0; i < 4; i++) {
        int k = t + 128 * i;
        bool ok = (k <= qpos) && (mask[b * Sc + k] > 0);
        v[i] = ok ? r[k] : -1e30f;
        mx = fmaxf(mx, v[i]);
    }
    __shared__ float sh[128];
    sh[t] = mx; __syncthreads();
    for (int o = 64; o; o >>= 1) { if (t < o) sh[t] = fmaxf(sh[t], sh[t + o]); __syncthreads(); }
    mx = sh[0]; __syncthreads();
    float sm = 0.f;
    #pragma unroll
    for (int i = 0; i < 4; i++) { v[i] = expf(v[i] - mx); sm += v[i]; }
    sh[t] = sm; __syncthreads();
    for (int o = 64; o; o >>= 1) { if (t < o) sh[t] += sh[t + o]; __syncthreads(); }
    float inv = 1.0f / sh[0];
    #pragma unroll
    for (int i = 0; i < 4; i++) {
        float p = v[i] * inv;
        __nv_bfloat16 hb = __float2bfloat16(p);
        ph[(size_t)row * Sc + t + 128 * i] = hb;
        pl[(size_t)row * Sc + t + 128 * i] = __float2bfloat16(p - __bfloat162float(hb));
    }
}

// ---------------- silu(g)*u -> bf16 hi/lo ----------------
__global__ void silu_mul_kernel(const float* __restrict__ g, const float* __restrict__ u,
                                __nv_bfloat16* __restrict__ gh, __nv_bfloat16* __restrict__ gl, int n) {
    int i = blockIdx.x * 256 + threadIdx.x;
    if (i < n) {
        float x = g[i];
        float v = (x / (1.0f + expf(-x))) * u[i];
        __nv_bfloat16 hb = __float2bfloat16(v);
        gh[i] = hb;
        gl[i] = __float2bfloat16(v - __bfloat162float(hb));
    }
}

// ---------------- final pooling + rmsnorm(lnf) ----------------
__global__ void pool_kernel(const float* __restrict__ h, const int* __restrict__ mask,
                            const float* __restrict__ lnf, float* __restrict__ pooled) {
    int b = blockIdx.x;
    int t = threadIdx.x;
    __shared__ float sh[256];
    int cnt = 0;
    for (int i = t; i < Sc; i += 256) cnt += mask[b * Sc + i];
    sh[t] = (float)cnt; __syncthreads();
    for (int o = 128; o; o >>= 1) { if (t < o) sh[t] += sh[t + o]; __syncthreads(); }
    int last = (int)sh[0] - 1;
    __syncthreads();
    const float* row = h + ((size_t)b * Sc + last) * Hc;
    float ss = 0.f;
    for (int i = t; i < Hc; i += 256) { float x = row[i]; ss += x * x; }
    sh[t] = ss; __syncthreads();
    for (int o = 128; o; o >>= 1) { if (t < o) sh[t] += sh[t + o]; __syncthreads(); }
    float sc = rsqrtf(sh[0] / (float)Hc + 1e-6f);
    for (int i = t; i < Hc; i += 256) pooled[b * Hc + i] = row[i] * sc * lnf[i];
}

// ---------------- classifier ----------------
__global__ void cls1_kernel(const float* __restrict__ pooled, const float* __restrict__ cw1,
                            const float* __restrict__ cb1, float* __restrict__ hid) {
    int n = blockIdx.x * 128 + threadIdx.x;
    int b = blockIdx.y;
    float acc = cb1[n];
    const float* p = pooled + (size_t)b * Hc;
    for (int k = 0; k < Hc; k++) acc += p[k] * cw1[(size_t)k * Hc + n];
    hid[(size_t)b * Hc + n] = fmaxf(acc, 0.f);
}

__global__ void cls2_kernel(const float* __restrict__ hid, const float* __restrict__ cw2,
                            const float* __restrict__ cb2, float* __restrict__ out) {
    int b = blockIdx.x >> 1, c = blockIdx.x & 1;
    float acc = 0.f;
    for (int k = threadIdx.x; k < Hc; k += 128) acc += hid[(size_t)b * Hc + k] * cw2[k * NCc + c];
    __shared__ float sh[128];
    sh[threadIdx.x] = acc; __syncthreads();
    for (int o = 64; o; o >>= 1) { if (threadIdx.x < o) sh[threadIdx.x] += sh[threadIdx.x + o]; __syncthreads(); }
    if (threadIdx.x == 0) out[b * NCc + c] = sh[0] + cb2[c];
}

// ---------------- host orchestration ----------------
extern "C" void kernel_launch(void* const* d_in, const int* in_sizes, int n_in,
                              void* d_out, int out_size) {
    (void)in_sizes; (void)n_in; (void)out_size;
    const int*   ids   = (const int*)d_in[0];
    const int*   mask  = (const int*)d_in[1];
    const float* embed = (const float*)d_in[2];
    const float* ln1   = (const float*)d_in[3];
    const float* wq    = (const float*)d_in[4];
    const float* bq    = (const float*)d_in[5];
    const float* wk    = (const float*)d_in[6];
    const float* bk    = (const float*)d_in[7];
    const float* wv    = (const float*)d_in[8];
    const float* bv    = (const float*)d_in[9];
    const float* wo    = (const float*)d_in[10];
    const float* laq   = (const float*)d_in[11];
    const float* lbq   = (const float*)d_in[12];
    const float* lak   = (const float*)d_in[13];
    const float* lbk   = (const float*)d_in[14];
    const float* lav   = (const float*)d_in[15];
    const float* lbv   = (const float*)d_in[16];
    const float* lao   = (const float*)d_in[17];
    const float* lbo   = (const float*)d_in[18];
    const float* ln2   = (const float*)d_in[19];
    const float* wg    = (const float*)d_in[20];
    const float* wu    = (const float*)d_in[21];
    const float* wd    = (const float*)d_in[22];
    const float* lnf   = (const float*)d_in[23];
    const float* cw1   = (const float*)d_in[24];
    const float* cb1   = (const float*)d_in[25];
    const float* cw2   = (const float*)d_in[26];
    const float* cb2   = (const float*)d_in[27];
    float* out = (float*)d_out;

    cudaFuncSetAttribute(gemm_bf16x3, cudaFuncAttributeMaxDynamicSharedMemorySize, GEMM_SMEM);
    cudaFuncSetAttribute(attn_scores_mma, cudaFuncAttributeMaxDynamicSharedMemorySize, GEMM_SMEM);
    cudaFuncSetAttribute(attn_ctx_mma, cudaFuncAttributeMaxDynamicSharedMemorySize, GEMM_SMEM);

    float *h, *x, *q, *k, *v, *t1, *t2, *t3, *tp, *sc, *ctx, *g, *u, *pooled, *cls;
    __nv_bfloat16 *xh, *xl, *qh, *ql, *kh, *kl, *vTh, *vTl, *ph, *pl, *ch, *cl, *gh, *gl, *whT, *wlT;
    cudaGetSymbolAddress((void**)&h,   d_h);
    cudaGetSymbolAddress((void**)&x,   d_x);
    cudaGetSymbolAddress((void**)&xh,  d_xh);
    cudaGetSymbolAddress((void**)&xl,  d_xl);
    cudaGetSymbolAddress((void**)&q,   d_q);
    cudaGetSymbolAddress((void**)&k,   d_k);
    cudaGetSymbolAddress((void**)&v,   d_v);
    cudaGetSymbolAddress((void**)&qh,  d_qh);
    cudaGetSymbolAddress((void**)&ql,  d_ql);
    cudaGetSymbolAddress((void**)&kh,  d_kh);
    cudaGetSymbolAddress((void**)&kl,  d_kl);
    cudaGetSymbolAddress((void**)&vTh, d_vTh);
    cudaGetSymbolAddress((void**)&vTl, d_vTl);
    cudaGetSymbolAddress((void**)&t1,  d_t1);
    cudaGetSymbolAddress((void**)&t2,  d_t2);
    cudaGetSymbolAddress((void**)&t3,  d_t3);
    cudaGetSymbolAddress((void**)&tp,  d_tp);
    cudaGetSymbolAddress((void**)&sc,  d_sc);
    cudaGetSymbolAddress((void**)&ph,  d_ph);
    cudaGetSymbolAddress((void**)&pl,  d_pl);
    cudaGetSymbolAddress((void**)&ctx, d_ctx);
    cudaGetSymbolAddress((void**)&ch,  d_ch);
    cudaGetSymbolAddress((void**)&cl,  d_cl);
    cudaGetSymbolAddress((void**)&g,   d_g);
    cudaGetSymbolAddress((void**)&u,   d_u);
    cudaGetSymbolAddress((void**)&gh,  d_gh);
    cudaGetSymbolAddress((void**)&gl,  d_gl);
    cudaGetSymbolAddress((void**)&pooled, d_pooled);
    cudaGetSymbolAddress((void**)&cls,    d_cls);
    cudaGetSymbolAddress((void**)&whT,    d_whT);
    cudaGetSymbolAddress((void**)&wlT,    d_wlT);

    wsplit_all_kernel<<<Lc * TILES_PER_LAYER, dim3(32, 8)>>>(wq, wk, wv, wo, wg, wu, wd, whT, wlT);
    embed_kernel<<<MTc, 256>>>(ids, embed, h);

    for (int l = 0; l < Lc; l++) {
        size_t lw = (size_t)l * LAYER_W;
        const float* LN1 = ln1 + (size_t)l * Hc;
        const float* BQ = bq + (size_t)l * QNc;
        const float* BK = bk + (size_t)l * KNc;
        const float* BV = bv + (size_t)l * KNc;
        const float* LAQ = laq + (size_t)l * Rc * Hc;  const float* LBQ = lbq + (size_t)l * QNc * Rc;
        const float* LAK = lak + (size_t)l * Rc * Hc;  const float* LBK = lbk + (size_t)l * KNc * Rc;
        const float* LAV = lav + (size_t)l * Rc * Hc;  const float* LBV = lbv + (size_t)l * KNc * Rc;
        const float* LAO = lao + (size_t)l * Rc * QNc; const float* LBO = lbo + (size_t)l * Hc * Rc;
        const float* LN2 = ln2 + (size_t)l * Hc;

        rmsnorm_kernel<<<MTc, 256>>>(h, LN1, x, xh, xl);
        lora_down_part<<<dim3(MTc / 64, 3, LKS), 256>>>(x, LAQ, LAK, LAV, tp, Hc);
        lora_reduce<<<dim3((MTc * Rc) / 256, 3), 256>>>(tp, t1, t2, t3);

        gemm_bf16x3<<<dim3(QNc / 128, MTc / 128, 1), 256, GEMM_SMEM>>>(
            xh, xl,
            whT + lw + WOFF_Q, wlT + lw + WOFF_Q, BQ, nullptr, t1, LBQ, q,
            nullptr, nullptr, nullptr, nullptr, nullptr, nullptr, nullptr,
            MTc, QNc, Hc);
        gemm_bf16x3<<<dim3(KNc / 128, MTc / 128, 2), 256, GEMM_SMEM>>>(
            xh, xl,
            whT + lw + WOFF_K, wlT + lw + WOFF_K, BK, nullptr, t2, LBK, k,
            whT + lw + WOFF_V, wlT + lw + WOFF_V, BV, nullptr, t3, LBV, v,
            MTc, KNc, Hc);

        rope_split2_kernel<<<dim3(MTc, NHc + NKVc), 64>>>(q, k, qh, ql, kh, kl);
        vsplitT_kernel<<<dim3(16, 16, Bc), dim3(32, 8)>>>(v, vTh, vTl);

        attn_scores_mma<<<dim3(4, 4, Bc * NHc), 256, GEMM_SMEM>>>(qh, ql, kh, kl, sc);
        softmax_kernel<<<Bc * NHc * Sc, 128>>>(sc, mask, ph, pl);
        attn_ctx_mma<<<dim3(1, 4, Bc * NHc), 256, GEMM_SMEM>>>(ph, pl, vTh, vTl, ctx, ch, cl);

        lora_down_part<<<dim3(MTc / 64, 1, LKS), 256>>>(ctx, LAO, nullptr, nullptr, tp, QNc);
        lora_reduce<<<dim3((MTc * Rc) / 256, 1), 256>>>(tp, t1, t2, t3);
        gemm_bf16x3<<<dim3(Hc / 128, MTc / 128, 1), 256, GEMM_SMEM>>>(
            ch, cl,
            whT + lw + WOFF_O, wlT + lw + WOFF_O, nullptr, h, t1, LBO, h,
            nullptr, nullptr, nullptr, nullptr, nullptr, nullptr, nullptr,
            MTc, Hc, QNc);

        rmsnorm_kernel<<<MTc, 256>>>(h, LN2, x, xh, xl);
        gemm_bf16x3<<<dim3(Fc / 128, MTc / 128, 2), 256, GEMM_SMEM>>>(
            xh, xl,
            whT + lw + WOFF_G, wlT + lw + WOFF_G, nullptr, nullptr, nullptr, nullptr, g,
            whT + lw + WOFF_U, wlT + lw + WOFF_U, nullptr, nullptr, nullptr, nullptr, u,
            MTc, Fc, Hc);
        silu_mul_kernel<<<(MTc * Fc) / 256, 256>>>(g, u, gh, gl, MTc * Fc);
        gemm_bf16x3<<<dim3(Hc / 128, MTc / 128, 1), 256, GEMM_SMEM>>>(
            gh, gl,
            whT + lw + WOFF_D, wlT + lw + WOFF_D, nullptr, h, nullptr, nullptr, h,
            nullptr, nullptr, nullptr, nullptr, nullptr, nullptr, nullptr,
            MTc, Hc, Fc);
    }

    pool_kernel<<<Bc, 256>>>(h, mask, lnf, pooled);
    cls1_kernel<<<dim3(Hc / 128, Bc), 128>>>(pooled, cw1, cb1, cls);
    cls2_kernel<<<Bc * NCc, 128>>>(cls, cw2, cb2, out);
}

// round 11
// speedup vs baseline: 1.1527x; 1.0369x over previous
#include <cuda_runtime.h>
#include <cuda_bf16.h>
#include <cstddef>
#include <cstdint>
#include <math.h>

// ---------------- problem constants ----------------
#define Lc   4
#define Hc   2048
#define NHc  16
#define NKVc 4
#define DHc  128
#define Fc   5632
#define Rc   16
#define Bc   4
#define Sc   512
#define NCc  2
#define MTc  (Bc * Sc)          // 2048 tokens
#define QNc  (NHc * DHc)        // 2048
#define KNc  (NKVc * DHc)       // 512
#define LORA_SCALE 2.0f
#define INV_SQRT_DH 0.08838834764831845f

// per-layer transposed weight buffer offsets (elements)
#define WOFF_Q 0
#define WOFF_K (WOFF_Q + Hc * QNc)
#define WOFF_V (WOFF_K + Hc * KNc)
#define WOFF_O (WOFF_V + Hc * KNc)
#define WOFF_G (WOFF_O + QNc * Hc)
#define WOFF_U (WOFF_G + Hc * Fc)
#define WOFF_D (WOFF_U + Hc * Fc)
#define LAYER_W (WOFF_D + Fc * Hc)   // 45,088,768

// ---------------- scratch (static device memory; allocation-free) ----------------
__device__ float          d_h[MTc * Hc];
__device__ float          d_x[MTc * Hc];
__device__ __nv_bfloat16  d_xh[MTc * Hc];
__device__ __nv_bfloat16  d_xl[MTc * Hc];
__device__ float          d_q[MTc * QNc];
__device__ float          d_k[MTc * KNc];
__device__ float          d_v[MTc * KNc];
__device__ __nv_bfloat16  d_qh[MTc * QNc];
__device__ __nv_bfloat16  d_ql[MTc * QNc];
__device__ __nv_bfloat16  d_kh[MTc * KNc];
__device__ __nv_bfloat16  d_kl[MTc * KNc];
__device__ __nv_bfloat16  d_vTh[Bc * KNc * Sc];
__device__ __nv_bfloat16  d_vTl[Bc * KNc * Sc];
__device__ float          d_ropec[Sc * 64];
__device__ float          d_ropes[Sc * 64];
__device__ float          d_sc[Bc * NHc * Sc * Sc];
__device__ __nv_bfloat16  d_ph[Bc * NHc * Sc * Sc];
__device__ __nv_bfloat16  d_pl[Bc * NHc * Sc * Sc];
__device__ float          d_ctx[MTc * QNc];
__device__ __nv_bfloat16  d_ch[MTc * QNc];
__device__ __nv_bfloat16  d_cl[MTc * QNc];
__device__ float          d_g[MTc * Fc];
__device__ float          d_u[MTc * Fc];
__device__ __nv_bfloat16  d_gh[MTc * Fc];
__device__ __nv_bfloat16  d_gl[MTc * Fc];
__device__ float          d_pooled[Bc * Hc];
__device__ float          d_cls[Bc * Hc];
__device__ __nv_bfloat16  d_whT[(size_t)Lc * LAYER_W];  // hi weights (lora folded), [N,K]
__device__ __nv_bfloat16  d_wlT[(size_t)Lc * LAYER_W];  // lo weights, [N,K]

// ---------------- PTX helpers ----------------
__device__ __forceinline__ uint32_t sptr(const void* p) {
    return (uint32_t)__cvta_generic_to_shared(p);
}
#define CP_ASYNC16(dst, src) asm volatile("cp.async.cg.shared.global [%0], [%1], 16;\n" :: "r"(dst), "l"(src))
#define CP_COMMIT()          asm volatile("cp.async.commit_group;\n" ::: "memory")
#define CP_WAIT(n)           asm volatile("cp.async.wait_group %0;\n" :: "n"(n) : "memory")

__device__ __forceinline__ void mma_bf16(float* c, const uint32_t* a, const uint32_t* b) {
    asm volatile(
        "mma.sync.aligned.m16n8k16.row.col.f32.bf16.bf16.f32 "
        "{%0,%1,%2,%3}, {%4,%5,%6,%7}, {%8,%9}, {%0,%1,%2,%3};\n"
        : "+f"(c[0]), "+f"(c[1]), "+f"(c[2]), "+f"(c[3])
        : "r"(a[0]), "r"(a[1]), "r"(a[2]), "r"(a[3]), "r"(b[0]), "r"(b[1]));
}

__device__ __forceinline__ void ldsm4(uint32_t* r, uint32_t addr) {
    asm volatile("ldmatrix.sync.aligned.m8n8.x4.shared.b16 {%0,%1,%2,%3}, [%4];"
        : "=r"(r[0]), "=r"(r[1]), "=r"(r[2]), "=r"(r[3]) : "r"(addr));
}

// ---------------- ALL weights: transpose + LoRA fold + bf16 split, ONE launch ----------------
// W[K,N] fp32 (+ scale*(B@A)^T for Q/K/V/O) -> hiT/loT [N,K] bf16.
// k-tile 64, n-tile 32. Tiles/layer: Q 2048, K 512, V 512, O 2048, G 5632, U 5632, D 5632.
#define TILES_PER_LAYER 22016
__global__ void wsplit_all_kernel(const float* __restrict__ wq, const float* __restrict__ wk,
                                  const float* __restrict__ wv, const float* __restrict__ wo,
                                  const float* __restrict__ wg, const float* __restrict__ wu,
                                  const float* __restrict__ wd,
                                  const float* __restrict__ laq, const float* __restrict__ lbq,
                                  const float* __restrict__ lak, const float* __restrict__ lbk,
                                  const float* __restrict__ lav, const float* __restrict__ lbv,
                                  const float* __restrict__ lao, const float* __restrict__ lbo,
                                  __nv_bfloat16* __restrict__ hiT,
                                  __nv_bfloat16* __restrict__ loT) {
    int l = blockIdx.x / TILES_PER_LAYER;
    int r = blockIdx.x % TILES_PER_LAYER;
    const float* src; size_t woff; int K, N, tidx;
    const float* loA = nullptr; const float* loB = nullptr;
    if (r < 2048)       { src = wq + (size_t)l * Hc * QNc; woff = WOFF_Q; K = Hc;  N = QNc; tidx = r;
                          loA = laq + (size_t)l * Rc * Hc;  loB = lbq + (size_t)l * QNc * Rc; }
    else if (r < 2560)  { src = wk + (size_t)l * Hc * KNc; woff = WOFF_K; K = Hc;  N = KNc; tidx = r - 2048;
                          loA = lak + (size_t)l * Rc * Hc;  loB = lbk + (size_t)l * KNc * Rc; }
    else if (r < 3072)  { src = wv + (size_t)l * Hc * KNc; woff = WOFF_V; K = Hc;  N = KNc; tidx = r - 2560;
                          loA = lav + (size_t)l * Rc * Hc;  loB = lbv + (size_t)l * KNc * Rc; }
    else if (r < 5120)  { src = wo + (size_t)l * QNc * Hc; woff = WOFF_O; K = QNc; N = Hc;  tidx = r - 3072;
                          loA = lao + (size_t)l * Rc * QNc; loB = lbo + (size_t)l * Hc * Rc; }
    else if (r < 10752) { src = wg + (size_t)l * Hc * Fc;  woff = WOFF_G; K = Hc;  N = Fc;  tidx = r - 5120; }
    else if (r < 16384) { src = wu + (size_t)l * Hc * Fc;  woff = WOFF_U; K = Hc;  N = Fc;  tidx = r - 10752; }
    else                { src = wd + (size_t)l * Fc * Hc;  woff = WOFF_D; K = Fc;  N = Hc;  tidx = r - 16384; }
    woff += (size_t)l * LAYER_W;
    int nt = N / 32;
    int k0 = (tidx / nt) * 64, n0 = (tidx % nt) * 32;

    __shared__ float tile[64][33];   // [k][n]
    __shared__ float sA[16][64];     // lora A[r][k-local]
    __shared__ float sB[32][17];     // lora B[n-local][r]
    int tx = threadIdx.x, ty = threadIdx.y;   // (32, 8)
    int tid = ty * 32 + tx;
    for (int i = ty; i < 64; i += 8)
        tile[i][tx] = src[(size_t)(k0 + i) * N + n0 + tx];
    if (loA) {
        for (int idx = tid; idx < 1024; idx += 256) {
            int rr = idx >> 6, kk = idx & 63;
            sA[rr][kk] = loA[(size_t)rr * K + k0 + kk];
        }
        for (int idx = tid; idx < 512; idx += 256) {
            int nn = idx >> 4, rr = idx & 15;
            sB[nn][rr] = loB[(size_t)(n0 + nn) * Rc + rr];
        }
    }
    __syncthreads();
    for (int i = ty; i < 32; i += 8) {
        float v0 = tile[2 * tx][i], v1 = tile[2 * tx + 1][i];
        if (loA) {
            float d0 = 0.f, d1 = 0.f;
            #pragma unroll
            for (int rr = 0; rr < Rc; rr++) {
                float bb = sB[i][rr];
                d0 += sA[rr][2 * tx] * bb;
                d1 += sA[rr][2 * tx + 1] * bb;
            }
            v0 += LORA_SCALE * d0;
            v1 += LORA_SCALE * d1;
        }
        __nv_bfloat16 h0 = __float2bfloat16(v0), h1 = __float2bfloat16(v1);
        __nv_bfloat162 hv; hv.x = h0; hv.y = h1;
        __nv_bfloat162 lv;
        lv.x = __float2bfloat16(v0 - __bfloat162float(h0));
        lv.y = __float2bfloat16(v1 - __bfloat162float(h1));
        size_t idx = woff + (size_t)(n0 + i) * K + k0 + 2 * tx;
        *(__nv_bfloat162*)(hiT + idx) = hv;
        *(__nv_bfloat162*)(loT + idx) = lv;
    }
}

// ---------------- RoPE table precompute ----------------
__global__ void rope_table_kernel(float* __restrict__ rc, float* __restrict__ rs) {
    int s = blockIdx.x;
    int d = threadIdx.x;
    float freq = powf(1000000.0f, -(float)d / 64.0f);
    float ang = (float)s * freq;
    float sn, cs;
    sincosf(ang, &sn, &cs);
    rc[s * 64 + d] = cs;
    rs[s * 64 + d] = sn;
}

// ---------------- embedding gather ----------------
__global__ void embed_kernel(const int* __restrict__ ids,
                             const float* __restrict__ emb,
                             float* __restrict__ h) {
    int row = blockIdx.x;
    const float* src = emb + (size_t)ids[row] * Hc;
    float* dst = h + (size_t)row * Hc;
    for (int i = threadIdx.x; i < Hc; i += 256) dst[i] = src[i];
}

// ---------------- rmsnorm: fp32 out + bf16 hi/lo split ----------------
__global__ void rmsnorm_kernel(const float* __restrict__ in,
                               const float* __restrict__ w,
                               float* __restrict__ out,
                               __nv_bfloat16* __restrict__ oh,
                               __nv_bfloat16* __restrict__ ol) {
    int row = blockIdx.x;
    const float* x = in + (size_t)row * Hc;
    float ss = 0.f;
    for (int i = threadIdx.x; i < Hc; i += 256) { float v = x[i]; ss += v * v; }
    __shared__ float sh[256];
    sh[threadIdx.x] = ss; __syncthreads();
    for (int o = 128; o; o >>= 1) { if (threadIdx.x < o) sh[threadIdx.x] += sh[threadIdx.x + o]; __syncthreads(); }
    float sc = rsqrtf(sh[0] / (float)Hc + 1e-6f);
    for (int i = threadIdx.x; i < Hc; i += 256) {
        float v = x[i] * sc * w[i];
        out[(size_t)row * Hc + i] = v;
        __nv_bfloat16 hb = __float2bfloat16(v);
        oh[(size_t)row * Hc + i] = hb;
        ol[(size_t)row * Hc + i] = __float2bfloat16(v - __bfloat162float(hb));
    }
}

// ---------------- bf16x3 mma.sync GEMM (projections, lora pre-folded) ----------------
#define TILE_B 8192                  // 128 * 64B
#define STAGE_B (4 * TILE_B)         // Ah, Al, Bh, Bl = 32KB
#define NSTAGE 3
#define GEMM_SMEM (NSTAGE * STAGE_B) // 96KB

__global__ __launch_bounds__(256, 2) void gemm_bf16x3(
    const __nv_bfloat16* __restrict__ Ahi, const __nv_bfloat16* __restrict__ Alo,
    const __nv_bfloat16* __restrict__ Bhi1, const __nv_bfloat16* __restrict__ Blo1,
    const float* __restrict__ bias1, const float* __restrict__ resid1,
    float* __restrict__ C1,
    const __nv_bfloat16* __restrict__ Bhi2, const __nv_bfloat16* __restrict__ Blo2,
    const float* __restrict__ bias2, const float* __restrict__ resid2,
    float* __restrict__ C2,
    int M, int N, int K) {
    extern __shared__ uint8_t smraw[];
    const int tid = threadIdx.x;
    const int bm = blockIdx.y * 128, bn = blockIdx.x * 128;

    const __nv_bfloat16* Bhi = Bhi1; const __nv_bfloat16* Blo = Blo1;
    const float* bias = bias1; const float* resid = resid1;
    float* C = C1;
    if (blockIdx.z == 1) {
        Bhi = Bhi2; Blo = Blo2; bias = bias2; resid = resid2; C = C2;
    }

    const int warpId = tid >> 5, lane = tid & 31;
    const int warpM = warpId & 3, warpN = warpId >> 2;
    const int m0 = warpM * 32, n0 = warpN * 64;
    const int grp = lane >> 2, qd = lane & 3;

    const int lrow16 = lane & 15;
    const int lch    = lane >> 4;
    const int lsw    = (lrow16 >> 1) & 3;
    const uint32_t sb = sptr(smraw);

    const int lrow = tid >> 1, lg0 = (tid & 1) * 2;
    const int lswz = (lrow >> 1) & 3;
    const __nv_bfloat16* pAh = Ahi + (size_t)(bm + lrow) * K;
    const __nv_bfloat16* pAl = Alo + (size_t)(bm + lrow) * K;
    const __nv_bfloat16* pBh = Bhi + (size_t)(bn + lrow) * K;
    const __nv_bfloat16* pBl = Blo + (size_t)(bn + lrow) * K;
    const uint32_t srow = sb + lrow * 64;

    float acc[2][8][4];
    #pragma unroll
    for (int mt = 0; mt < 2; mt++)
        #pragma unroll
        for (int nt = 0; nt < 8; nt++)
            #pragma unroll
            for (int r = 0; r < 4; r++) acc[mt][nt][r] = 0.f;

    auto loadStage = [&](int st, int k0) {
        uint32_t d = srow + st * STAGE_B;
        #pragma unroll
        for (int i = 0; i < 2; i++) {
            int g = lg0 + i;
            uint32_t off = (uint32_t)(g ^ lswz) << 4;
            CP_ASYNC16(d + 0 * TILE_B + off, pAh + k0 + g * 8);
            CP_ASYNC16(d + 1 * TILE_B + off, pAl + k0 + g * 8);
            CP_ASYNC16(d + 2 * TILE_B + off, pBh + k0 + g * 8);
            CP_ASYNC16(d + 3 * TILE_B + off, pBl + k0 + g * 8);
        }
        CP_COMMIT();
    };

    const int KT = K >> 5;
    loadStage(0, 0);
    if (KT > 1) loadStage(1, 32);

    for (int kt = 0; kt < KT; kt++) {
        const int st = kt % NSTAGE;
        if (kt + 1 < KT) { CP_WAIT(1); } else { CP_WAIT(0); }
        __syncthreads();
        if (kt + 2 < KT) loadStage((kt + 2) % NSTAGE, (kt + 2) << 5);

        const uint32_t tAh = sb + st * STAGE_B;
        const uint32_t tAl = tAh + TILE_B;
        const uint32_t tBh = tAh + 2 * TILE_B;
        const uint32_t tBl = tAh + 3 * TILE_B;

        #pragma unroll
        for (int ks = 0; ks < 2; ks++) {
            const uint32_t choff = (uint32_t)(((ks * 2 + lch) ^ lsw)) << 4;
            uint32_t ra0 = (uint32_t)(m0 + lrow16) * 64 + choff;
            uint32_t ra1 = (uint32_t)(m0 + 16 + lrow16) * 64 + choff;
            uint32_t rb0 = (uint32_t)(n0 + lrow16) * 64 + choff;

            uint32_t afH[2][4], afL[2][4], bf[8][2];

            #pragma unroll
            for (int np = 0; np < 4; np++) {
                uint32_t q[4];
                ldsm4(q, tBh + rb0 + (uint32_t)(np * 16 * 64));
                bf[2 * np][0] = q[0]; bf[2 * np + 1][0] = q[1];
                bf[2 * np][1] = q[2]; bf[2 * np + 1][1] = q[3];
            }
            ldsm4(afH[0], tAh + ra0);
            ldsm4(afH[1], tAh + ra1);
            #pragma unroll
            for (int mt = 0; mt < 2; mt++)
                #pragma unroll
                for (int nt = 0; nt < 8; nt++)
                    mma_bf16(acc[mt][nt], afH[mt], bf[nt]);
            ldsm4(afL[0], tAl + ra0);
            ldsm4(afL[1], tAl + ra1);
            #pragma unroll
            for (int mt = 0; mt < 2; mt++)
                #pragma unroll
                for (int nt = 0; nt < 8; nt++)
                    mma_bf16(acc[mt][nt], afL[mt], bf[nt]);
            #pragma unroll
            for (int np = 0; np < 4; np++) {
                uint32_t q[4];
                ldsm4(q, tBl + rb0 + (uint32_t)(np * 16 * 64));
                bf[2 * np][0] = q[0]; bf[2 * np + 1][0] = q[1];
                bf[2 * np][1] = q[2]; bf[2 * np + 1][1] = q[3];
            }
            #pragma unroll
            for (int mt = 0; mt < 2; mt++)
                #pragma unroll
                for (int nt = 0; nt < 8; nt++)
                    mma_bf16(acc[mt][nt], afH[mt], bf[nt]);
        }
    }

    #pragma unroll
    for (int mt = 0; mt < 2; mt++) {
        int lr0 = m0 + mt * 16 + grp;
        int lr1 = lr0 + 8;
        int row0 = bm + lr0, row1 = bm + lr1;
        #pragma unroll
        for (int nt = 0; nt < 8; nt++) {
            int lc0 = n0 + nt * 8 + 2 * qd;
            int col0 = bn + lc0, col1 = col0 + 1;
            float o00 = acc[mt][nt][0], o01 = acc[mt][nt][1];
            float o10 = acc[mt][nt][2], o11 = acc[mt][nt][3];
            if (bias) {
                float b0 = bias[col0], b1 = bias[col1];
                o00 += b0; o01 += b1; o10 += b0; o11 += b1;
            }
            if (resid) {
                o00 += resid[(size_t)row0 * N + col0];
                o01 += resid[(size_t)row0 * N + col1];
                o10 += resid[(size_t)row1 * N + col0];
                o11 += resid[(size_t)row1 * N + col1];
            }
            *(float2*)(C + (size_t)row0 * N + col0) = make_float2(o00, o01);
            *(float2*)(C + (size_t)row1 * N + col0) = make_float2(o10, o11);
        }
    }
}

// ---------------- attention scores on tensor cores: S = Qs * K^T (bf16x3) ----------------
__global__ __launch_bounds__(256, 2) void attn_scores_mma(
    const __nv_bfloat16* __restrict__ qh, const __nv_bfloat16* __restrict__ ql,
    const __nv_bfloat16* __restrict__ kh, const __nv_bfloat16* __restrict__ kl,
    float* __restrict__ scores) {
    if (blockIdx.x > blockIdx.y) return;
    extern __shared__ uint8_t smraw[];
    const int tid = threadIdx.x;
    const int bh = blockIdx.z;
    const int b = bh >> 4, hd = bh & 15, kvh = hd >> 2;
    const int bm = blockIdx.y * 128, bn = blockIdx.x * 128;
    const __nv_bfloat16* Ah = qh + (size_t)b * Sc * QNc + (size_t)hd * DHc;
    const __nv_bfloat16* Al = ql + (size_t)b * Sc * QNc + (size_t)hd * DHc;
    const __nv_bfloat16* Bh = kh + (size_t)b * Sc * KNc + (size_t)kvh * DHc;
    const __nv_bfloat16* Bl = kl + (size_t)b * Sc * KNc + (size_t)kvh * DHc;
    float* C = scores + (size_t)bh * Sc * Sc;

    const int warpId = tid >> 5, lane = tid & 31;
    const int warpM = warpId & 3, warpN = warpId >> 2;
    const int m0 = warpM * 32, n0 = warpN * 64;
    const int grp = lane >> 2, qd = lane & 3;
    const int lrow16 = lane & 15, lch = lane >> 4, lsw = (lrow16 >> 1) & 3;
    const uint32_t sb = sptr(smraw);

    const int lrow = tid >> 1, lg0 = (tid & 1) * 2;
    const int lswz = (lrow >> 1) & 3;
    const __nv_bfloat16* pAh = Ah + (size_t)(bm + lrow) * QNc;
    const __nv_bfloat16* pAl = Al + (size_t)(bm + lrow) * QNc;
    const __nv_bfloat16* pBh = Bh + (size_t)(bn + lrow) * KNc;
    const __nv_bfloat16* pBl = Bl + (size_t)(bn + lrow) * KNc;
    const uint32_t srow = sb + lrow * 64;

    float acc[2][8][4];
    #pragma unroll
    for (int mt = 0; mt < 2; mt++)
        #pragma unroll
        for (int nt = 0; nt < 8; nt++)
            #pragma unroll
            for (int r = 0; r < 4; r++) acc[mt][nt][r] = 0.f;

    auto loadStage = [&](int st, int k0) {
        uint32_t d = srow + st * STAGE_B;
        #pragma unroll
        for (int i = 0; i < 2; i++) {
            int g = lg0 + i;
            uint32_t off = (uint32_t)(g ^ lswz) << 4;
            CP_ASYNC16(d + 0 * TILE_B + off, pAh + k0 + g * 8);
            CP_ASYNC16(d + 1 * TILE_B + off, pAl + k0 + g * 8);
            CP_ASYNC16(d + 2 * TILE_B + off, pBh + k0 + g * 8);
            CP_ASYNC16(d + 3 * TILE_B + off, pBl + k0 + g * 8);
        }
        CP_COMMIT();
    };

    const int KT = DHc >> 5;
    loadStage(0, 0);
    loadStage(1, 32);

    for (int kt = 0; kt < KT; kt++) {
        const int st = kt % NSTAGE;
        if (kt + 1 < KT) { CP_WAIT(1); } else { CP_WAIT(0); }
        __syncthreads();
        if (kt + 2 < KT) loadStage((kt + 2) % NSTAGE, (kt + 2) << 5);

        const uint32_t tAh = sb + st * STAGE_B;
        const uint32_t tAl = tAh + TILE_B;
        const uint32_t tBh = tAh + 2 * TILE_B;
        const uint32_t tBl = tAh + 3 * TILE_B;

        #pragma unroll
        for (int ks = 0; ks < 2; ks++) {
            const uint32_t choff = (uint32_t)(((ks * 2 + lch) ^ lsw)) << 4;
            uint32_t ra0 = (uint32_t)(m0 + lrow16) * 64 + choff;
            uint32_t ra1 = (uint32_t)(m0 + 16 + lrow16) * 64 + choff;
            uint32_t rb0 = (uint32_t)(n0 + lrow16) * 64 + choff;
            uint32_t afH[2][4], afL[2][4], bf[8][2];
            #pragma unroll
            for (int np = 0; np < 4; np++) {
                uint32_t q[4];
                ldsm4(q, tBh + rb0 + (uint32_t)(np * 16 * 64));
                bf[2 * np][0] = q[0]; bf[2 * np + 1][0] = q[1];
                bf[2 * np][1] = q[2]; bf[2 * np + 1][1] = q[3];
            }
            ldsm4(afH[0], tAh + ra0);
            ldsm4(afH[1], tAh + ra1);
            #pragma unroll
            for (int mt = 0; mt < 2; mt++)
                #pragma unroll
                for (int nt = 0; nt < 8; nt++)
                    mma_bf16(acc[mt][nt], afH[mt], bf[nt]);
            ldsm4(afL[0], tAl + ra0);
            ldsm4(afL[1], tAl + ra1);
            #pragma unroll
            for (int mt = 0; mt < 2; mt++)
                #pragma unroll
                for (int nt = 0; nt < 8; nt++)
                    mma_bf16(acc[mt][nt], afL[mt], bf[nt]);
            #pragma unroll
            for (int np = 0; np < 4; np++) {
                uint32_t q[4];
                ldsm4(q, tBl + rb0 + (uint32_t)(np * 16 * 64));
                bf[2 * np][0] = q[0]; bf[2 * np + 1][0] = q[1];
                bf[2 * np][1] = q[2]; bf[2 * np + 1][1] = q[3];
            }
            #pragma unroll
            for (int mt = 0; mt < 2; mt++)
                #pragma unroll
                for (int nt = 0; nt < 8; nt++)
                    mma_bf16(acc[mt][nt], afH[mt], bf[nt]);
        }
    }

    #pragma unroll
    for (int mt = 0; mt < 2; mt++) {
        int row0 = bm + m0 + mt * 16 + grp;
        int row1 = row0 + 8;
        #pragma unroll
        for (int nt = 0; nt < 8; nt++) {
            int col = bn + n0 + nt * 8 + 2 * qd;
            *(float2*)(C + (size_t)row0 * Sc + col) = make_float2(acc[mt][nt][0], acc[mt][nt][1]);
            *(float2*)(C + (size_t)row1 * Sc + col) = make_float2(acc[mt][nt][2], acc[mt][nt][3]);
        }
    }
}

// ---------------- attention context on tensor cores: ctx = P * V (bf16x3) ----------------
__global__ __launch_bounds__(256, 2) void attn_ctx_mma(
    const __nv_bfloat16* __restrict__ ph, const __nv_bfloat16* __restrict__ pl,
    const __nv_bfloat16* __restrict__ vTh, const __nv_bfloat16* __restrict__ vTl,
    float* __restrict__ ctx,
    __nv_bfloat16* __restrict__ ch, __nv_bfloat16* __restrict__ cl) {
    extern __shared__ uint8_t smraw[];
    const int tid = threadIdx.x;
    const int bh = blockIdx.z;
    const int b = bh >> 4, hd = bh & 15, kvh = hd >> 2;
    const int bm = blockIdx.y * 128;
    const __nv_bfloat16* Ah = ph + (size_t)bh * Sc * Sc;
    const __nv_bfloat16* Al = pl + (size_t)bh * Sc * Sc;
    const __nv_bfloat16* Bh = vTh + ((size_t)b * KNc + (size_t)kvh * DHc) * Sc;
    const __nv_bfloat16* Bl = vTl + ((size_t)b * KNc + (size_t)kvh * DHc) * Sc;

    const int warpId = tid >> 5, lane = tid & 31;
    const int warpM = warpId & 3, warpN = warpId >> 2;
    const int m0 = warpM * 32, n0 = warpN * 64;
    const int grp = lane >> 2, qd = lane & 3;
    const int lrow16 = lane & 15, lch = lane >> 4, lsw = (lrow16 >> 1) & 3;
    const uint32_t sb = sptr(smraw);

    const int lrow = tid >> 1, lg0 = (tid & 1) * 2;
    const int lswz = (lrow >> 1) & 3;
    const __nv_bfloat16* pAh = Ah + (size_t)(bm + lrow) * Sc;
    const __nv_bfloat16* pAl = Al + (size_t)(bm + lrow) * Sc;
    const __nv_bfloat16* pBh = Bh + (size_t)lrow * Sc;
    const __nv_bfloat16* pBl = Bl + (size_t)lrow * Sc;
    const uint32_t srow = sb + lrow * 64;

    float acc[2][8][4];
    #pragma unroll
    for (int mt = 0; mt < 2; mt++)
        #pragma unroll
        for (int nt = 0; nt < 8; nt++)
            #pragma unroll
            for (int r = 0; r < 4; r++) acc[mt][nt][r] = 0.f;

    auto loadStage = [&](int st, int k0) {
        uint32_t d = srow + st * STAGE_B;
        #pragma unroll
        for (int i = 0; i < 2; i++) {
            int g = lg0 + i;
            uint32_t off = (uint32_t)(g ^ lswz) << 4;
            CP_ASYNC16(d + 0 * TILE_B + off, pAh + k0 + g * 8);
            CP_ASYNC16(d + 1 * TILE_B + off, pAl + k0 + g * 8);
            CP_ASYNC16(d + 2 * TILE_B + off, pBh + k0 + g * 8);
            CP_ASYNC16(d + 3 * TILE_B + off, pBl + k0 + g * 8);
        }
        CP_COMMIT();
    };

    const int KT = (bm >> 5) + 4;
    loadStage(0, 0);
    loadStage(1, 32);

    for (int kt = 0; kt < KT; kt++) {
        const int st = kt % NSTAGE;
        if (kt + 1 < KT) { CP_WAIT(1); } else { CP_WAIT(0); }
        __syncthreads();
        if (kt + 2 < KT) loadStage((kt + 2) % NSTAGE, (kt + 2) << 5);

        const uint32_t tAh = sb + st * STAGE_B;
        const uint32_t tAl = tAh + TILE_B;
        const uint32_t tBh = tAh + 2 * TILE_B;
        const uint32_t tBl = tAh + 3 * TILE_B;

        #pragma unroll
        for (int ks = 0; ks < 2; ks++) {
            const uint32_t choff = (uint32_t)(((ks * 2 + lch) ^ lsw)) << 4;
            uint32_t ra0 = (uint32_t)(m0 + lrow16) * 64 + choff;
            uint32_t ra1 = (uint32_t)(m0 + 16 + lrow16) * 64 + choff;
            uint32_t rb0 = (uint32_t)(n0 + lrow16) * 64 + choff;
            uint32_t afH[2][4], afL[2][4], bf[8][2];
            #pragma unroll
            for (int np = 0; np < 4; np++) {
                uint32_t q[4];
                ldsm4(q, tBh + rb0 + (uint32_t)(np * 16 * 64));
                bf[2 * np][0] = q[0]; bf[2 * np + 1][0] = q[1];
                bf[2 * np][1] = q[2]; bf[2 * np + 1][1] = q[3];
            }
            ldsm4(afH[0], tAh + ra0);
            ldsm4(afH[1], tAh + ra1);
            #pragma unroll
            for (int mt = 0; mt < 2; mt++)
                #pragma unroll
                for (int nt = 0; nt < 8; nt++)
                    mma_bf16(acc[mt][nt], afH[mt], bf[nt]);
            ldsm4(afL[0], tAl + ra0);
            ldsm4(afL[1], tAl + ra1);
            #pragma unroll
            for (int mt = 0; mt < 2; mt++)
                #pragma unroll
                for (int nt = 0; nt < 8; nt++)
                    mma_bf16(acc[mt][nt], afL[mt], bf[nt]);
            #pragma unroll
            for (int np = 0; np < 4; np++) {
                uint32_t q[4];
                ldsm4(q, tBl + rb0 + (uint32_t)(np * 16 * 64));
                bf[2 * np][0] = q[0]; bf[2 * np + 1][0] = q[1];
                bf[2 * np][1] = q[2]; bf[2 * np + 1][1] = q[3];
            }
            #pragma unroll
            for (int mt = 0; mt < 2; mt++)
                #pragma unroll
                for (int nt = 0; nt < 8; nt++)
                    mma_bf16(acc[mt][nt], afH[mt], bf[nt]);
        }
    }

    #pragma unroll
    for (int mt = 0; mt < 2; mt++) {
        int lr0 = m0 + mt * 16 + grp;
        #pragma unroll
        for (int half = 0; half < 2; half++) {
            int row = bm + lr0 + half * 8;
            size_t base = ((size_t)(b * Sc + row)) * QNc + (size_t)hd * DHc;
            #pragma unroll
            for (int nt = 0; nt < 8; nt++) {
                int col = n0 + nt * 8 + 2 * qd;
                float v0 = acc[mt][nt][half * 2 + 0];
                float v1 = acc[mt][nt][half * 2 + 1];
                *(float2*)(ctx + base + col) = make_float2(v0, v1);
                __nv_bfloat16 h0 = __float2bfloat16(v0);
                __nv_bfloat16 h1 = __float2bfloat16(v1);
                __nv_bfloat162 hv; hv.x = h0; hv.y = h1;
                __nv_bfloat162 lv;
                lv.x = __float2bfloat16(v0 - __bfloat162float(h0));
                lv.y = __float2bfloat16(v1 - __bfloat162float(h1));
                *(__nv_bfloat162*)(ch + base + col) = hv;
                *(__nv_bfloat162*)(cl + base + col) = lv;
            }
        }
    }
}

// ---------------- RoPE (q+k fused), table-driven, + scale + bf16 hi/lo split ----------------
__global__ void rope_split2_kernel(const float* __restrict__ qb, const float* __restrict__ kb,
                                   const float* __restrict__ rc, const float* __restrict__ rs,
                                   __nv_bfloat16* __restrict__ qh, __nv_bfloat16* __restrict__ ql,
                                   __nv_bfloat16* __restrict__ kh, __nv_bfloat16* __restrict__ kl) {
    int token = blockIdx.x;
    int head  = blockIdx.y;       // 0..19: 0-15 = q, 16-19 = k
    int d = threadIdx.x;
    int s = token % Sc;
    const float* p;
    __nv_bfloat16 *oh, *ol;
    size_t idx;
    float scale;
    if (head < NHc) {
        p = qb + ((size_t)token * NHc + head) * DHc;
        idx = ((size_t)token * NHc + head) * DHc;
        oh = qh; ol = ql; scale = INV_SQRT_DH;
    } else {
        int h2 = head - NHc;
        p = kb + ((size_t)token * NKVc + h2) * DHc;
        idx = ((size_t)token * NKVc + h2) * DHc;
        oh = kh; ol = kl; scale = 1.0f;
    }
    float cs = rc[s * 64 + d];
    float sn = rs[s * 64 + d];
    float x1 = p[d], x2 = p[d + 64];
    float v0 = (x1 * cs - x2 * sn) * scale;
    float v1 = (x2 * cs + x1 * sn) * scale;
    __nv_bfloat16 h0 = __float2bfloat16(v0);
    __nv_bfloat16 h1 = __float2bfloat16(v1);
    oh[idx + d]      = h0;
    ol[idx + d]      = __float2bfloat16(v0 - __bfloat162float(h0));
    oh[idx + d + 64] = h1;
    ol[idx + d + 64] = __float2bfloat16(v1 - __bfloat162float(h1));
}

// ---------------- V transpose + split ----------------
__global__ void vsplitT_kernel(const float* __restrict__ v,
                               __nv_bfloat16* __restrict__ vTh,
                               __nv_bfloat16* __restrict__ vTl) {
    __shared__ float tile[32][33];
    int b = blockIdx.z;
    int t0 = blockIdx.x * 32, d0 = blockIdx.y * 32;
    int tx = threadIdx.x, ty = threadIdx.y;
    for (int i = ty; i < 32; i += 8)
        tile[i][tx] = v[(size_t)(b * Sc + t0 + i) * KNc + d0 + tx];
    __syncthreads();
    for (int i = ty; i < 32; i += 8) {
        float val = tile[tx][i];
        size_t idx = ((size_t)b * KNc + d0 + i) * Sc + t0 + tx;
        __nv_bfloat16 hb = __float2bfloat16(val);
        vTh[idx] = hb;
        vTl[idx] = __float2bfloat16(val - __bfloat162float(hb));
    }
}

// ---------------- masked softmax -> bf16 hi/lo P ----------------
__global__ void softmax_kernel(const float* __restrict__ scores, const int* __restrict__ mask,
                               __nv_bfloat16* __restrict__ ph, __nv_bfloat16* __restrict__ pl) {
    int row = blockIdx.x;
    int qpos = row % Sc;
    int b = row / (NHc * Sc);
    const float* r = scores + (size_t)row * Sc;
    int t = threadIdx.x;
    float v[4];
    float mx = -3.0e38f;
    #pragma unroll
    for (int i = 0; i < 4; i++) {
        int k = t + 128 * i;
        bool ok = (k <= qpos) && (mask[b * Sc + k] > 0);
        v[i] = ok ? r[k] : -1e30f;
        mx = fmaxf(mx, v[i]);
    }
    __shared__ float sh[128];
    sh[t] = mx; __syncthreads();
    for (int o = 64; o; o >>= 1) { if (t < o) sh[t] = fmaxf(sh[t], sh[t + o]); __syncthreads(); }
    mx = sh[0]; __syncthreads();
    float sm = 0.f;
    #pragma unroll
    for (int i = 0; i < 4; i++) { v[i] = expf(v[i] - mx); sm += v[i]; }
    sh[t] = sm; __syncthreads();
    for (int o = 64; o; o >>= 1) { if (t < o) sh[t] += sh[t + o]; __syncthreads(); }
    float inv = 1.0f / sh[0];
    #pragma unroll
    for (int i = 0; i < 4; i++) {
        float p = v[i] * inv;
        __nv_bfloat16 hb = __float2bfloat16(p);
        ph[(size_t)row * Sc + t + 128 * i] = hb;
        pl[(size_t)row * Sc + t + 128 * i] = __float2bfloat16(p - __bfloat162float(hb));
    }
}

// ---------------- silu(g)*u -> bf16 hi/lo ----------------
__global__ void silu_mul_kernel(const float* __restrict__ g, const float* __restrict__ u,
                                __nv_bfloat16* __restrict__ gh, __nv_bfloat16* __restrict__ gl, int n) {
    int i = blockIdx.x * 256 + threadIdx.x;
    if (i < n) {
        float x = g[i];
        float v = (x / (1.0f + expf(-x))) * u[i];
        __nv_bfloat16 hb = __float2bfloat16(v);
        gh[i] = hb;
        gl[i] = __float2bfloat16(v - __bfloat162float(hb));
    }
}

// ---------------- final pooling + rmsnorm(lnf) ----------------
__global__ void pool_kernel(const float* __restrict__ h, const int* __restrict__ mask,
                            const float* __restrict__ lnf, float* __restrict__ pooled) {
    int b = blockIdx.x;
    int t = threadIdx.x;
    __shared__ float sh[256];
    int cnt = 0;
    for (int i = t; i < Sc; i += 256) cnt += mask[b * Sc + i];
    sh[t] = (float)cnt; __syncthreads();
    for (int o = 128; o; o >>= 1) { if (t < o) sh[t] += sh[t + o]; __syncthreads(); }
    int last = (int)sh[0] - 1;
    __syncthreads();
    const float* row = h + ((size_t)b * Sc + last) * Hc;
    float ss = 0.f;
    for (int i = t; i < Hc; i += 256) { float x = row[i]; ss += x * x; }
    sh[t] = ss; __syncthreads();
    for (int o = 128; o; o >>= 1) { if (t < o) sh[t] += sh[t + o]; __syncthreads(); }
    float sc = rsqrtf(sh[0] / (float)Hc + 1e-6f);
    for (int i = t; i < Hc; i += 256) pooled[b * Hc + i] = row[i] * sc * lnf[i];
}

// ---------------- classifier ----------------
__global__ void cls1_kernel(const float* __restrict__ pooled, const float* __restrict__ cw1,
                            const float* __restrict__ cb1, float* __restrict__ hid) {
    int n = blockIdx.x * 128 + threadIdx.x;
    int b = blockIdx.y;
    float acc = cb1[n];
    const float* p = pooled + (size_t)b * Hc;
    for (int k = 0; k < Hc; k++) acc += p[k] * cw1[(size_t)k * Hc + n];
    hid[(size_t)b * Hc + n] = fmaxf(acc, 0.f);
}

__global__ void cls2_kernel(const float* __restrict__ hid, const float* __restrict__ cw2,
                            const float* __restrict__ cb2, float* __restrict__ out) {
    int b = blockIdx.x >> 1, c = blockIdx.x & 1;
    float acc = 0.f;
    for (int k = threadIdx.x; k < Hc; k += 128) acc += hid[(size_t)b * Hc + k] * cw2[k * NCc + c];
    __shared__ float sh[128];
    sh[threadIdx.x] = acc; __syncthreads();
    for (int o = 64; o; o >>= 1) { if (threadIdx.x < o) sh[threadIdx.x] += sh[threadIdx.x + o]; __syncthreads(); }
    if (threadIdx.x == 0) out[b * NCc + c] = sh[0] + cb2[c];
}

// ---------------- host orchestration ----------------
extern "C" void kernel_launch(void* const* d_in, const int* in_sizes, int n_in,
                              void* d_out, int out_size) {
    (void)in_sizes; (void)n_in; (void)out_size;
    const int*   ids   = (const int*)d_in[0];
    const int*   mask  = (const int*)d_in[1];
    const float* embed = (const float*)d_in[2];
    const float* ln1   = (const float*)d_in[3];
    const float* wq    = (const float*)d_in[4];
    const float* bq    = (const float*)d_in[5];
    const float* wk    = (const float*)d_in[6];
    const float* bk    = (const float*)d_in[7];
    const float* wv    = (const float*)d_in[8];
    const float* bv    = (const float*)d_in[9];
    const float* wo    = (const float*)d_in[10];
    const float* laq   = (const float*)d_in[11];
    const float* lbq   = (const float*)d_in[12];
    const float* lak   = (const float*)d_in[13];
    const float* lbk   = (const float*)d_in[14];
    const float* lav   = (const float*)d_in[15];
    const float* lbv   = (const float*)d_in[16];
    const float* lao   = (const float*)d_in[17];
    const float* lbo   = (const float*)d_in[18];
    const float* ln2   = (const float*)d_in[19];
    const float* wg    = (const float*)d_in[20];
    const float* wu    = (const float*)d_in[21];
    const float* wd    = (const float*)d_in[22];
    const float* lnf   = (const float*)d_in[23];
    const float* cw1   = (const float*)d_in[24];
    const float* cb1   = (const float*)d_in[25];
    const float* cw2   = (const float*)d_in[26];
    const float* cb2   = (const float*)d_in[27];
    float* out = (float*)d_out;

    cudaFuncSetAttribute(gemm_bf16x3, cudaFuncAttributeMaxDynamicSharedMemorySize, GEMM_SMEM);
    cudaFuncSetAttribute(attn_scores_mma, cudaFuncAttributeMaxDynamicSharedMemorySize, GEMM_SMEM);
    cudaFuncSetAttribute(attn_ctx_mma, cudaFuncAttributeMaxDynamicSharedMemorySize, GEMM_SMEM);

    float *h, *x, *q, *k, *v, *sc, *ctx, *g, *u, *pooled, *cls, *rc, *rs;
    __nv_bfloat16 *xh, *xl, *qh, *ql, *kh, *kl, *vTh, *vTl, *ph, *pl, *ch, *cl, *gh, *gl, *whT, *wlT;
    cudaGetSymbolAddress((void**)&h,   d_h);
    cudaGetSymbolAddress((void**)&x,   d_x);
    cudaGetSymbolAddress((void**)&xh,  d_xh);
    cudaGetSymbolAddress((void**)&xl,  d_xl);
    cudaGetSymbolAddress((void**)&q,   d_q);
    cudaGetSymbolAddress((void**)&k,   d_k);
    cudaGetSymbolAddress((void**)&v,   d_v);
    cudaGetSymbolAddress((void**)&qh,  d_qh);
    cudaGetSymbolAddress((void**)&ql,  d_ql);
    cudaGetSymbolAddress((void**)&kh,  d_kh);
    cudaGetSymbolAddress((void**)&kl,  d_kl);
    cudaGetSymbolAddress((void**)&vTh, d_vTh);
    cudaGetSymbolAddress((void**)&vTl, d_vTl);
    cudaGetSymbolAddress((void**)&rc,  d_ropec);
    cudaGetSymbolAddress((void**)&rs,  d_ropes);
    cudaGetSymbolAddress((void**)&sc,  d_sc);
    cudaGetSymbolAddress((void**)&ph,  d_ph);
    cudaGetSymbolAddress((void**)&pl,  d_pl);
    cudaGetSymbolAddress((void**)&ctx, d_ctx);
    cudaGetSymbolAddress((void**)&ch,  d_ch);
    cudaGetSymbolAddress((void**)&cl,  d_cl);
    cudaGetSymbolAddress((void**)&g,   d_g);
    cudaGetSymbolAddress((void**)&u,   d_u);
    cudaGetSymbolAddress((void**)&gh,  d_gh);
    cudaGetSymbolAddress((void**)&gl,  d_gl);
    cudaGetSymbolAddress((void**)&pooled, d_pooled);
    cudaGetSymbolAddress((void**)&cls,    d_cls);
    cudaGetSymbolAddress((void**)&whT,    d_whT);
    cudaGetSymbolAddress((void**)&wlT,    d_wlT);

    // preprocessing: weights (with LoRA folded) + rope tables
    wsplit_all_kernel<<<Lc * TILES_PER_LAYER, dim3(32, 8)>>>(
        wq, wk, wv, wo, wg, wu, wd,
        laq, lbq, lak, lbk, lav, lbv, lao, lbo, whT, wlT);
    rope_table_kernel<<<Sc, 64>>>(rc, rs);
    embed_kernel<<<MTc, 256>>>(ids, embed, h);

    for (int l = 0; l < Lc; l++) {
        size_t lw = (size_t)l * LAYER_W;
        const float* LN1 = ln1 + (size_t)l * Hc;
        const float* BQ = bq + (size_t)l * QNc;
        const float* BK = bk + (size_t)l * KNc;
        const float* BV = bv + (size_t)l * KNc;
        const float* LN2 = ln2 + (size_t)l * Hc;

        rmsnorm_kernel<<<MTc, 256>>>(h, LN1, x, xh, xl);

        gemm_bf16x3<<<dim3(QNc / 128, MTc / 128, 1), 256, GEMM_SMEM>>>(
            xh, xl,
            whT + lw + WOFF_Q, wlT + lw + WOFF_Q, BQ, nullptr, q,
            nullptr, nullptr, nullptr, nullptr, nullptr,
            MTc, QNc, Hc);
        gemm_bf16x3<<<dim3(KNc / 128, MTc / 128, 2), 256, GEMM_SMEM>>>(
            xh, xl,
            whT + lw + WOFF_K, wlT + lw + WOFF_K, BK, nullptr, k,
            whT + lw + WOFF_V, wlT + lw + WOFF_V, BV, nullptr, v,
            MTc, KNc, Hc);

        rope_split2_kernel<<<dim3(MTc, NHc + NKVc), 64>>>(q, k, rc, rs, qh, ql, kh, kl);
        vsplitT_kernel<<<dim3(16, 16, Bc), dim3(32, 8)>>>(v, vTh, vTl);

        attn_scores_mma<<<dim3(4, 4, Bc * NHc), 256, GEMM_SMEM>>>(qh, ql, kh, kl, sc);
        softmax_kernel<<<Bc * NHc * Sc, 128>>>(sc, mask, ph, pl);
        attn_ctx_mma<<<dim3(1, 4, Bc * NHc), 256, GEMM_SMEM>>>(ph, pl, vTh, vTl, ctx, ch, cl);

        gemm_bf16x3<<<dim3(Hc / 128, MTc / 128, 1), 256, GEMM_SMEM>>>(
            ch, cl,
            whT + lw + WOFF_O, wlT + lw + WOFF_O, nullptr, h, h,
            nullptr, nullptr, nullptr, nullptr, nullptr,
            MTc, Hc, QNc);

        rmsnorm_kernel<<<MTc, 256>>>(h, LN2, x, xh, xl);
        gemm_bf16x3<<<dim3(Fc / 128, MTc / 128, 2), 256, GEMM_SMEM>>>(
            xh, xl,
            whT + lw + WOFF_G, wlT + lw + WOFF_G, nullptr, nullptr, g,
            whT + lw + WOFF_U, wlT + lw + WOFF_U, nullptr, nullptr, u,
            MTc, Fc, Hc);
        silu_mul_kernel<<<(MTc * Fc) / 256, 256>>>(g, u, gh, gl, MTc * Fc);
        gemm_bf16x3<<<dim3(Hc / 128, MTc / 128, 1), 256, GEMM_SMEM>>>(
            gh, gl,
            whT + lw + WOFF_D, wlT + lw + WOFF_D, nullptr, h, h,
            nullptr, nullptr, nullptr, nullptr, nullptr,
            MTc, Hc, Fc);
    }

    pool_kernel<<<Bc, 256>>>(h, mask, lnf, pooled);
    cls1_kernel<<<dim3(Hc / 128, Bc), 128>>>(pooled, cw1, cb1, cls);
    cls2_kernel<<<Bc * NCc, 128>>>(cls, cw2, cb2, out);
}

// round 12
// speedup vs baseline: 1.1561x; 1.0030x over previous
#include <cuda_runtime.h>
#include <cuda_bf16.h>
#include <cstddef>
#include <cstdint>
#include <math.h>

// ---------------- problem constants ----------------
#define Lc   4
#define Hc   2048
#define NHc  16
#define NKVc 4
#define DHc  128
#define Fc   5632
#define Rc   16
#define Bc   4
#define Sc   512
#define NCc  2
#define MTc  (Bc * Sc)          // 2048 tokens
#define QNc  (NHc * DHc)        // 2048
#define KNc  (NKVc * DHc)       // 512
#define LORA_SCALE 2.0f
#define INV_SQRT_DH 0.08838834764831845f

// per-layer transposed weight buffer offsets (elements)
#define WOFF_Q 0
#define WOFF_K (WOFF_Q + Hc * QNc)
#define WOFF_V (WOFF_K + Hc * KNc)
#define WOFF_O (WOFF_V + Hc * KNc)
#define WOFF_G (WOFF_O + QNc * Hc)
#define WOFF_U (WOFF_G + Hc * Fc)
#define WOFF_D (WOFF_U + Hc * Fc)
#define LAYER_W (WOFF_D + Fc * Hc)   // 45,088,768

// ---------------- scratch (static device memory; allocation-free) ----------------
__device__ float          d_h[MTc * Hc];
__device__ __nv_bfloat16  d_xh[MTc * Hc];
__device__ __nv_bfloat16  d_xl[MTc * Hc];
__device__ float          d_q[MTc * QNc];
__device__ float          d_k[MTc * KNc];
__device__ float          d_v[MTc * KNc];
__device__ __nv_bfloat16  d_qh[MTc * QNc];
__device__ __nv_bfloat16  d_ql[MTc * QNc];
__device__ __nv_bfloat16  d_kh[MTc * KNc];
__device__ __nv_bfloat16  d_kl[MTc * KNc];
__device__ __nv_bfloat16  d_vTh[Bc * KNc * Sc];
__device__ __nv_bfloat16  d_vTl[Bc * KNc * Sc];
__device__ float          d_ropec[Sc * 64];
__device__ float          d_ropes[Sc * 64];
__device__ float          d_sc[Bc * NHc * Sc * Sc];
__device__ __nv_bfloat16  d_ph[Bc * NHc * Sc * Sc];
__device__ __nv_bfloat16  d_pl[Bc * NHc * Sc * Sc];
__device__ __nv_bfloat16  d_ch[MTc * QNc];
__device__ __nv_bfloat16  d_cl[MTc * QNc];
__device__ float          d_g[MTc * Fc];
__device__ float          d_u[MTc * Fc];
__device__ __nv_bfloat16  d_gh[MTc * Fc];
__device__ __nv_bfloat16  d_gl[MTc * Fc];
__device__ float          d_pooled[Bc * Hc];
__device__ float          d_cls[Bc * Hc];
__device__ __nv_bfloat16  d_whT[(size_t)Lc * LAYER_W];  // hi weights (lora folded), [N,K]
__device__ __nv_bfloat16  d_wlT[(size_t)Lc * LAYER_W];  // lo weights, [N,K]

// ---------------- PTX helpers ----------------
__device__ __forceinline__ uint32_t sptr(const void* p) {
    return (uint32_t)__cvta_generic_to_shared(p);
}
#define CP_ASYNC16(dst, src) asm volatile("cp.async.cg.shared.global [%0], [%1], 16;\n" :: "r"(dst), "l"(src))
#define CP_COMMIT()          asm volatile("cp.async.commit_group;\n" ::: "memory")
#define CP_WAIT(n)           asm volatile("cp.async.wait_group %0;\n" :: "n"(n) : "memory")

__device__ __forceinline__ void mma_bf16(float* c, const uint32_t* a, const uint32_t* b) {
    asm volatile(
        "mma.sync.aligned.m16n8k16.row.col.f32.bf16.bf16.f32 "
        "{%0,%1,%2,%3}, {%4,%5,%6,%7}, {%8,%9}, {%0,%1,%2,%3};\n"
        : "+f"(c[0]), "+f"(c[1]), "+f"(c[2]), "+f"(c[3])
        : "r"(a[0]), "r"(a[1]), "r"(a[2]), "r"(a[3]), "r"(b[0]), "r"(b[1]));
}

__device__ __forceinline__ void ldsm4(uint32_t* r, uint32_t addr) {
    asm volatile("ldmatrix.sync.aligned.m8n8.x4.shared.b16 {%0,%1,%2,%3}, [%4];"
        : "=r"(r[0]), "=r"(r[1]), "=r"(r[2]), "=r"(r[3]) : "r"(addr));
}

// ---------------- ALL weights: transpose + LoRA fold + bf16 split, ONE launch ----------------
#define TILES_PER_LAYER 22016
__global__ void wsplit_all_kernel(const float* __restrict__ wq, const float* __restrict__ wk,
                                  const float* __restrict__ wv, const float* __restrict__ wo,
                                  const float* __restrict__ wg, const float* __restrict__ wu,
                                  const float* __restrict__ wd,
                                  const float* __restrict__ laq, const float* __restrict__ lbq,
                                  const float* __restrict__ lak, const float* __restrict__ lbk,
                                  const float* __restrict__ lav, const float* __restrict__ lbv,
                                  const float* __restrict__ lao, const float* __restrict__ lbo,
                                  __nv_bfloat16* __restrict__ hiT,
                                  __nv_bfloat16* __restrict__ loT) {
    int l = blockIdx.x / TILES_PER_LAYER;
    int r = blockIdx.x % TILES_PER_LAYER;
    const float* src; size_t woff; int K, N, tidx;
    const float* loA = nullptr; const float* loB = nullptr;
    if (r < 2048)       { src = wq + (size_t)l * Hc * QNc; woff = WOFF_Q; K = Hc;  N = QNc; tidx = r;
                          loA = laq + (size_t)l * Rc * Hc;  loB = lbq + (size_t)l * QNc * Rc; }
    else if (r < 2560)  { src = wk + (size_t)l * Hc * KNc; woff = WOFF_K; K = Hc;  N = KNc; tidx = r - 2048;
                          loA = lak + (size_t)l * Rc * Hc;  loB = lbk + (size_t)l * KNc * Rc; }
    else if (r < 3072)  { src = wv + (size_t)l * Hc * KNc; woff = WOFF_V; K = Hc;  N = KNc; tidx = r - 2560;
                          loA = lav + (size_t)l * Rc * Hc;  loB = lbv + (size_t)l * KNc * Rc; }
    else if (r < 5120)  { src = wo + (size_t)l * QNc * Hc; woff = WOFF_O; K = QNc; N = Hc;  tidx = r - 3072;
                          loA = lao + (size_t)l * Rc * QNc; loB = lbo + (size_t)l * Hc * Rc; }
    else if (r < 10752) { src = wg + (size_t)l * Hc * Fc;  woff = WOFF_G; K = Hc;  N = Fc;  tidx = r - 5120; }
    else if (r < 16384) { src = wu + (size_t)l * Hc * Fc;  woff = WOFF_U; K = Hc;  N = Fc;  tidx = r - 10752; }
    else                { src = wd + (size_t)l * Fc * Hc;  woff = WOFF_D; K = Fc;  N = Hc;  tidx = r - 16384; }
    woff += (size_t)l * LAYER_W;
    int nt = N / 32;
    int k0 = (tidx / nt) * 64, n0 = (tidx % nt) * 32;

    __shared__ float tile[64][33];   // [k][n]
    __shared__ float sA[16][64];     // lora A[r][k-local]
    __shared__ float sB[32][17];     // lora B[n-local][r]
    int tx = threadIdx.x, ty = threadIdx.y;   // (32, 8)
    int tid = ty * 32 + tx;
    for (int i = ty; i < 64; i += 8)
        tile[i][tx] = src[(size_t)(k0 + i) * N + n0 + tx];
    if (loA) {
        for (int idx = tid; idx < 1024; idx += 256) {
            int rr = idx >> 6, kk = idx & 63;
            sA[rr][kk] = loA[(size_t)rr * K + k0 + kk];
        }
        for (int idx = tid; idx < 512; idx += 256) {
            int nn = idx >> 4, rr = idx & 15;
            sB[nn][rr] = loB[(size_t)(n0 + nn) * Rc + rr];
        }
    }
    __syncthreads();
    for (int i = ty; i < 32; i += 8) {
        float v0 = tile[2 * tx][i], v1 = tile[2 * tx + 1][i];
        if (loA) {
            float d0 = 0.f, d1 = 0.f;
            #pragma unroll
            for (int rr = 0; rr < Rc; rr++) {
                float bb = sB[i][rr];
                d0 += sA[rr][2 * tx] * bb;
                d1 += sA[rr][2 * tx + 1] * bb;
            }
            v0 += LORA_SCALE * d0;
            v1 += LORA_SCALE * d1;
        }
        __nv_bfloat16 h0 = __float2bfloat16(v0), h1 = __float2bfloat16(v1);
        __nv_bfloat162 hv; hv.x = h0; hv.y = h1;
        __nv_bfloat162 lv;
        lv.x = __float2bfloat16(v0 - __bfloat162float(h0));
        lv.y = __float2bfloat16(v1 - __bfloat162float(h1));
        size_t idx = woff + (size_t)(n0 + i) * K + k0 + 2 * tx;
        *(__nv_bfloat162*)(hiT + idx) = hv;
        *(__nv_bfloat162*)(loT + idx) = lv;
    }
}

// ---------------- RoPE table precompute ----------------
__global__ void rope_table_kernel(float* __restrict__ rc, float* __restrict__ rs) {
    int s = blockIdx.x;
    int d = threadIdx.x;
    float freq = powf(1000000.0f, -(float)d / 64.0f);
    float ang = (float)s * freq;
    float sn, cs;
    sincosf(ang, &sn, &cs);
    rc[s * 64 + d] = cs;
    rs[s * 64 + d] = sn;
}

// ---------------- embedding gather ----------------
__global__ void embed_kernel(const int* __restrict__ ids,
                             const float* __restrict__ emb,
                             float* __restrict__ h) {
    int row = blockIdx.x;
    const float* src = emb + (size_t)ids[row] * Hc;
    float* dst = h + (size_t)row * Hc;
    for (int i = threadIdx.x; i < Hc; i += 256) dst[i] = src[i];
}

// ---------------- rmsnorm: bf16 hi/lo split only ----------------
__global__ void rmsnorm_kernel(const float* __restrict__ in,
                               const float* __restrict__ w,
                               __nv_bfloat16* __restrict__ oh,
                               __nv_bfloat16* __restrict__ ol) {
    int row = blockIdx.x;
    const float* x = in + (size_t)row * Hc;
    float ss = 0.f;
    for (int i = threadIdx.x; i < Hc; i += 256) { float v = x[i]; ss += v * v; }
    __shared__ float sh[256];
    sh[threadIdx.x] = ss; __syncthreads();
    for (int o = 128; o; o >>= 1) { if (threadIdx.x < o) sh[threadIdx.x] += sh[threadIdx.x + o]; __syncthreads(); }
    float sc = rsqrtf(sh[0] / (float)Hc + 1e-6f);
    for (int i = threadIdx.x; i < Hc; i += 256) {
        float v = x[i] * sc * w[i];
        __nv_bfloat16 hb = __float2bfloat16(v);
        oh[(size_t)row * Hc + i] = hb;
        ol[(size_t)row * Hc + i] = __float2bfloat16(v - __bfloat162float(hb));
    }
}

// ---------------- bf16x3 mma.sync GEMM (projections, lora pre-folded) ----------------
#define TILE_B 8192                  // 128 * 64B
#define STAGE_B (4 * TILE_B)         // Ah, Al, Bh, Bl = 32KB
#define NSTAGE 3
#define GEMM_SMEM (NSTAGE * STAGE_B) // 96KB

__global__ __launch_bounds__(256, 2) void gemm_bf16x3(
    const __nv_bfloat16* __restrict__ Ahi, const __nv_bfloat16* __restrict__ Alo,
    const __nv_bfloat16* __restrict__ Bhi1, const __nv_bfloat16* __restrict__ Blo1,
    const float* __restrict__ bias1, const float* __restrict__ resid1,
    float* __restrict__ C1,
    const __nv_bfloat16* __restrict__ Bhi2, const __nv_bfloat16* __restrict__ Blo2,
    const float* __restrict__ bias2, const float* __restrict__ resid2,
    float* __restrict__ C2,
    int M, int N, int K) {
    extern __shared__ uint8_t smraw[];
    const int tid = threadIdx.x;
    const int bm = blockIdx.y * 128, bn = blockIdx.x * 128;

    const __nv_bfloat16* Bhi = Bhi1; const __nv_bfloat16* Blo = Blo1;
    const float* bias = bias1; const float* resid = resid1;
    float* C = C1;
    if (blockIdx.z == 1) {
        Bhi = Bhi2; Blo = Blo2; bias = bias2; resid = resid2; C = C2;
    }

    const int warpId = tid >> 5, lane = tid & 31;
    const int warpM = warpId & 3, warpN = warpId >> 2;
    const int m0 = warpM * 32, n0 = warpN * 64;
    const int grp = lane >> 2, qd = lane & 3;

    const int lrow16 = lane & 15;
    const int lch    = lane >> 4;
    const int lsw    = (lrow16 >> 1) & 3;
    const uint32_t sb = sptr(smraw);

    const int lrow = tid >> 1, lg0 = (tid & 1) * 2;
    const int lswz = (lrow >> 1) & 3;
    const __nv_bfloat16* pAh = Ahi + (size_t)(bm + lrow) * K;
    const __nv_bfloat16* pAl = Alo + (size_t)(bm + lrow) * K;
    const __nv_bfloat16* pBh = Bhi + (size_t)(bn + lrow) * K;
    const __nv_bfloat16* pBl = Blo + (size_t)(bn + lrow) * K;
    const uint32_t srow = sb + lrow * 64;

    float acc[2][8][4];
    #pragma unroll
    for (int mt = 0; mt < 2; mt++)
        #pragma unroll
        for (int nt = 0; nt < 8; nt++)
            #pragma unroll
            for (int r = 0; r < 4; r++) acc[mt][nt][r] = 0.f;

    auto loadStage = [&](int st, int k0) {
        uint32_t d = srow + st * STAGE_B;
        #pragma unroll
        for (int i = 0; i < 2; i++) {
            int g = lg0 + i;
            uint32_t off = (uint32_t)(g ^ lswz) << 4;
            CP_ASYNC16(d + 0 * TILE_B + off, pAh + k0 + g * 8);
            CP_ASYNC16(d + 1 * TILE_B + off, pAl + k0 + g * 8);
            CP_ASYNC16(d + 2 * TILE_B + off, pBh + k0 + g * 8);
            CP_ASYNC16(d + 3 * TILE_B + off, pBl + k0 + g * 8);
        }
        CP_COMMIT();
    };

    const int KT = K >> 5;
    loadStage(0, 0);
    if (KT > 1) loadStage(1, 32);

    for (int kt = 0; kt < KT; kt++) {
        const int st = kt % NSTAGE;
        if (kt + 1 < KT) { CP_WAIT(1); } else { CP_WAIT(0); }
        __syncthreads();
        if (kt + 2 < KT) loadStage((kt + 2) % NSTAGE, (kt + 2) << 5);

        const uint32_t tAh = sb + st * STAGE_B;
        const uint32_t tAl = tAh + TILE_B;
        const uint32_t tBh = tAh + 2 * TILE_B;
        const uint32_t tBl = tAh + 3 * TILE_B;

        #pragma unroll
        for (int ks = 0; ks < 2; ks++) {
            const uint32_t choff = (uint32_t)(((ks * 2 + lch) ^ lsw)) << 4;
            uint32_t ra0 = (uint32_t)(m0 + lrow16) * 64 + choff;
            uint32_t ra1 = (uint32_t)(m0 + 16 + lrow16) * 64 + choff;
            uint32_t rb0 = (uint32_t)(n0 + lrow16) * 64 + choff;

            uint32_t afH[2][4], afL[2][4], bf[8][2];

            #pragma unroll
            for (int np = 0; np < 4; np++) {
                uint32_t q[4];
                ldsm4(q, tBh + rb0 + (uint32_t)(np * 16 * 64));
                bf[2 * np][0] = q[0]; bf[2 * np + 1][0] = q[1];
                bf[2 * np][1] = q[2]; bf[2 * np + 1][1] = q[3];
            }
            ldsm4(afH[0], tAh + ra0);
            ldsm4(afH[1], tAh + ra1);
            #pragma unroll
            for (int mt = 0; mt < 2; mt++)
                #pragma unroll
                for (int nt = 0; nt < 8; nt++)
                    mma_bf16(acc[mt][nt], afH[mt], bf[nt]);
            ldsm4(afL[0], tAl + ra0);
            ldsm4(afL[1], tAl + ra1);
            #pragma unroll
            for (int mt = 0; mt < 2; mt++)
                #pragma unroll
                for (int nt = 0; nt < 8; nt++)
                    mma_bf16(acc[mt][nt], afL[mt], bf[nt]);
            #pragma unroll
            for (int np = 0; np < 4; np++) {
                uint32_t q[4];
                ldsm4(q, tBl + rb0 + (uint32_t)(np * 16 * 64));
                bf[2 * np][0] = q[0]; bf[2 * np + 1][0] = q[1];
                bf[2 * np][1] = q[2]; bf[2 * np + 1][1] = q[3];
            }
            #pragma unroll
            for (int mt = 0; mt < 2; mt++)
                #pragma unroll
                for (int nt = 0; nt < 8; nt++)
                    mma_bf16(acc[mt][nt], afH[mt], bf[nt]);
        }
    }

    #pragma unroll
    for (int mt = 0; mt < 2; mt++) {
        int lr0 = m0 + mt * 16 + grp;
        int lr1 = lr0 + 8;
        int row0 = bm + lr0, row1 = bm + lr1;
        #pragma unroll
        for (int nt = 0; nt < 8; nt++) {
            int lc0 = n0 + nt * 8 + 2 * qd;
            int col0 = bn + lc0, col1 = col0 + 1;
            float o00 = acc[mt][nt][0], o01 = acc[mt][nt][1];
            float o10 = acc[mt][nt][2], o11 = acc[mt][nt][3];
            if (bias) {
                float b0 = bias[col0], b1 = bias[col1];
                o00 += b0; o01 += b1; o10 += b0; o11 += b1;
            }
            if (resid) {
                o00 += resid[(size_t)row0 * N + col0];
                o01 += resid[(size_t)row0 * N + col1];
                o10 += resid[(size_t)row1 * N + col0];
                o11 += resid[(size_t)row1 * N + col1];
            }
            *(float2*)(C + (size_t)row0 * N + col0) = make_float2(o00, o01);
            *(float2*)(C + (size_t)row1 * N + col0) = make_float2(o10, o11);
        }
    }
}

// ---------------- attention scores on tensor cores: S = Qs * K^T (bf16x3) ----------------
__global__ __launch_bounds__(256, 2) void attn_scores_mma(
    const __nv_bfloat16* __restrict__ qh, const __nv_bfloat16* __restrict__ ql,
    const __nv_bfloat16* __restrict__ kh, const __nv_bfloat16* __restrict__ kl,
    float* __restrict__ scores) {
    if (blockIdx.x > blockIdx.y) return;
    extern __shared__ uint8_t smraw[];
    const int tid = threadIdx.x;
    const int bh = blockIdx.z;
    const int b = bh >> 4, hd = bh & 15, kvh = hd >> 2;
    const int bm = blockIdx.y * 128, bn = blockIdx.x * 128;
    const __nv_bfloat16* Ah = qh + (size_t)b * Sc * QNc + (size_t)hd * DHc;
    const __nv_bfloat16* Al = ql + (size_t)b * Sc * QNc + (size_t)hd * DHc;
    const __nv_bfloat16* Bh = kh + (size_t)b * Sc * KNc + (size_t)kvh * DHc;
    const __nv_bfloat16* Bl = kl + (size_t)b * Sc * KNc + (size_t)kvh * DHc;
    float* C = scores + (size_t)bh * Sc * Sc;

    const int warpId = tid >> 5, lane = tid & 31;
    const int warpM = warpId & 3, warpN = warpId >> 2;
    const int m0 = warpM * 32, n0 = warpN * 64;
    const int grp = lane >> 2, qd = lane & 3;
    const int lrow16 = lane & 15, lch = lane >> 4, lsw = (lrow16 >> 1) & 3;
    const uint32_t sb = sptr(smraw);

    const int lrow = tid >> 1, lg0 = (tid & 1) * 2;
    const int lswz = (lrow >> 1) & 3;
    const __nv_bfloat16* pAh = Ah + (size_t)(bm + lrow) * QNc;
    const __nv_bfloat16* pAl = Al + (size_t)(bm + lrow) * QNc;
    const __nv_bfloat16* pBh = Bh + (size_t)(bn + lrow) * KNc;
    const __nv_bfloat16* pBl = Bl + (size_t)(bn + lrow) * KNc;
    const uint32_t srow = sb + lrow * 64;

    float acc[2][8][4];
    #pragma unroll
    for (int mt = 0; mt < 2; mt++)
        #pragma unroll
        for (int nt = 0; nt < 8; nt++)
            #pragma unroll
            for (int r = 0; r < 4; r++) acc[mt][nt][r] = 0.f;

    auto loadStage = [&](int st, int k0) {
        uint32_t d = srow + st * STAGE_B;
        #pragma unroll
        for (int i = 0; i < 2; i++) {
            int g = lg0 + i;
            uint32_t off = (uint32_t)(g ^ lswz) << 4;
            CP_ASYNC16(d + 0 * TILE_B + off, pAh + k0 + g * 8);
            CP_ASYNC16(d + 1 * TILE_B + off, pAl + k0 + g * 8);
            CP_ASYNC16(d + 2 * TILE_B + off, pBh + k0 + g * 8);
            CP_ASYNC16(d + 3 * TILE_B + off, pBl + k0 + g * 8);
        }
        CP_COMMIT();
    };

    const int KT = DHc >> 5;
    loadStage(0, 0);
    loadStage(1, 32);

    for (int kt = 0; kt < KT; kt++) {
        const int st = kt % NSTAGE;
        if (kt + 1 < KT) { CP_WAIT(1); } else { CP_WAIT(0); }
        __syncthreads();
        if (kt + 2 < KT) loadStage((kt + 2) % NSTAGE, (kt + 2) << 5);

        const uint32_t tAh = sb + st * STAGE_B;
        const uint32_t tAl = tAh + TILE_B;
        const uint32_t tBh = tAh + 2 * TILE_B;
        const uint32_t tBl = tAh + 3 * TILE_B;

        #pragma unroll
        for (int ks = 0; ks < 2; ks++) {
            const uint32_t choff = (uint32_t)(((ks * 2 + lch) ^ lsw)) << 4;
            uint32_t ra0 = (uint32_t)(m0 + lrow16) * 64 + choff;
            uint32_t ra1 = (uint32_t)(m0 + 16 + lrow16) * 64 + choff;
            uint32_t rb0 = (uint32_t)(n0 + lrow16) * 64 + choff;
            uint32_t afH[2][4], afL[2][4], bf[8][2];
            #pragma unroll
            for (int np = 0; np < 4; np++) {
                uint32_t q[4];
                ldsm4(q, tBh + rb0 + (uint32_t)(np * 16 * 64));
                bf[2 * np][0] = q[0]; bf[2 * np + 1][0] = q[1];
                bf[2 * np][1] = q[2]; bf[2 * np + 1][1] = q[3];
            }
            ldsm4(afH[0], tAh + ra0);
            ldsm4(afH[1], tAh + ra1);
            #pragma unroll
            for (int mt = 0; mt < 2; mt++)
                #pragma unroll
                for (int nt = 0; nt < 8; nt++)
                    mma_bf16(acc[mt][nt], afH[mt], bf[nt]);
            ldsm4(afL[0], tAl + ra0);
            ldsm4(afL[1], tAl + ra1);
            #pragma unroll
            for (int mt = 0; mt < 2; mt++)
                #pragma unroll
                for (int nt = 0; nt < 8; nt++)
                    mma_bf16(acc[mt][nt], afL[mt], bf[nt]);
            #pragma unroll
            for (int np = 0; np < 4; np++) {
                uint32_t q[4];
                ldsm4(q, tBl + rb0 + (uint32_t)(np * 16 * 64));
                bf[2 * np][0] = q[0]; bf[2 * np + 1][0] = q[1];
                bf[2 * np][1] = q[2]; bf[2 * np + 1][1] = q[3];
            }
            #pragma unroll
            for (int mt = 0; mt < 2; mt++)
                #pragma unroll
                for (int nt = 0; nt < 8; nt++)
                    mma_bf16(acc[mt][nt], afH[mt], bf[nt]);
        }
    }

    #pragma unroll
    for (int mt = 0; mt < 2; mt++) {
        int row0 = bm + m0 + mt * 16 + grp;
        int row1 = row0 + 8;
        #pragma unroll
        for (int nt = 0; nt < 8; nt++) {
            int col = bn + n0 + nt * 8 + 2 * qd;
            *(float2*)(C + (size_t)row0 * Sc + col) = make_float2(acc[mt][nt][0], acc[mt][nt][1]);
            *(float2*)(C + (size_t)row1 * Sc + col) = make_float2(acc[mt][nt][2], acc[mt][nt][3]);
        }
    }
}

// ---------------- attention context on tensor cores: ctx = P * V (bf16x3) ----------------
__global__ __launch_bounds__(256, 2) void attn_ctx_mma(
    const __nv_bfloat16* __restrict__ ph, const __nv_bfloat16* __restrict__ pl,
    const __nv_bfloat16* __restrict__ vTh, const __nv_bfloat16* __restrict__ vTl,
    __nv_bfloat16* __restrict__ ch, __nv_bfloat16* __restrict__ cl) {
    extern __shared__ uint8_t smraw[];
    const int tid = threadIdx.x;
    const int bh = blockIdx.z;
    const int b = bh >> 4, hd = bh & 15, kvh = hd >> 2;
    const int bm = blockIdx.y * 128;
    const __nv_bfloat16* Ah = ph + (size_t)bh * Sc * Sc;
    const __nv_bfloat16* Al = pl + (size_t)bh * Sc * Sc;
    const __nv_bfloat16* Bh = vTh + ((size_t)b * KNc + (size_t)kvh * DHc) * Sc;
    const __nv_bfloat16* Bl = vTl + ((size_t)b * KNc + (size_t)kvh * DHc) * Sc;

    const int warpId = tid >> 5, lane = tid & 31;
    const int warpM = warpId & 3, warpN = warpId >> 2;
    const int m0 = warpM * 32, n0 = warpN * 64;
    const int grp = lane >> 2, qd = lane & 3;
    const int lrow16 = lane & 15, lch = lane >> 4, lsw = (lrow16 >> 1) & 3;
    const uint32_t sb = sptr(smraw);

    const int lrow = tid >> 1, lg0 = (tid & 1) * 2;
    const int lswz = (lrow >> 1) & 3;
    const __nv_bfloat16* pAh = Ah + (size_t)(bm + lrow) * Sc;
    const __nv_bfloat16* pAl = Al + (size_t)(bm + lrow) * Sc;
    const __nv_bfloat16* pBh = Bh + (size_t)lrow * Sc;
    const __nv_bfloat16* pBl = Bl + (size_t)lrow * Sc;
    const uint32_t srow = sb + lrow * 64;

    float acc[2][8][4];
    #pragma unroll
    for (int mt = 0; mt < 2; mt++)
        #pragma unroll
        for (int nt = 0; nt < 8; nt++)
            #pragma unroll
            for (int r = 0; r < 4; r++) acc[mt][nt][r] = 0.f;

    auto loadStage = [&](int st, int k0) {
        uint32_t d = srow + st * STAGE_B;
        #pragma unroll
        for (int i = 0; i < 2; i++) {
            int g = lg0 + i;
            uint32_t off = (uint32_t)(g ^ lswz) << 4;
            CP_ASYNC16(d + 0 * TILE_B + off, pAh + k0 + g * 8);
            CP_ASYNC16(d + 1 * TILE_B + off, pAl + k0 + g * 8);
            CP_ASYNC16(d + 2 * TILE_B + off, pBh + k0 + g * 8);
            CP_ASYNC16(d + 3 * TILE_B + off, pBl + k0 + g * 8);
        }
        CP_COMMIT();
    };

    const int KT = (bm >> 5) + 4;
    loadStage(0, 0);
    loadStage(1, 32);

    for (int kt = 0; kt < KT; kt++) {
        const int st = kt % NSTAGE;
        if (kt + 1 < KT) { CP_WAIT(1); } else { CP_WAIT(0); }
        __syncthreads();
        if (kt + 2 < KT) loadStage((kt + 2) % NSTAGE, (kt + 2) << 5);

        const uint32_t tAh = sb + st * STAGE_B;
        const uint32_t tAl = tAh + TILE_B;
        const uint32_t tBh = tAh + 2 * TILE_B;
        const uint32_t tBl = tAh + 3 * TILE_B;

        #pragma unroll
        for (int ks = 0; ks < 2; ks++) {
            const uint32_t choff = (uint32_t)(((ks * 2 + lch) ^ lsw)) << 4;
            uint32_t ra0 = (uint32_t)(m0 + lrow16) * 64 + choff;
            uint32_t ra1 = (uint32_t)(m0 + 16 + lrow16) * 64 + choff;
            uint32_t rb0 = (uint32_t)(n0 + lrow16) * 64 + choff;
            uint32_t afH[2][4], afL[2][4], bf[8][2];
            #pragma unroll
            for (int np = 0; np < 4; np++) {
                uint32_t q[4];
                ldsm4(q, tBh + rb0 + (uint32_t)(np * 16 * 64));
                bf[2 * np][0] = q[0]; bf[2 * np + 1][0] = q[1];
                bf[2 * np][1] = q[2]; bf[2 * np + 1][1] = q[3];
            }
            ldsm4(afH[0], tAh + ra0);
            ldsm4(afH[1], tAh + ra1);
            #pragma unroll
            for (int mt = 0; mt < 2; mt++)
                #pragma unroll
                for (int nt = 0; nt < 8; nt++)
                    mma_bf16(acc[mt][nt], afH[mt], bf[nt]);
            ldsm4(afL[0], tAl + ra0);
            ldsm4(afL[1], tAl + ra1);
            #pragma unroll
            for (int mt = 0; mt < 2; mt++)
                #pragma unroll
                for (int nt = 0; nt < 8; nt++)
                    mma_bf16(acc[mt][nt], afL[mt], bf[nt]);
            #pragma unroll
            for (int np = 0; np < 4; np++) {
                uint32_t q[4];
                ldsm4(q, tBl + rb0 + (uint32_t)(np * 16 * 64));
                bf[2 * np][0] = q[0]; bf[2 * np + 1][0] = q[1];
                bf[2 * np][1] = q[2]; bf[2 * np + 1][1] = q[3];
            }
            #pragma unroll
            for (int mt = 0; mt < 2; mt++)
                #pragma unroll
                for (int nt = 0; nt < 8; nt++)
                    mma_bf16(acc[mt][nt], afH[mt], bf[nt]);
        }
    }

    #pragma unroll
    for (int mt = 0; mt < 2; mt++) {
        int lr0 = m0 + mt * 16 + grp;
        #pragma unroll
        for (int half = 0; half < 2; half++) {
            int row = bm + lr0 + half * 8;
            size_t base = ((size_t)(b * Sc + row)) * QNc + (size_t)hd * DHc;
            #pragma unroll
            for (int nt = 0; nt < 8; nt++) {
                int col = n0 + nt * 8 + 2 * qd;
                float v0 = acc[mt][nt][half * 2 + 0];
                float v1 = acc[mt][nt][half * 2 + 1];
                __nv_bfloat16 h0 = __float2bfloat16(v0);
                __nv_bfloat16 h1 = __float2bfloat16(v1);
                __nv_bfloat162 hv; hv.x = h0; hv.y = h1;
                __nv_bfloat162 lv;
                lv.x = __float2bfloat16(v0 - __bfloat162float(h0));
                lv.y = __float2bfloat16(v1 - __bfloat162float(h1));
                *(__nv_bfloat162*)(ch + base + col) = hv;
                *(__nv_bfloat162*)(cl + base + col) = lv;
            }
        }
    }
}

// ---------------- RoPE (q+k fused), table-driven, + scale + bf16 hi/lo split ----------------
__global__ void rope_split2_kernel(const float* __restrict__ qb, const float* __restrict__ kb,
                                   const float* __restrict__ rc, const float* __restrict__ rs,
                                   __nv_bfloat16* __restrict__ qh, __nv_bfloat16* __restrict__ ql,
                                   __nv_bfloat16* __restrict__ kh, __nv_bfloat16* __restrict__ kl) {
    int token = blockIdx.x;
    int head  = blockIdx.y;       // 0..19: 0-15 = q, 16-19 = k
    int d = threadIdx.x;
    int s = token % Sc;
    const float* p;
    __nv_bfloat16 *oh, *ol;
    size_t idx;
    float scale;
    if (head < NHc) {
        p = qb + ((size_t)token * NHc + head) * DHc;
        idx = ((size_t)token * NHc + head) * DHc;
        oh = qh; ol = ql; scale = INV_SQRT_DH;
    } else {
        int h2 = head - NHc;
        p = kb + ((size_t)token * NKVc + h2) * DHc;
        idx = ((size_t)token * NKVc + h2) * DHc;
        oh = kh; ol = kl; scale = 1.0f;
    }
    float cs = rc[s * 64 + d];
    float sn = rs[s * 64 + d];
    float x1 = p[d], x2 = p[d + 64];
    float v0 = (x1 * cs - x2 * sn) * scale;
    float v1 = (x2 * cs + x1 * sn) * scale;
    __nv_bfloat16 h0 = __float2bfloat16(v0);
    __nv_bfloat16 h1 = __float2bfloat16(v1);
    oh[idx + d]      = h0;
    ol[idx + d]      = __float2bfloat16(v0 - __bfloat162float(h0));
    oh[idx + d + 64] = h1;
    ol[idx + d + 64] = __float2bfloat16(v1 - __bfloat162float(h1));
}

// ---------------- V transpose + split ----------------
__global__ void vsplitT_kernel(const float* __restrict__ v,
                               __nv_bfloat16* __restrict__ vTh,
                               __nv_bfloat16* __restrict__ vTl) {
    __shared__ float tile[32][33];
    int b = blockIdx.z;
    int t0 = blockIdx.x * 32, d0 = blockIdx.y * 32;
    int tx = threadIdx.x, ty = threadIdx.y;
    for (int i = ty; i < 32; i += 8)
        tile[i][tx] = v[(size_t)(b * Sc + t0 + i) * KNc + d0 + tx];
    __syncthreads();
    for (int i = ty; i < 32; i += 8) {
        float val = tile[tx][i];
        size_t idx = ((size_t)b * KNc + d0 + i) * Sc + t0 + tx;
        __nv_bfloat16 hb = __float2bfloat16(val);
        vTh[idx] = hb;
        vTl[idx] = __float2bfloat16(val - __bfloat162float(hb));
    }
}

// ---------------- masked softmax -> bf16 hi/lo P ----------------
__global__ void softmax_kernel(const float* __restrict__ scores, const int* __restrict__ mask,
                               __nv_bfloat16* __restrict__ ph, __nv_bfloat16* __restrict__ pl) {
    int row = blockIdx.x;
    int qpos = row % Sc;
    int b = row / (NHc * Sc);
    const float* r = scores + (size_t)row * Sc;
    int t = threadIdx.x;
    float v[4];
    float mx = -3.0e38f;
    #pragma unroll
    for (int i = 0; i < 4; i++) {
        int k = t + 128 * i;
        bool ok = (k <= qpos) && (mask[b * Sc + k] > 0);
        v[i] = ok ? r[k] : -1e30f;
        mx = fmaxf(mx, v[i]);
    }
    __shared__ float sh[128];
    sh[t] = mx; __syncthreads();
    for (int o = 64; o; o >>= 1) { if (t < o) sh[t] = fmaxf(sh[t], sh[t + o]); __syncthreads(); }
    mx = sh[0]; __syncthreads();
    float sm = 0.f;
    #pragma unroll
    for (int i = 0; i < 4; i++) { v[i] = expf(v[i] - mx); sm += v[i]; }
    sh[t] = sm; __syncthreads();
    for (int o = 64; o; o >>= 1) { if (t < o) sh[t] += sh[t + o]; __syncthreads(); }
    float inv = 1.0f / sh[0];
    #pragma unroll
    for (int i = 0; i < 4; i++) {
        float p = v[i] * inv;
        __nv_bfloat16 hb = __float2bfloat16(p);
        ph[(size_t)row * Sc + t + 128 * i] = hb;
        pl[(size_t)row * Sc + t + 128 * i] = __float2bfloat16(p - __bfloat162float(hb));
    }
}

// ---------------- silu(g)*u -> bf16 hi/lo ----------------
__global__ void silu_mul_kernel(const float* __restrict__ g, const float* __restrict__ u,
                                __nv_bfloat16* __restrict__ gh, __nv_bfloat16* __restrict__ gl, int n) {
    int i = blockIdx.x * 256 + threadIdx.x;
    if (i < n) {
        float x = g[i];
        float v = (x / (1.0f + expf(-x))) * u[i];
        __nv_bfloat16 hb = __float2bfloat16(v);
        gh[i] = hb;
        gl[i] = __float2bfloat16(v - __bfloat162float(hb));
    }
}

// ---------------- final pooling + rmsnorm(lnf) ----------------
__global__ void pool_kernel(const float* __restrict__ h, const int* __restrict__ mask,
                            const float* __restrict__ lnf, float* __restrict__ pooled) {
    int b = blockIdx.x;
    int t = threadIdx.x;
    __shared__ float sh[256];
    int cnt = 0;
    for (int i = t; i < Sc; i += 256) cnt += mask[b * Sc + i];
    sh[t] = (float)cnt; __syncthreads();
    for (int o = 128; o; o >>= 1) { if (t < o) sh[t] += sh[t + o]; __syncthreads(); }
    int last = (int)sh[0] - 1;
    __syncthreads();
    const float* row = h + ((size_t)b * Sc + last) * Hc;
    float ss = 0.f;
    for (int i = t; i < Hc; i += 256) { float x = row[i]; ss += x * x; }
    sh[t] = ss; __syncthreads();
    for (int o = 128; o; o >>= 1) { if (t < o) sh[t] += sh[t + o]; __syncthreads(); }
    float sc = rsqrtf(sh[0] / (float)Hc + 1e-6f);
    for (int i = t; i < Hc; i += 256) pooled[b * Hc + i] = row[i] * sc * lnf[i];
}

// ---------------- classifier ----------------
__global__ void cls1_kernel(const float* __restrict__ pooled, const float* __restrict__ cw1,
                            const float* __restrict__ cb1, float* __restrict__ hid) {
    int n = blockIdx.x * 128 + threadIdx.x;
    int b = blockIdx.y;
    float acc = cb1[n];
    const float* p = pooled + (size_t)b * Hc;
    for (int k = 0; k < Hc; k++) acc += p[k] * cw1[(size_t)k * Hc + n];
    hid[(size_t)b * Hc + n] = fmaxf(acc, 0.f);
}

__global__ void cls2_kernel(const float* __restrict__ hid, const float* __restrict__ cw2,
                            const float* __restrict__ cb2, float* __restrict__ out) {
    int b = blockIdx.x >> 1, c = blockIdx.x & 1;
    float acc = 0.f;
    for (int k = threadIdx.x; k < Hc; k += 128) acc += hid[(size_t)b * Hc + k] * cw2[k * NCc + c];
    __shared__ float sh[128];
    sh[threadIdx.x] = acc; __syncthreads();
    for (int o = 64; o; o >>= 1) { if (threadIdx.x < o) sh[threadIdx.x] += sh[threadIdx.x + o]; __syncthreads(); }
    if (threadIdx.x == 0) out[b * NCc + c] = sh[0] + cb2[c];
}

// ---------------- host orchestration ----------------
extern "C" void kernel_launch(void* const* d_in, const int* in_sizes, int n_in,
                              void* d_out, int out_size) {
    (void)in_sizes; (void)n_in; (void)out_size;
    const int*   ids   = (const int*)d_in[0];
    const int*   mask  = (const int*)d_in[1];
    const float* embed = (const float*)d_in[2];
    const float* ln1   = (const float*)d_in[3];
    const float* wq    = (const float*)d_in[4];
    const float* bq    = (const float*)d_in[5];
    const float* wk    = (const float*)d_in[6];
    const float* bk    = (const float*)d_in[7];
    const float* wv    = (const float*)d_in[8];
    const float* bv    = (const float*)d_in[9];
    const float* wo    = (const float*)d_in[10];
    const float* laq   = (const float*)d_in[11];
    const float* lbq   = (const float*)d_in[12];
    const float* lak   = (const float*)d_in[13];
    const float* lbk   = (const float*)d_in[14];
    const float* lav   = (const float*)d_in[15];
    const float* lbv   = (const float*)d_in[16];
    const float* lao   = (const float*)d_in[17];
    const float* lbo   = (const float*)d_in[18];
    const float* ln2   = (const float*)d_in[19];
    const float* wg    = (const float*)d_in[20];
    const float* wu    = (const float*)d_in[21];
    const float* wd    = (const float*)d_in[22];
    const float* lnf   = (const float*)d_in[23];
    const float* cw1   = (const float*)d_in[24];
    const float* cb1   = (const float*)d_in[25];
    const float* cw2   = (const float*)d_in[26];
    const float* cb2   = (const float*)d_in[27];
    float* out = (float*)d_out;

    cudaFuncSetAttribute(gemm_bf16x3, cudaFuncAttributeMaxDynamicSharedMemorySize, GEMM_SMEM);
    cudaFuncSetAttribute(attn_scores_mma, cudaFuncAttributeMaxDynamicSharedMemorySize, GEMM_SMEM);
    cudaFuncSetAttribute(attn_ctx_mma, cudaFuncAttributeMaxDynamicSharedMemorySize, GEMM_SMEM);

    float *h, *q, *k, *v, *sc, *g, *u, *pooled, *cls, *rc, *rs;
    __nv_bfloat16 *xh, *xl, *qh, *ql, *kh, *kl, *vTh, *vTl, *ph, *pl, *ch, *cl, *gh, *gl, *whT, *wlT;
    cudaGetSymbolAddress((void**)&h,   d_h);
    cudaGetSymbolAddress((void**)&xh,  d_xh);
    cudaGetSymbolAddress((void**)&xl,  d_xl);
    cudaGetSymbolAddress((void**)&q,   d_q);
    cudaGetSymbolAddress((void**)&k,   d_k);
    cudaGetSymbolAddress((void**)&v,   d_v);
    cudaGetSymbolAddress((void**)&qh,  d_qh);
    cudaGetSymbolAddress((void**)&ql,  d_ql);
    cudaGetSymbolAddress((void**)&kh,  d_kh);
    cudaGetSymbolAddress((void**)&kl,  d_kl);
    cudaGetSymbolAddress((void**)&vTh, d_vTh);
    cudaGetSymbolAddress((void**)&vTl, d_vTl);
    cudaGetSymbolAddress((void**)&rc,  d_ropec);
    cudaGetSymbolAddress((void**)&rs,  d_ropes);
    cudaGetSymbolAddress((void**)&sc,  d_sc);
    cudaGetSymbolAddress((void**)&ph,  d_ph);
    cudaGetSymbolAddress((void**)&pl,  d_pl);
    cudaGetSymbolAddress((void**)&ch,  d_ch);
    cudaGetSymbolAddress((void**)&cl,  d_cl);
    cudaGetSymbolAddress((void**)&g,   d_g);
    cudaGetSymbolAddress((void**)&u,   d_u);
    cudaGetSymbolAddress((void**)&gh,  d_gh);
    cudaGetSymbolAddress((void**)&gl,  d_gl);
    cudaGetSymbolAddress((void**)&pooled, d_pooled);
    cudaGetSymbolAddress((void**)&cls,    d_cls);
    cudaGetSymbolAddress((void**)&whT,    d_whT);
    cudaGetSymbolAddress((void**)&wlT,    d_wlT);

    // preprocessing (rope_table launched later so gemm_bf16x3 is the 4th launch -> ncu target)
    wsplit_all_kernel<<<Lc * TILES_PER_LAYER, dim3(32, 8)>>>(
        wq, wk, wv, wo, wg, wu, wd,
        laq, lbq, lak, lbk, lav, lbv, lao, lbo, whT, wlT);
    embed_kernel<<<MTc, 256>>>(ids, embed, h);

    for (int l = 0; l < Lc; l++) {
        size_t lw = (size_t)l * LAYER_W;
        const float* LN1 = ln1 + (size_t)l * Hc;
        const float* BQ = bq + (size_t)l * QNc;
        const float* BK = bk + (size_t)l * KNc;
        const float* BV = bv + (size_t)l * KNc;
        const float* LN2 = ln2 + (size_t)l * Hc;

        rmsnorm_kernel<<<MTc, 256>>>(h, LN1, xh, xl);

        gemm_bf16x3<<<dim3(QNc / 128, MTc / 128, 1), 256, GEMM_SMEM>>>(
            xh, xl,
            whT + lw + WOFF_Q, wlT + lw + WOFF_Q, BQ, nullptr, q,
            nullptr, nullptr, nullptr, nullptr, nullptr,
            MTc, QNc, Hc);
        gemm_bf16x3<<<dim3(KNc / 128, MTc / 128, 2), 256, GEMM_SMEM>>>(
            xh, xl,
            whT + lw + WOFF_K, wlT + lw + WOFF_K, BK, nullptr, k,
            whT + lw + WOFF_V, wlT + lw + WOFF_V, BV, nullptr, v,
            MTc, KNc, Hc);

        if (l == 0) rope_table_kernel<<<Sc, 64>>>(rc, rs);

        rope_split2_kernel<<<dim3(MTc, NHc + NKVc), 64>>>(q, k, rc, rs, qh, ql, kh, kl);
        vsplitT_kernel<<<dim3(16, 16, Bc), dim3(32, 8)>>>(v, vTh, vTl);

        attn_scores_mma<<<dim3(4, 4, Bc * NHc), 256, GEMM_SMEM>>>(qh, ql, kh, kl, sc);
        softmax_kernel<<<Bc * NHc * Sc, 128>>>(sc, mask, ph, pl);
        attn_ctx_mma<<<dim3(1, 4, Bc * NHc), 256, GEMM_SMEM>>>(ph, pl, vTh, vTl, ch, cl);

        gemm_bf16x3<<<dim3(Hc / 128, MTc / 128, 1), 256, GEMM_SMEM>>>(
            ch, cl,
            whT + lw + WOFF_O, wlT + lw + WOFF_O, nullptr, h, h,
            nullptr, nullptr, nullptr, nullptr, nullptr,
            MTc, Hc, QNc);

        rmsnorm_kernel<<<MTc, 256>>>(h, LN2, xh, xl);
        gemm_bf16x3<<<dim3(Fc / 128, MTc / 128, 2), 256, GEMM_SMEM>>>(
            xh, xl,
            whT + lw + WOFF_G, wlT + lw + WOFF_G, nullptr, nullptr, g,
            whT + lw + WOFF_U, wlT + lw + WOFF_U, nullptr, nullptr, u,
            MTc, Fc, Hc);
        silu_mul_kernel<<<(MTc * Fc) / 256, 256>>>(g, u, gh, gl, MTc * Fc);
        gemm_bf16x3<<<dim3(Hc / 128, MTc / 128, 1), 256, GEMM_SMEM>>>(
            gh, gl,
            whT + lw + WOFF_D, wlT + lw + WOFF_D, nullptr, h, h,
            nullptr, nullptr, nullptr, nullptr, nullptr,
            MTc, Hc, Fc);
    }

    pool_kernel<<<Bc, 256>>>(h, mask, lnf, pooled);
    cls1_kernel<<<dim3(Hc / 128, Bc), 128>>>(pooled, cw1, cb1, cls);
    cls2_kernel<<<Bc * NCc, 128>>>(cls, cw2, cb2, out);
}

// round 13
// speedup vs baseline: 1.1610x; 1.0043x over previous
#include <cuda_runtime.h>
#include <cuda_bf16.h>
#include <cstddef>
#include <cstdint>
#include <math.h>

// ---------------- problem constants ----------------
#define Lc   4
#define Hc   2048
#define NHc  16
#define NKVc 4
#define DHc  128
#define Fc   5632
#define Rc   16
#define Bc   4
#define Sc   512
#define NCc  2
#define MTc  (Bc * Sc)          // 2048 tokens
#define QNc  (NHc * DHc)        // 2048
#define KNc  (NKVc * DHc)       // 512
#define LORA_SCALE 2.0f
#define INV_SQRT_DH 0.08838834764831845f

// per-layer transposed weight buffer offsets (elements)
#define WOFF_Q 0
#define WOFF_K (WOFF_Q + Hc * QNc)
#define WOFF_V (WOFF_K + Hc * KNc)
#define WOFF_O (WOFF_V + Hc * KNc)
#define WOFF_G (WOFF_O + QNc * Hc)
#define WOFF_U (WOFF_G + Hc * Fc)
#define WOFF_D (WOFF_U + Hc * Fc)
#define LAYER_W (WOFF_D + Fc * Hc)   // 45,088,768

// ---------------- scratch (static device memory; allocation-free) ----------------
__device__ float          d_h[MTc * Hc];
__device__ __nv_bfloat16  d_xh[MTc * Hc];
__device__ __nv_bfloat16  d_xl[MTc * Hc];
__device__ float          d_q[MTc * QNc];
__device__ float          d_k[MTc * KNc];
__device__ float          d_v[MTc * KNc];
__device__ __nv_bfloat16  d_qh[MTc * QNc];
__device__ __nv_bfloat16  d_ql[MTc * QNc];
__device__ __nv_bfloat16  d_kh[MTc * KNc];
__device__ __nv_bfloat16  d_kl[MTc * KNc];
__device__ __nv_bfloat16  d_vTh[Bc * KNc * Sc];
__device__ __nv_bfloat16  d_vTl[Bc * KNc * Sc];
__device__ float          d_ropec[Sc * 64];
__device__ float          d_ropes[Sc * 64];
__device__ float          d_sc[Bc * NHc * Sc * Sc];
__device__ __nv_bfloat16  d_ph[Bc * NHc * Sc * Sc];
__device__ __nv_bfloat16  d_pl[Bc * NHc * Sc * Sc];
__device__ __nv_bfloat16  d_ch[MTc * QNc];
__device__ __nv_bfloat16  d_cl[MTc * QNc];
__device__ float          d_g[MTc * Fc];
__device__ float          d_u[MTc * Fc];
__device__ __nv_bfloat16  d_gh[MTc * Fc];
__device__ __nv_bfloat16  d_gl[MTc * Fc];
__device__ float          d_pooled[Bc * Hc];
__device__ float          d_cls[Bc * Hc];
__device__ __nv_bfloat16  d_whT[(size_t)Lc * LAYER_W];  // hi weights (lora folded), [N,K]
__device__ __nv_bfloat16  d_wlT[(size_t)Lc * LAYER_W];  // lo weights, [N,K]

// ---------------- PTX helpers ----------------
__device__ __forceinline__ uint32_t sptr(const void* p) {
    return (uint32_t)__cvta_generic_to_shared(p);
}
#define CP_ASYNC16(dst, src) asm volatile("cp.async.cg.shared.global [%0], [%1], 16;\n" :: "r"(dst), "l"(src))
#define CP_COMMIT()          asm volatile("cp.async.commit_group;\n" ::: "memory")
#define CP_WAIT(n)           asm volatile("cp.async.wait_group %0;\n" :: "n"(n) : "memory")

__device__ __forceinline__ void mma_bf16(float* c, const uint32_t* a, const uint32_t* b) {
    asm volatile(
        "mma.sync.aligned.m16n8k16.row.col.f32.bf16.bf16.f32 "
        "{%0,%1,%2,%3}, {%4,%5,%6,%7}, {%8,%9}, {%0,%1,%2,%3};\n"
        : "+f"(c[0]), "+f"(c[1]), "+f"(c[2]), "+f"(c[3])
        : "r"(a[0]), "r"(a[1]), "r"(a[2]), "r"(a[3]), "r"(b[0]), "r"(b[1]));
}

__device__ __forceinline__ void ldsm4(uint32_t* r, uint32_t addr) {
    asm volatile("ldmatrix.sync.aligned.m8n8.x4.shared.b16 {%0,%1,%2,%3}, [%4];"
        : "=r"(r[0]), "=r"(r[1]), "=r"(r[2]), "=r"(r[3]) : "r"(addr));
}

// ---------------- ALL weights: transpose + LoRA fold + bf16 split, ONE launch ----------------
#define TILES_PER_LAYER 22016
__global__ void wsplit_all_kernel(const float* __restrict__ wq, const float* __restrict__ wk,
                                  const float* __restrict__ wv, const float* __restrict__ wo,
                                  const float* __restrict__ wg, const float* __restrict__ wu,
                                  const float* __restrict__ wd,
                                  const float* __restrict__ laq, const float* __restrict__ lbq,
                                  const float* __restrict__ lak, const float* __restrict__ lbk,
                                  const float* __restrict__ lav, const float* __restrict__ lbv,
                                  const float* __restrict__ lao, const float* __restrict__ lbo,
                                  __nv_bfloat16* __restrict__ hiT,
                                  __nv_bfloat16* __restrict__ loT) {
    int l = blockIdx.x / TILES_PER_LAYER;
    int r = blockIdx.x % TILES_PER_LAYER;
    const float* src; size_t woff; int K, N, tidx;
    const float* loA = nullptr; const float* loB = nullptr;
    if (r < 2048)       { src = wq + (size_t)l * Hc * QNc; woff = WOFF_Q; K = Hc;  N = QNc; tidx = r;
                          loA = laq + (size_t)l * Rc * Hc;  loB = lbq + (size_t)l * QNc * Rc; }
    else if (r < 2560)  { src = wk + (size_t)l * Hc * KNc; woff = WOFF_K; K = Hc;  N = KNc; tidx = r - 2048;
                          loA = lak + (size_t)l * Rc * Hc;  loB = lbk + (size_t)l * KNc * Rc; }
    else if (r < 3072)  { src = wv + (size_t)l * Hc * KNc; woff = WOFF_V; K = Hc;  N = KNc; tidx = r - 2560;
                          loA = lav + (size_t)l * Rc * Hc;  loB = lbv + (size_t)l * KNc * Rc; }
    else if (r < 5120)  { src = wo + (size_t)l * QNc * Hc; woff = WOFF_O; K = QNc; N = Hc;  tidx = r - 3072;
                          loA = lao + (size_t)l * Rc * QNc; loB = lbo + (size_t)l * Hc * Rc; }
    else if (r < 10752) { src = wg + (size_t)l * Hc * Fc;  woff = WOFF_G; K = Hc;  N = Fc;  tidx = r - 5120; }
    else if (r < 16384) { src = wu + (size_t)l * Hc * Fc;  woff = WOFF_U; K = Hc;  N = Fc;  tidx = r - 10752; }
    else                { src = wd + (size_t)l * Fc * Hc;  woff = WOFF_D; K = Fc;  N = Hc;  tidx = r - 16384; }
    woff += (size_t)l * LAYER_W;
    int nt = N / 32;
    int k0 = (tidx / nt) * 64, n0 = (tidx % nt) * 32;

    __shared__ float tile[64][33];   // [k][n]
    __shared__ float sA[16][64];     // lora A[r][k-local]
    __shared__ float sB[32][17];     // lora B[n-local][r]
    int tx = threadIdx.x, ty = threadIdx.y;   // (32, 8)
    int tid = ty * 32 + tx;
    for (int i = ty; i < 64; i += 8)
        tile[i][tx] = src[(size_t)(k0 + i) * N + n0 + tx];
    if (loA) {
        for (int idx = tid; idx < 1024; idx += 256) {
            int rr = idx >> 6, kk = idx & 63;
            sA[rr][kk] = loA[(size_t)rr * K + k0 + kk];
        }
        for (int idx = tid; idx < 512; idx += 256) {
            int nn = idx >> 4, rr = idx & 15;
            sB[nn][rr] = loB[(size_t)(n0 + nn) * Rc + rr];
        }
    }
    __syncthreads();
    for (int i = ty; i < 32; i += 8) {
        float v0 = tile[2 * tx][i], v1 = tile[2 * tx + 1][i];
        if (loA) {
            float d0 = 0.f, d1 = 0.f;
            #pragma unroll
            for (int rr = 0; rr < Rc; rr++) {
                float bb = sB[i][rr];
                d0 += sA[rr][2 * tx] * bb;
                d1 += sA[rr][2 * tx + 1] * bb;
            }
            v0 += LORA_SCALE * d0;
            v1 += LORA_SCALE * d1;
        }
        __nv_bfloat16 h0 = __float2bfloat16(v0), h1 = __float2bfloat16(v1);
        __nv_bfloat162 hv; hv.x = h0; hv.y = h1;
        __nv_bfloat162 lv;
        lv.x = __float2bfloat16(v0 - __bfloat162float(h0));
        lv.y = __float2bfloat16(v1 - __bfloat162float(h1));
        size_t idx = woff + (size_t)(n0 + i) * K + k0 + 2 * tx;
        *(__nv_bfloat162*)(hiT + idx) = hv;
        *(__nv_bfloat162*)(loT + idx) = lv;
    }
}

// ---------------- RoPE table precompute ----------------
__global__ void rope_table_kernel(float* __restrict__ rc, float* __restrict__ rs) {
    int s = blockIdx.x;
    int d = threadIdx.x;
    float freq = powf(1000000.0f, -(float)d / 64.0f);
    float ang = (float)s * freq;
    float sn, cs;
    sincosf(ang, &sn, &cs);
    rc[s * 64 + d] = cs;
    rs[s * 64 + d] = sn;
}

// ---------------- embedding gather ----------------
__global__ void embed_kernel(const int* __restrict__ ids,
                             const float* __restrict__ emb,
                             float* __restrict__ h) {
    int row = blockIdx.x;
    const float* src = emb + (size_t)ids[row] * Hc;
    float* dst = h + (size_t)row * Hc;
    for (int i = threadIdx.x; i < Hc; i += 256) dst[i] = src[i];
}

// ---------------- rmsnorm: bf16 hi/lo split only ----------------
__global__ void rmsnorm_kernel(const float* __restrict__ in,
                               const float* __restrict__ w,
                               __nv_bfloat16* __restrict__ oh,
                               __nv_bfloat16* __restrict__ ol) {
    int row = blockIdx.x;
    const float* x = in + (size_t)row * Hc;
    float ss = 0.f;
    for (int i = threadIdx.x; i < Hc; i += 256) { float v = x[i]; ss += v * v; }
    __shared__ float sh[256];
    sh[threadIdx.x] = ss; __syncthreads();
    for (int o = 128; o; o >>= 1) { if (threadIdx.x < o) sh[threadIdx.x] += sh[threadIdx.x + o]; __syncthreads(); }
    float sc = rsqrtf(sh[0] / (float)Hc + 1e-6f);
    for (int i = threadIdx.x; i < Hc; i += 256) {
        float v = x[i] * sc * w[i];
        __nv_bfloat16 hb = __float2bfloat16(v);
        oh[(size_t)row * Hc + i] = hb;
        ol[(size_t)row * Hc + i] = __float2bfloat16(v - __bfloat162float(hb));
    }
}

// ================= shared GEMM mainloop (macro-free inline function) =================
#define TILE_B 8192                  // 128 * 64B
#define STAGE_B (4 * TILE_B)         // Ah, Al, Bh, Bl = 32KB
#define NSTAGE 3
#define GEMM_SMEM (NSTAGE * STAGE_B) // 96KB

struct GemmCtx {
    const __nv_bfloat16 *pAh, *pAl, *pBh, *pBl;
    uint32_t sb, srow;
    int lg0, lswz;
    int m0, n0, lrow16, lch, lsw;
};

__device__ __forceinline__ void gemm_mainloop(GemmCtx& cx, float acc[2][8][4], int K) {
    auto loadStage = [&](int st, int k0) {
        uint32_t d = cx.srow + st * STAGE_B;
        #pragma unroll
        for (int i = 0; i < 2; i++) {
            int g = cx.lg0 + i;
            uint32_t off = (uint32_t)(g ^ cx.lswz) << 4;
            CP_ASYNC16(d + 0 * TILE_B + off, cx.pAh + k0 + g * 8);
            CP_ASYNC16(d + 1 * TILE_B + off, cx.pAl + k0 + g * 8);
            CP_ASYNC16(d + 2 * TILE_B + off, cx.pBh + k0 + g * 8);
            CP_ASYNC16(d + 3 * TILE_B + off, cx.pBl + k0 + g * 8);
        }
        CP_COMMIT();
    };
    const int KT = K >> 5;
    loadStage(0, 0);
    if (KT > 1) loadStage(1, 32);

    for (int kt = 0; kt < KT; kt++) {
        const int st = kt % NSTAGE;
        if (kt + 1 < KT) { CP_WAIT(1); } else { CP_WAIT(0); }
        __syncthreads();
        if (kt + 2 < KT) loadStage((kt + 2) % NSTAGE, (kt + 2) << 5);

        const uint32_t tAh = cx.sb + st * STAGE_B;
        const uint32_t tAl = tAh + TILE_B;
        const uint32_t tBh = tAh + 2 * TILE_B;
        const uint32_t tBl = tAh + 3 * TILE_B;

        #pragma unroll
        for (int ks = 0; ks < 2; ks++) {
            const uint32_t choff = (uint32_t)(((ks * 2 + cx.lch) ^ cx.lsw)) << 4;
            uint32_t ra0 = (uint32_t)(cx.m0 + cx.lrow16) * 64 + choff;
            uint32_t ra1 = (uint32_t)(cx.m0 + 16 + cx.lrow16) * 64 + choff;
            uint32_t rb0 = (uint32_t)(cx.n0 + cx.lrow16) * 64 + choff;

            uint32_t afH[2][4], afL[2][4], bf[8][2];
            #pragma unroll
            for (int np = 0; np < 4; np++) {
                uint32_t q[4];
                ldsm4(q, tBh + rb0 + (uint32_t)(np * 16 * 64));
                bf[2 * np][0] = q[0]; bf[2 * np + 1][0] = q[1];
                bf[2 * np][1] = q[2]; bf[2 * np + 1][1] = q[3];
            }
            ldsm4(afH[0], tAh + ra0);
            ldsm4(afH[1], tAh + ra1);
            #pragma unroll
            for (int mt = 0; mt < 2; mt++)
                #pragma unroll
                for (int nt = 0; nt < 8; nt++)
                    mma_bf16(acc[mt][nt], afH[mt], bf[nt]);
            ldsm4(afL[0], tAl + ra0);
            ldsm4(afL[1], tAl + ra1);
            #pragma unroll
            for (int mt = 0; mt < 2; mt++)
                #pragma unroll
                for (int nt = 0; nt < 8; nt++)
                    mma_bf16(acc[mt][nt], afL[mt], bf[nt]);
            #pragma unroll
            for (int np = 0; np < 4; np++) {
                uint32_t q[4];
                ldsm4(q, tBl + rb0 + (uint32_t)(np * 16 * 64));
                bf[2 * np][0] = q[0]; bf[2 * np + 1][0] = q[1];
                bf[2 * np][1] = q[2]; bf[2 * np + 1][1] = q[3];
            }
            #pragma unroll
            for (int mt = 0; mt < 2; mt++)
                #pragma unroll
                for (int nt = 0; nt < 8; nt++)
                    mma_bf16(acc[mt][nt], afH[mt], bf[nt]);
        }
    }
}

__device__ __forceinline__ void gemm_setup(GemmCtx& cx, uint8_t* smraw, int tid,
                                           const __nv_bfloat16* Ahi, const __nv_bfloat16* Alo,
                                           const __nv_bfloat16* Bhi, const __nv_bfloat16* Blo,
                                           int bm, int bn, int K) {
    const int warpId = tid >> 5, lane = tid & 31;
    cx.m0 = (warpId & 3) * 32;
    cx.n0 = (warpId >> 2) * 64;
    cx.lrow16 = lane & 15;
    cx.lch = lane >> 4;
    cx.lsw = (cx.lrow16 >> 1) & 3;
    cx.sb = sptr(smraw);
    int lrow = tid >> 1;
    cx.lg0 = (tid & 1) * 2;
    cx.lswz = (lrow >> 1) & 3;
    cx.pAh = Ahi + (size_t)(bm + lrow) * K;
    cx.pAl = Alo + (size_t)(bm + lrow) * K;
    cx.pBh = Bhi + (size_t)(bn + lrow) * K;
    cx.pBl = Blo + (size_t)(bn + lrow) * K;
    cx.srow = cx.sb + lrow * 64;
}

// ---------------- fused QKV GEMM: 24 N-tiles (16 Q + 4 K + 4 V) x 16 M-tiles ----------------
__global__ __launch_bounds__(256, 2) void gemm_qkv(
    const __nv_bfloat16* __restrict__ Ahi, const __nv_bfloat16* __restrict__ Alo,
    const __nv_bfloat16* __restrict__ WQh, const __nv_bfloat16* __restrict__ WQl,
    const __nv_bfloat16* __restrict__ WKh, const __nv_bfloat16* __restrict__ WKl,
    const __nv_bfloat16* __restrict__ WVh, const __nv_bfloat16* __restrict__ WVl,
    const float* __restrict__ BQ, const float* __restrict__ BK, const float* __restrict__ BV,
    float* __restrict__ q, float* __restrict__ k, float* __restrict__ v) {
    extern __shared__ uint8_t smraw[];
    const int tid = threadIdx.x;
    const int bx = blockIdx.x;
    const int bm = blockIdx.y * 128;

    const __nv_bfloat16 *Bhi, *Blo;
    const float* bias;
    float* C;
    int N, ntile;
    if (bx < 16)      { Bhi = WQh; Blo = WQl; bias = BQ; C = q; N = QNc; ntile = bx; }
    else if (bx < 20) { Bhi = WKh; Blo = WKl; bias = BK; C = k; N = KNc; ntile = bx - 16; }
    else              { Bhi = WVh; Blo = WVl; bias = BV; C = v; N = KNc; ntile = bx - 20; }
    const int bn = ntile * 128;

    float acc[2][8][4];
    #pragma unroll
    for (int mt = 0; mt < 2; mt++)
        #pragma unroll
        for (int nt = 0; nt < 8; nt++)
            #pragma unroll
            for (int r = 0; r < 4; r++) acc[mt][nt][r] = 0.f;

    GemmCtx cx;
    gemm_setup(cx, smraw, tid, Ahi, Alo, Bhi, Blo, bm, bn, Hc);
    gemm_mainloop(cx, acc, Hc);

    const int lane = tid & 31;
    const int grp = lane >> 2, qd = lane & 3;
    #pragma unroll
    for (int mt = 0; mt < 2; mt++) {
        int row0 = bm + cx.m0 + mt * 16 + grp;
        int row1 = row0 + 8;
        #pragma unroll
        for (int nt = 0; nt < 8; nt++) {
            int lc0 = cx.n0 + nt * 8 + 2 * qd;
            int col0 = bn + lc0, col1 = col0 + 1;
            float b0 = bias[col0], b1 = bias[col1];
            *(float2*)(C + (size_t)row0 * N + col0) =
                make_float2(acc[mt][nt][0] + b0, acc[mt][nt][1] + b1);
            *(float2*)(C + (size_t)row1 * N + col0) =
                make_float2(acc[mt][nt][2] + b0, acc[mt][nt][3] + b1);
        }
    }
}

// ---------------- generic bf16x3 GEMM (O / G+U / D) ----------------
__global__ __launch_bounds__(256, 2) void gemm_bf16x3(
    const __nv_bfloat16* __restrict__ Ahi, const __nv_bfloat16* __restrict__ Alo,
    const __nv_bfloat16* __restrict__ Bhi1, const __nv_bfloat16* __restrict__ Blo1,
    const float* __restrict__ resid1, float* __restrict__ C1,
    const __nv_bfloat16* __restrict__ Bhi2, const __nv_bfloat16* __restrict__ Blo2,
    const float* __restrict__ resid2, float* __restrict__ C2,
    int M, int N, int K) {
    extern __shared__ uint8_t smraw[];
    const int tid = threadIdx.x;
    const int bm = blockIdx.y * 128, bn = blockIdx.x * 128;

    const __nv_bfloat16* Bhi = Bhi1; const __nv_bfloat16* Blo = Blo1;
    const float* resid = resid1;
    float* C = C1;
    if (blockIdx.z == 1) { Bhi = Bhi2; Blo = Blo2; resid = resid2; C = C2; }

    float acc[2][8][4];
    #pragma unroll
    for (int mt = 0; mt < 2; mt++)
        #pragma unroll
        for (int nt = 0; nt < 8; nt++)
            #pragma unroll
            for (int r = 0; r < 4; r++) acc[mt][nt][r] = 0.f;

    GemmCtx cx;
    gemm_setup(cx, smraw, tid, Ahi, Alo, Bhi, Blo, bm, bn, K);
    gemm_mainloop(cx, acc, K);

    const int lane = tid & 31;
    const int grp = lane >> 2, qd = lane & 3;
    #pragma unroll
    for (int mt = 0; mt < 2; mt++) {
        int row0 = bm + cx.m0 + mt * 16 + grp;
        int row1 = row0 + 8;
        #pragma unroll
        for (int nt = 0; nt < 8; nt++) {
            int lc0 = cx.n0 + nt * 8 + 2 * qd;
            int col0 = bn + lc0, col1 = col0 + 1;
            float o00 = acc[mt][nt][0], o01 = acc[mt][nt][1];
            float o10 = acc[mt][nt][2], o11 = acc[mt][nt][3];
            if (resid) {
                o00 += resid[(size_t)row0 * N + col0];
                o01 += resid[(size_t)row0 * N + col1];
                o10 += resid[(size_t)row1 * N + col0];
                o11 += resid[(size_t)row1 * N + col1];
            }
            *(float2*)(C + (size_t)row0 * N + col0) = make_float2(o00, o01);
            *(float2*)(C + (size_t)row1 * N + col0) = make_float2(o10, o11);
        }
    }
}

// ---------------- attention scores on tensor cores: S = Qs * K^T (bf16x3) ----------------
__global__ __launch_bounds__(256, 2) void attn_scores_mma(
    const __nv_bfloat16* __restrict__ qh, const __nv_bfloat16* __restrict__ ql,
    const __nv_bfloat16* __restrict__ kh, const __nv_bfloat16* __restrict__ kl,
    float* __restrict__ scores) {
    if (blockIdx.x > blockIdx.y) return;
    extern __shared__ uint8_t smraw[];
    const int tid = threadIdx.x;
    const int bh = blockIdx.z;
    const int b = bh >> 4, hd = bh & 15, kvh = hd >> 2;
    const int bm = blockIdx.y * 128, bn = blockIdx.x * 128;
    float* C = scores + (size_t)bh * Sc * Sc;

    float acc[2][8][4];
    #pragma unroll
    for (int mt = 0; mt < 2; mt++)
        #pragma unroll
        for (int nt = 0; nt < 8; nt++)
            #pragma unroll
            for (int r = 0; r < 4; r++) acc[mt][nt][r] = 0.f;

    // A rows stride QNc, B rows stride KNc: use custom setup
    GemmCtx cx;
    {
        const int warpId = tid >> 5, lane = tid & 31;
        cx.m0 = (warpId & 3) * 32;
        cx.n0 = (warpId >> 2) * 64;
        cx.lrow16 = lane & 15;
        cx.lch = lane >> 4;
        cx.lsw = (cx.lrow16 >> 1) & 3;
        cx.sb = sptr(smraw);
        int lrow = tid >> 1;
        cx.lg0 = (tid & 1) * 2;
        cx.lswz = (lrow >> 1) & 3;
        cx.pAh = qh + (size_t)b * Sc * QNc + (size_t)hd * DHc + (size_t)(bm + lrow) * QNc;
        cx.pAl = ql + (size_t)b * Sc * QNc + (size_t)hd * DHc + (size_t)(bm + lrow) * QNc;
        cx.pBh = kh + (size_t)b * Sc * KNc + (size_t)kvh * DHc + (size_t)(bn + lrow) * KNc;
        cx.pBl = kl + (size_t)b * Sc * KNc + (size_t)kvh * DHc + (size_t)(bn + lrow) * KNc;
        cx.srow = cx.sb + lrow * 64;
    }
    gemm_mainloop(cx, acc, DHc);

    const int lane = tid & 31;
    const int grp = lane >> 2, qd = lane & 3;
    #pragma unroll
    for (int mt = 0; mt < 2; mt++) {
        int row0 = bm + cx.m0 + mt * 16 + grp;
        int row1 = row0 + 8;
        #pragma unroll
        for (int nt = 0; nt < 8; nt++) {
            int col = bn + cx.n0 + nt * 8 + 2 * qd;
            *(float2*)(C + (size_t)row0 * Sc + col) = make_float2(acc[mt][nt][0], acc[mt][nt][1]);
            *(float2*)(C + (size_t)row1 * Sc + col) = make_float2(acc[mt][nt][2], acc[mt][nt][3]);
        }
    }
}

// ---------------- attention context on tensor cores: ctx = P * V (bf16x3) ----------------
__global__ __launch_bounds__(256, 2) void attn_ctx_mma(
    const __nv_bfloat16* __restrict__ ph, const __nv_bfloat16* __restrict__ pl,
    const __nv_bfloat16* __restrict__ vTh, const __nv_bfloat16* __restrict__ vTl,
    __nv_bfloat16* __restrict__ ch, __nv_bfloat16* __restrict__ cl) {
    extern __shared__ uint8_t smraw[];
    const int tid = threadIdx.x;
    const int bh = blockIdx.z;
    const int b = bh >> 4, hd = bh & 15, kvh = hd >> 2;
    const int bm = blockIdx.y * 128;

    float acc[2][8][4];
    #pragma unroll
    for (int mt = 0; mt < 2; mt++)
        #pragma unroll
        for (int nt = 0; nt < 8; nt++)
            #pragma unroll
            for (int r = 0; r < 4; r++) acc[mt][nt][r] = 0.f;

    GemmCtx cx;
    {
        const int warpId = tid >> 5, lane = tid & 31;
        cx.m0 = (warpId & 3) * 32;
        cx.n0 = (warpId >> 2) * 64;
        cx.lrow16 = lane & 15;
        cx.lch = lane >> 4;
        cx.lsw = (cx.lrow16 >> 1) & 3;
        cx.sb = sptr(smraw);
        int lrow = tid >> 1;
        cx.lg0 = (tid & 1) * 2;
        cx.lswz = (lrow >> 1) & 3;
        cx.pAh = ph + (size_t)bh * Sc * Sc + (size_t)(bm + lrow) * Sc;
        cx.pAl = pl + (size_t)bh * Sc * Sc + (size_t)(bm + lrow) * Sc;
        cx.pBh = vTh + ((size_t)b * KNc + (size_t)kvh * DHc + lrow) * Sc;
        cx.pBl = vTl + ((size_t)b * KNc + (size_t)kvh * DHc + lrow) * Sc;
        cx.srow = cx.sb + lrow * 64;
    }
    gemm_mainloop(cx, acc, ((bm >> 5) + 4) << 5);   // causal truncation (exact)

    const int lane = tid & 31;
    const int grp = lane >> 2, qd = lane & 3;
    #pragma unroll
    for (int mt = 0; mt < 2; mt++) {
        int lr0 = cx.m0 + mt * 16 + grp;
        #pragma unroll
        for (int half = 0; half < 2; half++) {
            int row = bm + lr0 + half * 8;
            size_t base = ((size_t)(b * Sc + row)) * QNc + (size_t)hd * DHc;
            #pragma unroll
            for (int nt = 0; nt < 8; nt++) {
                int col = cx.n0 + nt * 8 + 2 * qd;
                float v0 = acc[mt][nt][half * 2 + 0];
                float v1 = acc[mt][nt][half * 2 + 1];
                __nv_bfloat16 h0 = __float2bfloat16(v0);
                __nv_bfloat16 h1 = __float2bfloat16(v1);
                __nv_bfloat162 hv; hv.x = h0; hv.y = h1;
                __nv_bfloat162 lv;
                lv.x = __float2bfloat16(v0 - __bfloat162float(h0));
                lv.y = __float2bfloat16(v1 - __bfloat162float(h1));
                *(__nv_bfloat162*)(ch + base + col) = hv;
                *(__nv_bfloat162*)(cl + base + col) = lv;
            }
        }
    }
}

// ---------------- RoPE (q+k fused), table-driven, + scale + bf16 hi/lo split ----------------
__global__ void rope_split2_kernel(const float* __restrict__ qb, const float* __restrict__ kb,
                                   const float* __restrict__ rc, const float* __restrict__ rs,
                                   __nv_bfloat16* __restrict__ qh, __nv_bfloat16* __restrict__ ql,
                                   __nv_bfloat16* __restrict__ kh, __nv_bfloat16* __restrict__ kl) {
    int token = blockIdx.x;
    int head  = blockIdx.y;       // 0..19: 0-15 = q, 16-19 = k
    int d = threadIdx.x;
    int s = token % Sc;
    const float* p;
    __nv_bfloat16 *oh, *ol;
    size_t idx;
    float scale;
    if (head < NHc) {
        p = qb + ((size_t)token * NHc + head) * DHc;
        idx = ((size_t)token * NHc + head) * DHc;
        oh = qh; ol = ql; scale = INV_SQRT_DH;
    } else {
        int h2 = head - NHc;
        p = kb + ((size_t)token * NKVc + h2) * DHc;
        idx = ((size_t)token * NKVc + h2) * DHc;
        oh = kh; ol = kl; scale = 1.0f;
    }
    float cs = rc[s * 64 + d];
    float sn = rs[s * 64 + d];
    float x1 = p[d], x2 = p[d + 64];
    float v0 = (x1 * cs - x2 * sn) * scale;
    float v1 = (x2 * cs + x1 * sn) * scale;
    __nv_bfloat16 h0 = __float2bfloat16(v0);
    __nv_bfloat16 h1 = __float2bfloat16(v1);
    oh[idx + d]      = h0;
    ol[idx + d]      = __float2bfloat16(v0 - __bfloat162float(h0));
    oh[idx + d + 64] = h1;
    ol[idx + d + 64] = __float2bfloat16(v1 - __bfloat162float(h1));
}

// ---------------- V transpose + split ----------------
__global__ void vsplitT_kernel(const float* __restrict__ v,
                               __nv_bfloat16* __restrict__ vTh,
                               __nv_bfloat16* __restrict__ vTl) {
    __shared__ float tile[32][33];
    int b = blockIdx.z;
    int t0 = blockIdx.x * 32, d0 = blockIdx.y * 32;
    int tx = threadIdx.x, ty = threadIdx.y;
    for (int i = ty; i < 32; i += 8)
        tile[i][tx] = v[(size_t)(b * Sc + t0 + i) * KNc + d0 + tx];
    __syncthreads();
    for (int i = ty; i < 32; i += 8) {
        float val = tile[tx][i];
        size_t idx = ((size_t)b * KNc + d0 + i) * Sc + t0 + tx;
        __nv_bfloat16 hb = __float2bfloat16(val);
        vTh[idx] = hb;
        vTl[idx] = __float2bfloat16(val - __bfloat162float(hb));
    }
}

// ---------------- masked softmax -> bf16 hi/lo P ----------------
__global__ void softmax_kernel(const float* __restrict__ scores, const int* __restrict__ mask,
                               __nv_bfloat16* __restrict__ ph, __nv_bfloat16* __restrict__ pl) {
    int row = blockIdx.x;
    int qpos = row % Sc;
    int b = row / (NHc * Sc);
    const float* r = scores + (size_t)row * Sc;
    int t = threadIdx.x;
    float v[4];
    float mx = -3.0e38f;
    #pragma unroll
    for (int i = 0; i < 4; i++) {
        int k = t + 128 * i;
        bool ok = (k <= qpos) && (mask[b * Sc + k] > 0);
        v[i] = ok ? r[k] : -1e30f;
        mx = fmaxf(mx, v[i]);
    }
    __shared__ float sh[128];
    sh[t] = mx; __syncthreads();
    for (int o = 64; o; o >>= 1) { if (t < o) sh[t] = fmaxf(sh[t], sh[t + o]); __syncthreads(); }
    mx = sh[0]; __syncthreads();
    float sm = 0.f;
    #pragma unroll
    for (int i = 0; i < 4; i++) { v[i] = expf(v[i] - mx); sm += v[i]; }
    sh[t] = sm; __syncthreads();
    for (int o = 64; o; o >>= 1) { if (t < o) sh[t] += sh[t + o]; __syncthreads(); }
    float inv = 1.0f / sh[0];
    #pragma unroll
    for (int i = 0; i < 4; i++) {
        float p = v[i] * inv;
        __nv_bfloat16 hb = __float2bfloat16(p);
        ph[(size_t)row * Sc + t + 128 * i] = hb;
        pl[(size_t)row * Sc + t + 128 * i] = __float2bfloat16(p - __bfloat162float(hb));
    }
}

// ---------------- silu(g)*u -> bf16 hi/lo ----------------
__global__ void silu_mul_kernel(const float* __restrict__ g, const float* __restrict__ u,
                                __nv_bfloat16* __restrict__ gh, __nv_bfloat16* __restrict__ gl, int n) {
    int i = blockIdx.x * 256 + threadIdx.x;
    if (i < n) {
        float x = g[i];
        float v = (x / (1.0f + expf(-x))) * u[i];
        __nv_bfloat16 hb = __float2bfloat16(v);
        gh[i] = hb;
        gl[i] = __float2bfloat16(v - __bfloat162float(hb));
    }
}

// ---------------- final pooling + rmsnorm(lnf) ----------------
__global__ void pool_kernel(const float* __restrict__ h, const int* __restrict__ mask,
                            const float* __restrict__ lnf, float* __restrict__ pooled) {
    int b = blockIdx.x;
    int t = threadIdx.x;
    __shared__ float sh[256];
    int cnt = 0;
    for (int i = t; i < Sc; i += 256) cnt += mask[b * Sc + i];
    sh[t] = (float)cnt; __syncthreads();
    for (int o = 128; o; o >>= 1) { if (t < o) sh[t] += sh[t + o]; __syncthreads(); }
    int last = (int)sh[0] - 1;
    __syncthreads();
    const float* row = h + ((size_t)b * Sc + last) * Hc;
    float ss = 0.f;
    for (int i = t; i < Hc; i += 256) { float x = row[i]; ss += x * x; }
    sh[t] = ss; __syncthreads();
    for (int o = 128; o; o >>= 1) { if (t < o) sh[t] += sh[t + o]; __syncthreads(); }
    float sc = rsqrtf(sh[0] / (float)Hc + 1e-6f);
    for (int i = t; i < Hc; i += 256) pooled[b * Hc + i] = row[i] * sc * lnf[i];
}

// ---------------- classifier ----------------
__global__ void cls1_kernel(const float* __restrict__ pooled, const float* __restrict__ cw1,
                            const float* __restrict__ cb1, float* __restrict__ hid) {
    int n = blockIdx.x * 128 + threadIdx.x;
    int b = blockIdx.y;
    float acc = cb1[n];
    const float* p = pooled + (size_t)b * Hc;
    for (int k = 0; k < Hc; k++) acc += p[k] * cw1[(size_t)k * Hc + n];
    hid[(size_t)b * Hc + n] = fmaxf(acc, 0.f);
}

__global__ void cls2_kernel(const float* __restrict__ hid, const float* __restrict__ cw2,
                            const float* __restrict__ cb2, float* __restrict__ out) {
    int b = blockIdx.x >> 1, c = blockIdx.x & 1;
    float acc = 0.f;
    for (int k = threadIdx.x; k < Hc; k += 128) acc += hid[(size_t)b * Hc + k] * cw2[k * NCc + c];
    __shared__ float sh[128];
    sh[threadIdx.x] = acc; __syncthreads();
    for (int o = 64; o; o >>= 1) { if (threadIdx.x < o) sh[threadIdx.x] += sh[threadIdx.x + o]; __syncthreads(); }
    if (threadIdx.x == 0) out[b * NCc + c] = sh[0] + cb2[c];
}

// ---------------- host orchestration ----------------
extern "C" void kernel_launch(void* const* d_in, const int* in_sizes, int n_in,
                              void* d_out, int out_size) {
    (void)in_sizes; (void)n_in; (void)out_size;
    const int*   ids   = (const int*)d_in[0];
    const int*   mask  = (const int*)d_in[1];
    const float* embed = (const float*)d_in[2];
    const float* ln1   = (const float*)d_in[3];
    const float* wq    = (const float*)d_in[4];
    const float* bq    = (const float*)d_in[5];
    const float* wk    = (const float*)d_in[6];
    const float* bk    = (const float*)d_in[7];
    const float* wv    = (const float*)d_in[8];
    const float* bv    = (const float*)d_in[9];
    const float* wo    = (const float*)d_in[10];
    const float* laq   = (const float*)d_in[11];
    const float* lbq   = (const float*)d_in[12];
    const float* lak   = (const float*)d_in[13];
    const float* lbk   = (const float*)d_in[14];
    const float* lav   = (const float*)d_in[15];
    const float* lbv   = (const float*)d_in[16];
    const float* lao   = (const float*)d_in[17];
    const float* lbo   = (const float*)d_in[18];
    const float* ln2   = (const float*)d_in[19];
    const float* wg    = (const float*)d_in[20];
    const float* wu    = (const float*)d_in[21];
    const float* wd    = (const float*)d_in[22];
    const float* lnf   = (const float*)d_in[23];
    const float* cw1   = (const float*)d_in[24];
    const float* cb1   = (const float*)d_in[25];
    const float* cw2   = (const float*)d_in[26];
    const float* cb2   = (const float*)d_in[27];
    float* out = (float*)d_out;

    cudaFuncSetAttribute(gemm_qkv, cudaFuncAttributeMaxDynamicSharedMemorySize, GEMM_SMEM);
    cudaFuncSetAttribute(gemm_bf16x3, cudaFuncAttributeMaxDynamicSharedMemorySize, GEMM_SMEM);
    cudaFuncSetAttribute(attn_scores_mma, cudaFuncAttributeMaxDynamicSharedMemorySize, GEMM_SMEM);
    cudaFuncSetAttribute(attn_ctx_mma, cudaFuncAttributeMaxDynamicSharedMemorySize, GEMM_SMEM);

    float *h, *q, *k, *v, *sc, *g, *u, *pooled, *cls, *rc, *rs;
    __nv_bfloat16 *xh, *xl, *qh, *ql, *kh, *kl, *vTh, *vTl, *ph, *pl, *ch, *cl, *gh, *gl, *whT, *wlT;
    cudaGetSymbolAddress((void**)&h,   d_h);
    cudaGetSymbolAddress((void**)&xh,  d_xh);
    cudaGetSymbolAddress((void**)&xl,  d_xl);
    cudaGetSymbolAddress((void**)&q,   d_q);
    cudaGetSymbolAddress((void**)&k,   d_k);
    cudaGetSymbolAddress((void**)&v,   d_v);
    cudaGetSymbolAddress((void**)&qh,  d_qh);
    cudaGetSymbolAddress((void**)&ql,  d_ql);
    cudaGetSymbolAddress((void**)&kh,  d_kh);
    cudaGetSymbolAddress((void**)&kl,  d_kl);
    cudaGetSymbolAddress((void**)&vTh, d_vTh);
    cudaGetSymbolAddress((void**)&vTl, d_vTl);
    cudaGetSymbolAddress((void**)&rc,  d_ropec);
    cudaGetSymbolAddress((void**)&rs,  d_ropes);
    cudaGetSymbolAddress((void**)&sc,  d_sc);
    cudaGetSymbolAddress((void**)&ph,  d_ph);
    cudaGetSymbolAddress((void**)&pl,  d_pl);
    cudaGetSymbolAddress((void**)&ch,  d_ch);
    cudaGetSymbolAddress((void**)&cl,  d_cl);
    cudaGetSymbolAddress((void**)&g,   d_g);
    cudaGetSymbolAddress((void**)&u,   d_u);
    cudaGetSymbolAddress((void**)&gh,  d_gh);
    cudaGetSymbolAddress((void**)&gl,  d_gl);
    cudaGetSymbolAddress((void**)&pooled, d_pooled);
    cudaGetSymbolAddress((void**)&cls,    d_cls);
    cudaGetSymbolAddress((void**)&whT,    d_whT);
    cudaGetSymbolAddress((void**)&wlT,    d_wlT);

    wsplit_all_kernel<<<Lc * TILES_PER_LAYER, dim3(32, 8)>>>(
        wq, wk, wv, wo, wg, wu, wd,
        laq, lbq, lak, lbk, lav, lbv, lao, lbo, whT, wlT);
    embed_kernel<<<MTc, 256>>>(ids, embed, h);

    for (int l = 0; l < Lc; l++) {
        size_t lw = (size_t)l * LAYER_W;
        const float* LN1 = ln1 + (size_t)l * Hc;
        const float* BQ = bq + (size_t)l * QNc;
        const float* BK = bk + (size_t)l * KNc;
        const float* BV = bv + (size_t)l * KNc;
        const float* LN2 = ln2 + (size_t)l * Hc;

        rmsnorm_kernel<<<MTc, 256>>>(h, LN1, xh, xl);

        // fused QKV projection: 24 N-tiles x 16 M-tiles = 384 CTAs
        gemm_qkv<<<dim3(24, MTc / 128), 256, GEMM_SMEM>>>(
            xh, xl,
            whT + lw + WOFF_Q, wlT + lw + WOFF_Q,
            whT + lw + WOFF_K, wlT + lw + WOFF_K,
            whT + lw + WOFF_V, wlT + lw + WOFF_V,
            BQ, BK, BV, q, k, v);

        if (l == 0) rope_table_kernel<<<Sc, 64>>>(rc, rs);

        rope_split2_kernel<<<dim3(MTc, NHc + NKVc), 64>>>(q, k, rc, rs, qh, ql, kh, kl);
        vsplitT_kernel<<<dim3(16, 16, Bc), dim3(32, 8)>>>(v, vTh, vTl);

        attn_scores_mma<<<dim3(4, 4, Bc * NHc), 256, GEMM_SMEM>>>(qh, ql, kh, kl, sc);
        softmax_kernel<<<Bc * NHc * Sc, 128>>>(sc, mask, ph, pl);
        attn_ctx_mma<<<dim3(1, 4, Bc * NHc), 256, GEMM_SMEM>>>(ph, pl, vTh, vTl, ch, cl);

        gemm_bf16x3<<<dim3(Hc / 128, MTc / 128, 1), 256, GEMM_SMEM>>>(
            ch, cl,
            whT + lw + WOFF_O, wlT + lw + WOFF_O, h, h,
            nullptr, nullptr, nullptr, nullptr,
            MTc, Hc, QNc);

        rmsnorm_kernel<<<MTc, 256>>>(h, LN2, xh, xl);
        gemm_bf16x3<<<dim3(Fc / 128, MTc / 128, 2), 256, GEMM_SMEM>>>(
            xh, xl,
            whT + lw + WOFF_G, wlT + lw + WOFF_G, nullptr, g,
            whT + lw + WOFF_U, wlT + lw + WOFF_U, nullptr, u,
            MTc, Fc, Hc);
        silu_mul_kernel<<<(MTc * Fc) / 256, 256>>>(g, u, gh, gl, MTc * Fc);
        gemm_bf16x3<<<dim3(Hc / 128, MTc / 128, 1), 256, GEMM_SMEM>>>(
            gh, gl,
            whT + lw + WOFF_D, wlT + lw + WOFF_D, h, h,
            nullptr, nullptr, nullptr, nullptr,
            MTc, Hc, Fc);
    }

    pool_kernel<<<Bc, 256>>>(h, mask, lnf, pooled);
    cls1_kernel<<<dim3(Hc / 128, Bc), 128>>>(pooled, cw1, cb1, cls);
    cls2_kernel<<<Bc * NCc, 128>>>(cls, cw2, cb2, out);
}